// round 6
// baseline (speedup 1.0000x reference)
#include <cuda_runtime.h>
#include <cuda_bf16.h>
#include <cstdint>

// ---------------------------------------------------------------------------
// Problem constants
// ---------------------------------------------------------------------------
#define BDIM 2
#define TDIM 4096
#define CDIM 768
#define HDIM 12
#define DDIM 64
#define N3DIM 2304            // 3*C
#define MTOT  (BDIM*TDIM)     // 8192

// ---------------------------------------------------------------------------
// Device scratch (bf16 split operands; no allocation in kernel_launch)
// ---------------------------------------------------------------------------
__device__ __align__(16) __nv_bfloat16 g_xhi[MTOT*CDIM],    g_xlo[MTOT*CDIM];
__device__ __align__(16) __nv_bfloat16 g_yhi[MTOT*CDIM],    g_ylo[MTOT*CDIM];
__device__ __align__(16) __nv_bfloat16 g_WaThi[N3DIM*CDIM], g_WaTlo[N3DIM*CDIM]; // [N,K]
__device__ __align__(16) __nv_bfloat16 g_WpThi[CDIM*CDIM],  g_WpTlo[CDIM*CDIM];  // [N,K]
// q/k/v split, [b*h][t][d] row-major, q pre-scaled by 0.125
__device__ __align__(16) __nv_bfloat16 g_qhi[BDIM*HDIM*TDIM*DDIM], g_qlo[BDIM*HDIM*TDIM*DDIM];
__device__ __align__(16) __nv_bfloat16 g_khi[BDIM*HDIM*TDIM*DDIM], g_klo[BDIM*HDIM*TDIM*DDIM];
__device__ __align__(16) __nv_bfloat16 g_vhi[BDIM*HDIM*TDIM*DDIM], g_vlo[BDIM*HDIM*TDIM*DDIM];

// ---------------------------------------------------------------------------
// Helpers (all sm_80-legal: mma.sync bf16, ldmatrix, cp.async)
// ---------------------------------------------------------------------------
__device__ __forceinline__ uint32_t smem_u32(const void* p) {
    uint32_t a;
    asm("{ .reg .u64 t; cvta.to.shared.u64 t, %1; cvt.u32.u64 %0, t; }"
        : "=r"(a) : "l"(p));
    return a;
}
#define SW128(off) ((off) ^ (((off) >> 3) & 0x70))

__device__ __forceinline__ void cp16(uint32_t dst, const void* src) {
    asm volatile("cp.async.cg.shared.global [%0], [%1], 16;"
                 :: "r"(dst), "l"(src) : "memory");
}
#define CP_COMMIT() asm volatile("cp.async.commit_group;" ::: "memory")
#define CP_WAIT0()  asm volatile("cp.async.wait_group 0;"  ::: "memory")
#define CP_WAIT1()  asm volatile("cp.async.wait_group 1;"  ::: "memory")

__device__ __forceinline__ void ldm_x4(uint32_t a, uint32_t& r0, uint32_t& r1,
                                       uint32_t& r2, uint32_t& r3) {
    asm volatile("ldmatrix.sync.aligned.m8n8.x4.shared.b16 {%0,%1,%2,%3}, [%4];"
                 : "=r"(r0), "=r"(r1), "=r"(r2), "=r"(r3) : "r"(a));
}
__device__ __forceinline__ void ldm_x4t(uint32_t a, uint32_t& r0, uint32_t& r1,
                                        uint32_t& r2, uint32_t& r3) {
    asm volatile("ldmatrix.sync.aligned.m8n8.x4.trans.shared.b16 {%0,%1,%2,%3}, [%4];"
                 : "=r"(r0), "=r"(r1), "=r"(r2), "=r"(r3) : "r"(a));
}
__device__ __forceinline__ void mma_bf16(float (&c)[4], const uint32_t (&a)[4],
                                         uint32_t b0, uint32_t b1) {
    asm volatile("mma.sync.aligned.m16n8k16.row.col.f32.bf16.bf16.f32 "
                 "{%0,%1,%2,%3}, {%4,%5,%6,%7}, {%8,%9}, {%0,%1,%2,%3};"
                 : "+f"(c[0]), "+f"(c[1]), "+f"(c[2]), "+f"(c[3])
                 : "r"(a[0]), "r"(a[1]), "r"(a[2]), "r"(a[3]), "r"(b0), "r"(b1));
}
// pack {v0 -> low half, v1 -> high half}
__device__ __forceinline__ uint32_t pk2(float v0, float v1) {
    uint32_t r;
    asm("cvt.rn.bf16x2.f32 %0, %1, %2;" : "=r"(r) : "f"(v1), "f"(v0));
    return r;
}
__device__ __forceinline__ float ex2f(float x) {
    float y; asm("ex2.approx.ftz.f32 %0, %1;" : "=f"(y) : "f"(x)); return y;
}
// split-pack (v0,v1) into bf16 hi pair + residual lo pair, store both
__device__ __forceinline__ void split_store(float v0, float v1,
                                            __nv_bfloat16* hi, __nv_bfloat16* lo,
                                            size_t idx) {
    uint32_t h = pk2(v0, v1);
    float r0 = v0 - __uint_as_float(h << 16);
    float r1 = v1 - __uint_as_float(h & 0xffff0000u);
    *(uint32_t*)(hi + idx) = h;
    *(uint32_t*)(lo + idx) = pk2(r0, r1);
}

// ---------------------------------------------------------------------------
// Conversion kernels
// ---------------------------------------------------------------------------
__global__ __launch_bounds__(256) void split_bf16(const float* __restrict__ in,
                                                  __nv_bfloat16* __restrict__ hi,
                                                  __nv_bfloat16* __restrict__ lo,
                                                  int n2) {
    int i = blockIdx.x * blockDim.x + threadIdx.x;
    if (i >= n2) return;
    float2 v = ((const float2*)in)[i];
    uint32_t h = pk2(v.x, v.y);
    float r0 = v.x - __uint_as_float(h << 16);
    float r1 = v.y - __uint_as_float(h & 0xffff0000u);
    ((uint32_t*)hi)[i] = h;
    ((uint32_t*)lo)[i] = pk2(r0, r1);
}

// W [K,N] fp32 -> hiT/loT [N,K] bf16 (transpose + split). block (32,8).
__global__ __launch_bounds__(256) void wsplit_T(const float* __restrict__ W,
                                                __nv_bfloat16* __restrict__ hiT,
                                                __nv_bfloat16* __restrict__ loT,
                                                int K, int N) {
    __shared__ float tile[32][33];
    const int tx = threadIdx.x, ty = threadIdx.y;
    const int bn = blockIdx.x * 32, bk = blockIdx.y * 32;
    #pragma unroll
    for (int i = 0; i < 4; i++)
        tile[ty + 8*i][tx] = W[(size_t)(bk + ty + 8*i) * N + bn + tx];
    __syncthreads();
    #pragma unroll
    for (int i = 0; i < 4; i++) {
        float v = tile[tx][ty + 8*i];
        __nv_bfloat16 h = __float2bfloat16(v);
        float l = v - __bfloat162float(h);
        size_t o = (size_t)(bn + ty + 8*i) * K + bk + tx;
        hiT[o] = h;
        loT[o] = __float2bfloat16(l);
    }
}

// ---------------------------------------------------------------------------
// Shared split-bf16 HMMA GEMM mainloop, 512 threads = 16 warps (4m x 4n),
// warp tile 32x32, CTA tile 128x128, K-chunk 64, 3-stage cp.async.
// Pass-major + dual accumulators: acc <- Ahi.Bhi ; acc2 <- Ahi.Blo + Alo.Bhi.
// smem stage (64KB): Ahi@0 Alo@16K Bhi@32K Blo@48K, rows 128B SW128.
// ---------------------------------------------------------------------------
#define GSMEM (3*65536)

__device__ __forceinline__ void gemm_issue(const __nv_bfloat16* Ahi,
                                           const __nv_bfloat16* Alo,
                                           const __nv_bfloat16* Bhi,
                                           const __nv_bfloat16* Blo,
                                           int am0, int bn0, int k0,
                                           uint32_t stbase, int tid) {
    #pragma unroll
    for (int arr = 0; arr < 4; arr++) {
        const __nv_bfloat16* base = arr == 0 ? Ahi : arr == 1 ? Alo
                                  : arr == 2 ? Bhi : Blo;
        const int r0 = (arr < 2) ? am0 : bn0;
        #pragma unroll
        for (int i = 0; i < 2; i++) {
            int s2 = tid + (i << 9);          // 0..1023
            int row = s2 >> 3, c16 = s2 & 7;
            cp16(stbase + (arr << 14) + SW128((uint32_t)(row*128 + (c16 << 4))),
                 base + (size_t)(r0 + row) * 768 + k0 + (c16 << 3));
        }
    }
    CP_COMMIT();
}

__device__ __forceinline__ void gemm_main(const __nv_bfloat16* Ahi,
                                          const __nv_bfloat16* Alo,
                                          const __nv_bfloat16* Bhi,
                                          const __nv_bfloat16* Blo,
                                          int am0, int bn0,
                                          float (&acc)[2][4][4], char* sm) {
    const int tid = threadIdx.x;
    const int wid = tid >> 5, lane = tid & 31;
    const uint32_t sb = smem_u32(sm);
    const int wm0 = (wid & 3) * 32;
    const int wn0 = (wid >> 2) * 32;
    const int r = lane & 7, g = lane >> 3;

    float acc2[2][4][4] = {};

    gemm_issue(Ahi, Alo, Bhi, Blo, am0, bn0, 0,  sb,         tid);
    gemm_issue(Ahi, Alo, Bhi, Blo, am0, bn0, 64, sb + 65536, tid);

    for (int c = 0; c < 12; c++) {
        if (c < 11) CP_WAIT1(); else CP_WAIT0();
        __syncthreads();
        if (c < 10)
            gemm_issue(Ahi, Alo, Bhi, Blo, am0, bn0, (c+2)*64,
                       sb + (uint32_t)(((c+2)%3) * 65536), tid);
        const uint32_t st = sb + (uint32_t)((c % 3) * 65536);
        #pragma unroll
        for (int kf = 0; kf < 4; kf++) {
            const int k0 = kf * 16;
            uint32_t ah[2][4], al[2][4];
            #pragma unroll
            for (int mf = 0; mf < 2; mf++) {
                uint32_t off = SW128((uint32_t)(
                    (wm0 + mf*16 + ((g & 1) ? 8 : 0) + r) * 128 +
                    (k0 + ((g & 2) ? 8 : 0)) * 2));
                ldm_x4(st + off,         ah[mf][0], ah[mf][1], ah[mf][2], ah[mf][3]);
                ldm_x4(st + 16384 + off, al[mf][0], al[mf][1], al[mf][2], al[mf][3]);
            }
            uint32_t bh[4][2], bl[4][2];
            #pragma unroll
            for (int nb = 0; nb < 2; nb++) {
                uint32_t off = SW128((uint32_t)(
                    (wn0 + nb*16 + ((g & 2) ? 8 : 0) + r) * 128 +
                    (k0 + ((g & 1) ? 8 : 0)) * 2));
                uint32_t t0, t1, t2, t3;
                ldm_x4(st + 32768 + off, t0, t1, t2, t3);
                bh[2*nb][0] = t0; bh[2*nb][1] = t1;
                bh[2*nb+1][0] = t2; bh[2*nb+1][1] = t3;
                ldm_x4(st + 49152 + off, t0, t1, t2, t3);
                bl[2*nb][0] = t0; bl[2*nb][1] = t1;
                bl[2*nb+1][0] = t2; bl[2*nb+1][1] = t3;
            }
            // pass-major: hh -> acc, hl -> acc2, lh -> acc2 (same-acc gap = 8)
            #pragma unroll
            for (int mf = 0; mf < 2; mf++)
                #pragma unroll
                for (int nf = 0; nf < 4; nf++)
                    mma_bf16(acc[mf][nf], ah[mf], bh[nf][0], bh[nf][1]);
            #pragma unroll
            for (int mf = 0; mf < 2; mf++)
                #pragma unroll
                for (int nf = 0; nf < 4; nf++)
                    mma_bf16(acc2[mf][nf], ah[mf], bl[nf][0], bl[nf][1]);
            #pragma unroll
            for (int mf = 0; mf < 2; mf++)
                #pragma unroll
                for (int nf = 0; nf < 4; nf++)
                    mma_bf16(acc2[mf][nf], al[mf], bh[nf][0], bh[nf][1]);
        }
    }
    #pragma unroll
    for (int mf = 0; mf < 2; mf++)
        #pragma unroll
        for (int nf = 0; nf < 4; nf++)
            #pragma unroll
            for (int q = 0; q < 4; q++)
                acc[mf][nf][q] += acc2[mf][nf][q];
}

// ---------------------------------------------------------------------------
// QKV GEMM: x @ W_attn + b -> split bf16 q/k/v at [b*h][t][d] (q *= 0.125)
// grid (18, 64), 512 threads
// ---------------------------------------------------------------------------
__global__ __launch_bounds__(512) void qkv_mma(const float* __restrict__ bias) {
    extern __shared__ char sm[];
    const int bm = blockIdx.y * 128;
    const int bn = blockIdx.x * 128;
    float acc[2][4][4] = {};
    gemm_main(g_xhi, g_xlo, g_WaThi, g_WaTlo, bm, bn, acc, sm);

    const int wid = threadIdx.x >> 5, lane = threadIdx.x & 31;
    const int which = bn / CDIM;              // 0=q 1=k 2=v (tiles never straddle)
    const int batch = bm >> 12;
    const float sc = (which == 0) ? 0.125f : 1.0f;
    __nv_bfloat16* dhi = which == 0 ? g_qhi : which == 1 ? g_khi : g_vhi;
    __nv_bfloat16* dlo = which == 0 ? g_qlo : which == 1 ? g_klo : g_vlo;

    #pragma unroll
    for (int nf = 0; nf < 4; nf++) {
        const int gcol = bn + (wid >> 2) * 32 + nf * 8 + (lane & 3) * 2;
        const float b0 = __ldg(bias + gcol), b1 = __ldg(bias + gcol + 1);
        const int within = gcol % CDIM;
        const int head = within >> 6, d = within & 63;
        #pragma unroll
        for (int mf = 0; mf < 2; mf++) {
            const int t = (bm & (TDIM - 1)) + (wid & 3) * 32 + mf * 16 + (lane >> 2);
            size_t o0 = ((size_t)(batch*HDIM + head)*TDIM + t)     * DDIM + d;
            size_t o1 = ((size_t)(batch*HDIM + head)*TDIM + t + 8) * DDIM + d;
            split_store((acc[mf][nf][0]+b0)*sc, (acc[mf][nf][1]+b1)*sc, dhi, dlo, o0);
            split_store((acc[mf][nf][2]+b0)*sc, (acc[mf][nf][3]+b1)*sc, dhi, dlo, o1);
        }
    }
}

// ---------------------------------------------------------------------------
// Projection GEMM: y @ W_proj + b -> d_out fp32.  grid (6, 64), 512 threads
// ---------------------------------------------------------------------------
__global__ __launch_bounds__(512) void proj_mma(const float* __restrict__ bias,
                                                float* __restrict__ out) {
    extern __shared__ char sm[];
    const int bm = blockIdx.y * 128;
    const int bn = blockIdx.x * 128;
    float acc[2][4][4] = {};
    gemm_main(g_yhi, g_ylo, g_WpThi, g_WpTlo, bm, bn, acc, sm);

    const int wid = threadIdx.x >> 5, lane = threadIdx.x & 31;
    #pragma unroll
    for (int nf = 0; nf < 4; nf++) {
        const int gcol = bn + (wid >> 2) * 32 + nf * 8 + (lane & 3) * 2;
        const float b0 = __ldg(bias + gcol), b1 = __ldg(bias + gcol + 1);
        #pragma unroll
        for (int mf = 0; mf < 2; mf++) {
            const int m = bm + (wid & 3) * 32 + mf * 16 + (lane >> 2);
            *(float2*)(out + (size_t)m * CDIM + gcol) =
                make_float2(acc[mf][nf][0] + b0, acc[mf][nf][1] + b1);
            *(float2*)(out + (size_t)(m + 8) * CDIM + gcol) =
                make_float2(acc[mf][nf][2] + b0, acc[mf][nf][3] + b1);
        }
    }
}

// ---------------------------------------------------------------------------
// Flash attention, split-bf16 HMMA, 3-stage cp.async, register-resident Q,
// 1 CTA/SM (no reg cap).  grid (32 q-tiles, 24 bh), 256 thr.
// Dual S-accumulator (hh -> s, cross -> sx), PV interleaved across o-pairs.
// smem stage 32KB: Khi@0 Klo@8K Vhi@16K Vlo@24K, [t][d] rows 128B SW128.
// ---------------------------------------------------------------------------
#define FSMEM (3*32768)

__global__ __launch_bounds__(256) void flash_mma() {
    extern __shared__ char sm[];
    const uint32_t sb = smem_u32(sm);
    const int tid = threadIdx.x, wid = tid >> 5, lane = tid & 31;
    const int qt = (int)gridDim.x - 1 - (int)blockIdx.x;   // heavy tiles first
    const int bh = blockIdx.y;
    const int qbase = qt * 128;
    const int ntiles = (qbase + 128) / 64;                  // 2qt+2 (>= 2)

    const __nv_bfloat16* qhi = g_qhi + (size_t)bh * TDIM * DDIM;
    const __nv_bfloat16* qlo = g_qlo + (size_t)bh * TDIM * DDIM;
    const __nv_bfloat16* khi = g_khi + (size_t)bh * TDIM * DDIM;
    const __nv_bfloat16* klo = g_klo + (size_t)bh * TDIM * DDIM;
    const __nv_bfloat16* vhi = g_vhi + (size_t)bh * TDIM * DDIM;
    const __nv_bfloat16* vlo = g_vlo + (size_t)bh * TDIM * DDIM;

    // Q fragments, register resident: [kf][a], a-order: (r,klo),(r+8,klo),(r,khi),(r+8,khi)
    uint32_t qh[4][4], ql[4][4];
    {
        const int row = qbase + wid * 16 + (lane >> 2);
        const int colb = (lane & 3) * 2;
        #pragma unroll
        for (int kf = 0; kf < 4; kf++)
            #pragma unroll
            for (int a = 0; a < 4; a++) {
                int rr = row + ((a & 1) ? 8 : 0);
                int cc = kf * 16 + colb + ((a & 2) ? 8 : 0);
                qh[kf][a] = *(const uint32_t*)(qhi + (size_t)rr * DDIM + cc);
                ql[kf][a] = *(const uint32_t*)(qlo + (size_t)rr * DDIM + cc);
            }
    }

    float m0 = -1e30f, m1 = -1e30f, l0 = 0.f, l1 = 0.f;
    float o[8][4] = {};
    const int qhi_row = qbase + wid * 16 + 15;
    const int r = lane & 7, g = lane >> 3;
    const float LOG2E = 1.4426950408889634f;

    // K/V tile loader (cp.async, 8 x 16B per thread)
    auto issue = [&](int jt) {
        const int kb = jt * 64;
        const uint32_t stg = sb + (uint32_t)((jt % 3) << 15);
        #pragma unroll
        for (int arr = 0; arr < 4; arr++) {
            const __nv_bfloat16* base = arr == 0 ? khi : arr == 1 ? klo
                                      : arr == 2 ? vhi : vlo;
            #pragma unroll
            for (int i = 0; i < 2; i++) {
                int s2 = tid + (i << 8);            // 0..511
                int row = s2 >> 3, c16 = s2 & 7;
                cp16(stg + (arr << 13) + SW128((uint32_t)(row*128 + (c16 << 4))),
                     base + (size_t)(kb + row) * DDIM + (c16 << 3));
            }
        }
        CP_COMMIT();
    };
    issue(0);
    issue(1);

    for (int jt = 0; jt < ntiles; jt++) {
        if (jt + 1 < ntiles) CP_WAIT1(); else CP_WAIT0();
        __syncthreads();
        if (jt + 2 < ntiles) issue(jt + 2);
        const int kb = jt * 64;
        if (kb <= qhi_row) {                        // causal per-warp skip
            const uint32_t st = sb + (uint32_t)((jt % 3) << 15);

            // ---- S = Q K^T: pass-major with dual accumulators ----
            float s[8][4] = {}, sx[8][4] = {};
            #pragma unroll
            for (int kf = 0; kf < 4; kf++) {
                const int k0 = kf * 16;
                uint32_t kh[4][4], kl[4][4];
                #pragma unroll
                for (int nb = 0; nb < 4; nb++) {
                    uint32_t off = SW128((uint32_t)(
                        (nb*16 + ((g & 2) ? 8 : 0) + r) * 128 +
                        (k0 + ((g & 1) ? 8 : 0)) * 2));
                    ldm_x4(st + off,        kh[nb][0], kh[nb][1], kh[nb][2], kh[nb][3]);
                    ldm_x4(st + 8192 + off, kl[nb][0], kl[nb][1], kl[nb][2], kl[nb][3]);
                }
                #pragma unroll
                for (int nb = 0; nb < 4; nb++) {     // hh -> s
                    mma_bf16(s[2*nb],   qh[kf], kh[nb][0], kh[nb][1]);
                    mma_bf16(s[2*nb+1], qh[kf], kh[nb][2], kh[nb][3]);
                }
                #pragma unroll
                for (int nb = 0; nb < 4; nb++) {     // hl -> sx
                    mma_bf16(sx[2*nb],   qh[kf], kl[nb][0], kl[nb][1]);
                    mma_bf16(sx[2*nb+1], qh[kf], kl[nb][2], kl[nb][3]);
                }
                #pragma unroll
                for (int nb = 0; nb < 4; nb++) {     // lh -> sx
                    mma_bf16(sx[2*nb],   ql[kf], kh[nb][0], kh[nb][1]);
                    mma_bf16(sx[2*nb+1], ql[kf], kh[nb][2], kh[nb][3]);
                }
            }
            #pragma unroll
            for (int nf = 0; nf < 8; nf++)
                #pragma unroll
                for (int q = 0; q < 4; q++)
                    s[nf][q] += sx[nf][q];

            // ---- causal mask (diagonal tiles only) ----
            const int row0 = qbase + wid * 16 + (lane >> 2);
            if (kb + 63 > row0) {
                #pragma unroll
                for (int nf = 0; nf < 8; nf++) {
                    int col = kb + nf * 8 + (lane & 3) * 2;
                    if (col     > row0)     s[nf][0] = -1e30f;
                    if (col + 1 > row0)     s[nf][1] = -1e30f;
                    if (col     > row0 + 8) s[nf][2] = -1e30f;
                    if (col + 1 > row0 + 8) s[nf][3] = -1e30f;
                }
            }

            // ---- online softmax ----
            float rmax0 = -1e30f, rmax1 = -1e30f;
            #pragma unroll
            for (int nf = 0; nf < 8; nf++) {
                rmax0 = fmaxf(rmax0, fmaxf(s[nf][0], s[nf][1]));
                rmax1 = fmaxf(rmax1, fmaxf(s[nf][2], s[nf][3]));
            }
            rmax0 = fmaxf(rmax0, __shfl_xor_sync(0xffffffffu, rmax0, 1));
            rmax0 = fmaxf(rmax0, __shfl_xor_sync(0xffffffffu, rmax0, 2));
            rmax1 = fmaxf(rmax1, __shfl_xor_sync(0xffffffffu, rmax1, 1));
            rmax1 = fmaxf(rmax1, __shfl_xor_sync(0xffffffffu, rmax1, 2));
            const float mn0 = fmaxf(m0, rmax0), mn1 = fmaxf(m1, rmax1);
            const float a0 = ex2f((m0 - mn0) * LOG2E);
            const float a1 = ex2f((m1 - mn1) * LOG2E);
            m0 = mn0; m1 = mn1;
            const float ml0 = mn0 * LOG2E, ml1 = mn1 * LOG2E;
            float rs0 = 0.f, rs1 = 0.f;
            #pragma unroll
            for (int nf = 0; nf < 8; nf++) {
                s[nf][0] = ex2f(fmaf(s[nf][0], LOG2E, -ml0));
                s[nf][1] = ex2f(fmaf(s[nf][1], LOG2E, -ml0));
                s[nf][2] = ex2f(fmaf(s[nf][2], LOG2E, -ml1));
                s[nf][3] = ex2f(fmaf(s[nf][3], LOG2E, -ml1));
                rs0 += s[nf][0] + s[nf][1];
                rs1 += s[nf][2] + s[nf][3];
            }
            rs0 += __shfl_xor_sync(0xffffffffu, rs0, 1);
            rs0 += __shfl_xor_sync(0xffffffffu, rs0, 2);
            rs1 += __shfl_xor_sync(0xffffffffu, rs1, 1);
            rs1 += __shfl_xor_sync(0xffffffffu, rs1, 2);
            l0 = l0 * a0 + rs0;
            l1 = l1 * a1 + rs1;
            #pragma unroll
            for (int nf = 0; nf < 8; nf++) {
                o[nf][0] *= a0; o[nf][1] *= a0;
                o[nf][2] *= a1; o[nf][3] *= a1;
            }

            // ---- P -> bf16 hi/lo A-fragments (registers only) ----
            uint32_t ph[4][4], pl[4][4];
            #pragma unroll
            for (int j = 0; j < 4; j++) {
                #pragma unroll
                for (int half = 0; half < 2; half++) {
                    float v0 = s[2*j + half][0], v1 = s[2*j + half][1];
                    float w0 = s[2*j + half][2], w1 = s[2*j + half][3];
                    uint32_t hA = pk2(v0, v1);
                    uint32_t hB = pk2(w0, w1);
                    ph[j][2*half]     = hA;
                    ph[j][2*half + 1] = hB;
                    pl[j][2*half] = pk2(v0 - __uint_as_float(hA << 16),
                                        v1 - __uint_as_float(hA & 0xffff0000u));
                    pl[j][2*half + 1] = pk2(w0 - __uint_as_float(hB << 16),
                                            w1 - __uint_as_float(hB & 0xffff0000u));
                }
            }

            // ---- O += P V (3 passes), interleaved across o-pair ----
            #pragma unroll
            for (int j = 0; j < 4; j++) {
                #pragma unroll
                for (int nb = 0; nb < 4; nb++) {
                    uint32_t off = SW128((uint32_t)(
                        (j*16 + ((g & 1) ? 8 : 0) + r) * 128 +
                        (nb*16 + ((g & 2) ? 8 : 0)) * 2));
                    uint32_t h0, h1, h2, h3, e0, e1, e2, e3;
                    ldm_x4t(st + 16384 + off, h0, h1, h2, h3);  // Vhi
                    ldm_x4t(st + 24576 + off, e0, e1, e2, e3);  // Vlo
                    mma_bf16(o[2*nb],   ph[j], h0, h1);
                    mma_bf16(o[2*nb+1], ph[j], h2, h3);
                    mma_bf16(o[2*nb],   pl[j], h0, h1);
                    mma_bf16(o[2*nb+1], pl[j], h2, h3);
                    mma_bf16(o[2*nb],   ph[j], e0, e1);
                    mma_bf16(o[2*nb+1], ph[j], e2, e3);
                }
            }
        }
    }

    // ---- epilogue: o / l, split to bf16 hi/lo into g_y ----
    const float inv0 = 1.0f / l0, inv1 = 1.0f / l1;
    const int batch = bh / HDIM, hh = bh % HDIM;
    const int row = qbase + wid * 16 + (lane >> 2);
    const size_t rb0 = ((size_t)(batch * TDIM + row))     * CDIM + hh * DDIM;
    const size_t rb1 = ((size_t)(batch * TDIM + row + 8)) * CDIM + hh * DDIM;
    #pragma unroll
    for (int nf = 0; nf < 8; nf++) {
        const int d = nf * 8 + (lane & 3) * 2;
        split_store(o[nf][0] * inv0, o[nf][1] * inv0, g_yhi, g_ylo, rb0 + d);
        split_store(o[nf][2] * inv1, o[nf][3] * inv1, g_yhi, g_ylo, rb1 + d);
    }
}

// ---------------------------------------------------------------------------
extern "C" void kernel_launch(void* const* d_in, const int* in_sizes, int n_in,
                              void* d_out, int out_size) {
    const float *x = nullptr, *Wa = nullptr, *ba = nullptr, *Wp = nullptr, *bp = nullptr;
    for (int i = 0; i < n_in; i++) {
        switch (in_sizes[i]) {
            case 6291456: x  = (const float*)d_in[i]; break;   // [2,4096,768]
            case 1769472: Wa = (const float*)d_in[i]; break;   // [768,2304]
            case 2304:    ba = (const float*)d_in[i]; break;
            case 589824:  Wp = (const float*)d_in[i]; break;   // [768,768]
            case 768:     bp = (const float*)d_in[i]; break;
        }
    }

    cudaFuncSetAttribute(qkv_mma,   cudaFuncAttributeMaxDynamicSharedMemorySize, GSMEM);
    cudaFuncSetAttribute(proj_mma,  cudaFuncAttributeMaxDynamicSharedMemorySize, GSMEM);
    cudaFuncSetAttribute(flash_mma, cudaFuncAttributeMaxDynamicSharedMemorySize, FSMEM);

    __nv_bfloat16 *xhi, *xlo, *wahi, *walo, *wphi, *wplo;
    cudaGetSymbolAddress((void**)&xhi,  g_xhi);
    cudaGetSymbolAddress((void**)&xlo,  g_xlo);
    cudaGetSymbolAddress((void**)&wahi, g_WaThi);
    cudaGetSymbolAddress((void**)&walo, g_WaTlo);
    cudaGetSymbolAddress((void**)&wphi, g_WpThi);
    cudaGetSymbolAddress((void**)&wplo, g_WpTlo);

    split_bf16<<<(MTOT*CDIM/2 + 255)/256, 256>>>(x, xhi, xlo, MTOT*CDIM/2);
    wsplit_T<<<dim3(N3DIM/32, CDIM/32), dim3(32, 8)>>>(Wa, wahi, walo, CDIM, N3DIM);
    wsplit_T<<<dim3(CDIM/32,  CDIM/32), dim3(32, 8)>>>(Wp, wphi, wplo, CDIM, CDIM);
    qkv_mma<<<dim3(N3DIM/128, MTOT/128), 512, GSMEM>>>(ba);        // (18,64)
    flash_mma<<<dim3(TDIM/128, BDIM*HDIM), 256, FSMEM>>>();        // (32,24)
    proj_mma<<<dim3(CDIM/128, MTOT/128), 512, GSMEM>>>(bp, (float*)d_out); // (6,64)
}

// round 7
// speedup vs baseline: 1.2935x; 1.2935x over previous
#include <cuda_runtime.h>
#include <cuda_bf16.h>
#include <cuda_fp16.h>
#include <cstdint>

// ---------------------------------------------------------------------------
// Problem constants
// ---------------------------------------------------------------------------
#define BDIM 2
#define TDIM 4096
#define CDIM 768
#define HDIM 12
#define DDIM 64
#define N3DIM 2304            // 3*C
#define MTOT  (BDIM*TDIM)     // 8192

// ---------------------------------------------------------------------------
// Device scratch (no allocation in kernel_launch)
// ---------------------------------------------------------------------------
__device__ __align__(16) __nv_bfloat16 g_xhi[MTOT*CDIM],    g_xlo[MTOT*CDIM];
__device__ __align__(16) __nv_bfloat16 g_yhi[MTOT*CDIM],    g_ylo[MTOT*CDIM];
__device__ __align__(16) __nv_bfloat16 g_WaThi[N3DIM*CDIM], g_WaTlo[N3DIM*CDIM]; // [N,K]
__device__ __align__(16) __nv_bfloat16 g_WpThi[CDIM*CDIM],  g_WpTlo[CDIM*CDIM];  // [N,K]
// flash operands, [b*h][t][d] row-major:
//   Q: fp16 2-way split, pre-scaled by 0.125.  K, V: single fp16.
__device__ __align__(16) __half g_qh[BDIM*HDIM*TDIM*DDIM], g_ql[BDIM*HDIM*TDIM*DDIM];
__device__ __align__(16) __half g_k [BDIM*HDIM*TDIM*DDIM];
__device__ __align__(16) __half g_v [BDIM*HDIM*TDIM*DDIM];

// ---------------------------------------------------------------------------
// Helpers (all sm_80-legal: mma.sync bf16/fp16, ldmatrix, cp.async)
// ---------------------------------------------------------------------------
__device__ __forceinline__ uint32_t smem_u32(const void* p) {
    uint32_t a;
    asm("{ .reg .u64 t; cvta.to.shared.u64 t, %1; cvt.u32.u64 %0, t; }"
        : "=r"(a) : "l"(p));
    return a;
}
#define SW128(off) ((off) ^ (((off) >> 3) & 0x70))

__device__ __forceinline__ void cp16(uint32_t dst, const void* src) {
    asm volatile("cp.async.cg.shared.global [%0], [%1], 16;"
                 :: "r"(dst), "l"(src) : "memory");
}
#define CP_COMMIT() asm volatile("cp.async.commit_group;" ::: "memory")
#define CP_WAIT0()  asm volatile("cp.async.wait_group 0;"  ::: "memory")
#define CP_WAIT1()  asm volatile("cp.async.wait_group 1;"  ::: "memory")

__device__ __forceinline__ void ldm_x4(uint32_t a, uint32_t& r0, uint32_t& r1,
                                       uint32_t& r2, uint32_t& r3) {
    asm volatile("ldmatrix.sync.aligned.m8n8.x4.shared.b16 {%0,%1,%2,%3}, [%4];"
                 : "=r"(r0), "=r"(r1), "=r"(r2), "=r"(r3) : "r"(a));
}
__device__ __forceinline__ void ldm_x4t(uint32_t a, uint32_t& r0, uint32_t& r1,
                                        uint32_t& r2, uint32_t& r3) {
    asm volatile("ldmatrix.sync.aligned.m8n8.x4.trans.shared.b16 {%0,%1,%2,%3}, [%4];"
                 : "=r"(r0), "=r"(r1), "=r"(r2), "=r"(r3) : "r"(a));
}
__device__ __forceinline__ void mma_bf16(float (&c)[4], const uint32_t (&a)[4],
                                         uint32_t b0, uint32_t b1) {
    asm volatile("mma.sync.aligned.m16n8k16.row.col.f32.bf16.bf16.f32 "
                 "{%0,%1,%2,%3}, {%4,%5,%6,%7}, {%8,%9}, {%0,%1,%2,%3};"
                 : "+f"(c[0]), "+f"(c[1]), "+f"(c[2]), "+f"(c[3])
                 : "r"(a[0]), "r"(a[1]), "r"(a[2]), "r"(a[3]), "r"(b0), "r"(b1));
}
__device__ __forceinline__ void mma_fp16(float (&c)[4], const uint32_t (&a)[4],
                                         uint32_t b0, uint32_t b1) {
    asm volatile("mma.sync.aligned.m16n8k16.row.col.f32.f16.f16.f32 "
                 "{%0,%1,%2,%3}, {%4,%5,%6,%7}, {%8,%9}, {%0,%1,%2,%3};"
                 : "+f"(c[0]), "+f"(c[1]), "+f"(c[2]), "+f"(c[3])
                 : "r"(a[0]), "r"(a[1]), "r"(a[2]), "r"(a[3]), "r"(b0), "r"(b1));
}
// pack {v0 -> low half, v1 -> high half} as bf16x2
__device__ __forceinline__ uint32_t pk2(float v0, float v1) {
    uint32_t r;
    asm("cvt.rn.bf16x2.f32 %0, %1, %2;" : "=r"(r) : "f"(v1), "f"(v0));
    return r;
}
// pack two halves into u32 (a -> low, b -> high)
__device__ __forceinline__ uint32_t pkh(__half a, __half b) {
    __half2 t = __halves2half2(a, b);
    return *(uint32_t*)&t;
}
__device__ __forceinline__ float ex2f(float x) {
    float y; asm("ex2.approx.ftz.f32 %0, %1;" : "=f"(y) : "f"(x)); return y;
}
// split-pack (v0,v1) into bf16 hi pair + residual lo pair, store both
__device__ __forceinline__ void split_store(float v0, float v1,
                                            __nv_bfloat16* hi, __nv_bfloat16* lo,
                                            size_t idx) {
    uint32_t h = pk2(v0, v1);
    float r0 = v0 - __uint_as_float(h << 16);
    float r1 = v1 - __uint_as_float(h & 0xffff0000u);
    *(uint32_t*)(hi + idx) = h;
    *(uint32_t*)(lo + idx) = pk2(r0, r1);
}
// fp16 2-way split store
__device__ __forceinline__ void split_store_h(float v0, float v1,
                                              __half* hi, __half* lo, size_t idx) {
    __half a0 = __float2half_rn(v0), a1 = __float2half_rn(v1);
    *(uint32_t*)(hi + idx) = pkh(a0, a1);
    *(uint32_t*)(lo + idx) = pkh(__float2half_rn(v0 - __half2float(a0)),
                                 __float2half_rn(v1 - __half2float(a1)));
}

// ---------------------------------------------------------------------------
// Conversion kernels
// ---------------------------------------------------------------------------
__global__ __launch_bounds__(256) void split_bf16(const float* __restrict__ in,
                                                  __nv_bfloat16* __restrict__ hi,
                                                  __nv_bfloat16* __restrict__ lo,
                                                  int n2) {
    int i = blockIdx.x * blockDim.x + threadIdx.x;
    if (i >= n2) return;
    float2 v = ((const float2*)in)[i];
    uint32_t h = pk2(v.x, v.y);
    float r0 = v.x - __uint_as_float(h << 16);
    float r1 = v.y - __uint_as_float(h & 0xffff0000u);
    ((uint32_t*)hi)[i] = h;
    ((uint32_t*)lo)[i] = pk2(r0, r1);
}

// W [K,N] fp32 -> hiT/loT [N,K] bf16 (transpose + split). block (32,8).
__global__ __launch_bounds__(256) void wsplit_T(const float* __restrict__ W,
                                                __nv_bfloat16* __restrict__ hiT,
                                                __nv_bfloat16* __restrict__ loT,
                                                int K, int N) {
    __shared__ float tile[32][33];
    const int tx = threadIdx.x, ty = threadIdx.y;
    const int bn = blockIdx.x * 32, bk = blockIdx.y * 32;
    #pragma unroll
    for (int i = 0; i < 4; i++)
        tile[ty + 8*i][tx] = W[(size_t)(bk + ty + 8*i) * N + bn + tx];
    __syncthreads();
    #pragma unroll
    for (int i = 0; i < 4; i++) {
        float v = tile[tx][ty + 8*i];
        __nv_bfloat16 h = __float2bfloat16(v);
        float l = v - __bfloat162float(h);
        size_t o = (size_t)(bn + ty + 8*i) * K + bk + tx;
        hiT[o] = h;
        loT[o] = __float2bfloat16(l);
    }
}

// ---------------------------------------------------------------------------
// Shared split-bf16 HMMA GEMM mainloop (proven R5 form).
// 512 thr = 16 warps (4m x 4n), warp tile 32x32, CTA 128x128, 3-stage.
// C = Ahi.B^T(hi) + Ahi.B^T(lo) + Alo.B^T(hi) over K=768.
// smem stage (64KB): Ahi@0 Alo@16K Bhi@32K Blo@48K, rows 128B SW128.
// ---------------------------------------------------------------------------
#define GSMEM (3*65536)

__device__ __forceinline__ void gemm_issue(const __nv_bfloat16* Ahi,
                                           const __nv_bfloat16* Alo,
                                           const __nv_bfloat16* Bhi,
                                           const __nv_bfloat16* Blo,
                                           int am0, int bn0, int k0,
                                           uint32_t stbase, int tid) {
    #pragma unroll
    for (int arr = 0; arr < 4; arr++) {
        const __nv_bfloat16* base = arr == 0 ? Ahi : arr == 1 ? Alo
                                  : arr == 2 ? Bhi : Blo;
        const int r0 = (arr < 2) ? am0 : bn0;
        #pragma unroll
        for (int i = 0; i < 2; i++) {
            int s2 = tid + (i << 9);          // 0..1023
            int row = s2 >> 3, c16 = s2 & 7;
            cp16(stbase + (arr << 14) + SW128((uint32_t)(row*128 + (c16 << 4))),
                 base + (size_t)(r0 + row) * 768 + k0 + (c16 << 3));
        }
    }
    CP_COMMIT();
}

__device__ __forceinline__ void gemm_main(const __nv_bfloat16* Ahi,
                                          const __nv_bfloat16* Alo,
                                          const __nv_bfloat16* Bhi,
                                          const __nv_bfloat16* Blo,
                                          int am0, int bn0,
                                          float (&acc)[2][4][4], char* sm) {
    const int tid = threadIdx.x;
    const int wid = tid >> 5, lane = tid & 31;
    const uint32_t sb = smem_u32(sm);
    const int wm0 = (wid & 3) * 32;
    const int wn0 = (wid >> 2) * 32;
    const int r = lane & 7, g = lane >> 3;

    gemm_issue(Ahi, Alo, Bhi, Blo, am0, bn0, 0,  sb,         tid);
    gemm_issue(Ahi, Alo, Bhi, Blo, am0, bn0, 64, sb + 65536, tid);

    for (int c = 0; c < 12; c++) {
        if (c < 11) CP_WAIT1(); else CP_WAIT0();
        __syncthreads();
        if (c < 10)
            gemm_issue(Ahi, Alo, Bhi, Blo, am0, bn0, (c+2)*64,
                       sb + (uint32_t)(((c+2)%3) * 65536), tid);
        const uint32_t st = sb + (uint32_t)((c % 3) * 65536);
        #pragma unroll
        for (int kf = 0; kf < 4; kf++) {
            const int k0 = kf * 16;
            uint32_t ah[2][4], al[2][4];
            #pragma unroll
            for (int mf = 0; mf < 2; mf++) {
                uint32_t off = SW128((uint32_t)(
                    (wm0 + mf*16 + ((g & 1) ? 8 : 0) + r) * 128 +
                    (k0 + ((g & 2) ? 8 : 0)) * 2));
                ldm_x4(st + off,         ah[mf][0], ah[mf][1], ah[mf][2], ah[mf][3]);
                ldm_x4(st + 16384 + off, al[mf][0], al[mf][1], al[mf][2], al[mf][3]);
            }
            uint32_t bh[4][2], bl[4][2];
            #pragma unroll
            for (int nb = 0; nb < 2; nb++) {
                uint32_t off = SW128((uint32_t)(
                    (wn0 + nb*16 + ((g & 2) ? 8 : 0) + r) * 128 +
                    (k0 + ((g & 1) ? 8 : 0)) * 2));
                uint32_t t0, t1, t2, t3;
                ldm_x4(st + 32768 + off, t0, t1, t2, t3);
                bh[2*nb][0] = t0; bh[2*nb][1] = t1;
                bh[2*nb+1][0] = t2; bh[2*nb+1][1] = t3;
                ldm_x4(st + 49152 + off, t0, t1, t2, t3);
                bl[2*nb][0] = t0; bl[2*nb][1] = t1;
                bl[2*nb+1][0] = t2; bl[2*nb+1][1] = t3;
            }
            #pragma unroll
            for (int mf = 0; mf < 2; mf++)
                #pragma unroll
                for (int nf = 0; nf < 4; nf++) {
                    mma_bf16(acc[mf][nf], ah[mf], bh[nf][0], bh[nf][1]);
                    mma_bf16(acc[mf][nf], ah[mf], bl[nf][0], bl[nf][1]);
                    mma_bf16(acc[mf][nf], al[mf], bh[nf][0], bh[nf][1]);
                }
        }
    }
}

// ---------------------------------------------------------------------------
// QKV GEMM: x @ W_attn + b.  Q -> fp16 split (x0.125), K/V -> single fp16.
// grid (18, 64), 512 threads
// ---------------------------------------------------------------------------
__global__ __launch_bounds__(512) void qkv_mma(const float* __restrict__ bias) {
    extern __shared__ char sm[];
    const int bm = blockIdx.y * 128;
    const int bn = blockIdx.x * 128;
    float acc[2][4][4] = {};
    gemm_main(g_xhi, g_xlo, g_WaThi, g_WaTlo, bm, bn, acc, sm);

    const int wid = threadIdx.x >> 5, lane = threadIdx.x & 31;
    const int which = bn / CDIM;              // 0=q 1=k 2=v (tiles never straddle)
    const int batch = bm >> 12;

    #pragma unroll
    for (int nf = 0; nf < 4; nf++) {
        const int gcol = bn + (wid >> 2) * 32 + nf * 8 + (lane & 3) * 2;
        const float b0 = __ldg(bias + gcol), b1 = __ldg(bias + gcol + 1);
        const int within = gcol % CDIM;
        const int head = within >> 6, d = within & 63;
        #pragma unroll
        for (int mf = 0; mf < 2; mf++) {
            const int t = (bm & (TDIM - 1)) + (wid & 3) * 32 + mf * 16 + (lane >> 2);
            size_t o0 = ((size_t)(batch*HDIM + head)*TDIM + t)     * DDIM + d;
            size_t o1 = ((size_t)(batch*HDIM + head)*TDIM + t + 8) * DDIM + d;
            if (which == 0) {
                split_store_h((acc[mf][nf][0]+b0)*0.125f, (acc[mf][nf][1]+b1)*0.125f,
                              g_qh, g_ql, o0);
                split_store_h((acc[mf][nf][2]+b0)*0.125f, (acc[mf][nf][3]+b1)*0.125f,
                              g_qh, g_ql, o1);
            } else {
                __half* dst = (which == 1) ? g_k : g_v;
                *(uint32_t*)(dst + o0) = pkh(__float2half_rn(acc[mf][nf][0]+b0),
                                             __float2half_rn(acc[mf][nf][1]+b1));
                *(uint32_t*)(dst + o1) = pkh(__float2half_rn(acc[mf][nf][2]+b0),
                                             __float2half_rn(acc[mf][nf][3]+b1));
            }
        }
    }
}

// ---------------------------------------------------------------------------
// Projection GEMM: y @ W_proj + b -> d_out fp32.  grid (6, 64), 512 threads
// ---------------------------------------------------------------------------
__global__ __launch_bounds__(512) void proj_mma(const float* __restrict__ bias,
                                                float* __restrict__ out) {
    extern __shared__ char sm[];
    const int bm = blockIdx.y * 128;
    const int bn = blockIdx.x * 128;
    float acc[2][4][4] = {};
    gemm_main(g_yhi, g_ylo, g_WpThi, g_WpTlo, bm, bn, acc, sm);

    const int wid = threadIdx.x >> 5, lane = threadIdx.x & 31;
    #pragma unroll
    for (int nf = 0; nf < 4; nf++) {
        const int gcol = bn + (wid >> 2) * 32 + nf * 8 + (lane & 3) * 2;
        const float b0 = __ldg(bias + gcol), b1 = __ldg(bias + gcol + 1);
        #pragma unroll
        for (int mf = 0; mf < 2; mf++) {
            const int m = bm + (wid & 3) * 32 + mf * 16 + (lane >> 2);
            *(float2*)(out + (size_t)m * CDIM + gcol) =
                make_float2(acc[mf][nf][0] + b0, acc[mf][nf][1] + b1);
            *(float2*)(out + (size_t)(m + 8) * CDIM + gcol) =
                make_float2(acc[mf][nf][2] + b0, acc[mf][nf][3] + b1);
        }
    }
}

// ---------------------------------------------------------------------------
// Flash attention, fp16 2-pass HMMA (R3 structure).
// grid (32 q-tiles, 24 bh), 256 thr, 1 CTA/SM.  Q fp16-split in registers;
// K,V single fp16 in smem (stage 16KB: K@0 V@8K), 3-stage cp.async.
// S = Qh.K + Ql.K ;  O = Ph.V + Pl.V  (split side exact).
// ---------------------------------------------------------------------------
#define FSMEM (3*16384)

__global__ __launch_bounds__(256) void flash_mma() {
    extern __shared__ char sm[];
    const uint32_t sb = smem_u32(sm);
    const int tid = threadIdx.x, wid = tid >> 5, lane = tid & 31;
    const int qt = (int)gridDim.x - 1 - (int)blockIdx.x;   // heavy tiles first
    const int bh = blockIdx.y;
    const int qbase = qt * 128;
    const int ntiles = (qbase + 128) / 64;                  // 2qt+2 (>= 2)

    const __half* qhp = g_qh + (size_t)bh * TDIM * DDIM;
    const __half* qlp = g_ql + (size_t)bh * TDIM * DDIM;
    const __half* kp  = g_k  + (size_t)bh * TDIM * DDIM;
    const __half* vp  = g_v  + (size_t)bh * TDIM * DDIM;

    // Q fragments, register resident (fp16 split)
    uint32_t qh[4][4], ql[4][4];
    {
        const int row = qbase + wid * 16 + (lane >> 2);
        const int colb = (lane & 3) * 2;
        #pragma unroll
        for (int kf = 0; kf < 4; kf++)
            #pragma unroll
            for (int a = 0; a < 4; a++) {
                int rr = row + ((a & 1) ? 8 : 0);
                int cc = kf * 16 + colb + ((a & 2) ? 8 : 0);
                qh[kf][a] = *(const uint32_t*)(qhp + (size_t)rr * DDIM + cc);
                ql[kf][a] = *(const uint32_t*)(qlp + (size_t)rr * DDIM + cc);
            }
    }

    float m0 = -1e30f, m1 = -1e30f, l0 = 0.f, l1 = 0.f;
    float o[8][4] = {};
    const int qhi_row = qbase + wid * 16 + 15;
    const int r = lane & 7, g = lane >> 3;
    const float LOG2E = 1.4426950408889634f;

    // K/V tile loader (cp.async, 4 x 16B per thread; stage = 16KB)
    auto issue = [&](int jt) {
        const int kb = jt * 64;
        const uint32_t stg = sb + (uint32_t)((jt % 3) << 14);
        #pragma unroll
        for (int arr = 0; arr < 2; arr++) {
            const __half* base = arr == 0 ? kp : vp;
            #pragma unroll
            for (int i = 0; i < 2; i++) {
                int s2 = tid + (i << 8);            // 0..511
                int row = s2 >> 3, c16 = s2 & 7;
                cp16(stg + (arr << 13) + SW128((uint32_t)(row*128 + (c16 << 4))),
                     base + (size_t)(kb + row) * DDIM + (c16 << 3));
            }
        }
        CP_COMMIT();
    };
    issue(0);
    issue(1);

    for (int jt = 0; jt < ntiles; jt++) {
        if (jt + 1 < ntiles) CP_WAIT1(); else CP_WAIT0();
        __syncthreads();
        if (jt + 2 < ntiles) issue(jt + 2);
        const int kb = jt * 64;
        if (kb <= qhi_row) {                        // causal per-warp skip
            const uint32_t st = sb + (uint32_t)((jt % 3) << 14);

            // ---- S = Qh.K + Ql.K (2 passes) ----
            float s[8][4] = {};
            #pragma unroll
            for (int kf = 0; kf < 4; kf++) {
                const int k0 = kf * 16;
                #pragma unroll
                for (int nb = 0; nb < 4; nb++) {
                    uint32_t off = SW128((uint32_t)(
                        (nb*16 + ((g & 2) ? 8 : 0) + r) * 128 +
                        (k0 + ((g & 1) ? 8 : 0)) * 2));
                    uint32_t h0, h1, h2, h3;
                    ldm_x4(st + off, h0, h1, h2, h3);          // K
                    mma_fp16(s[2*nb],   qh[kf], h0, h1);
                    mma_fp16(s[2*nb+1], qh[kf], h2, h3);
                    mma_fp16(s[2*nb],   ql[kf], h0, h1);
                    mma_fp16(s[2*nb+1], ql[kf], h2, h3);
                }
            }

            // ---- causal mask (diagonal tiles only) ----
            const int row0 = qbase + wid * 16 + (lane >> 2);
            if (kb + 63 > row0) {
                #pragma unroll
                for (int nf = 0; nf < 8; nf++) {
                    int col = kb + nf * 8 + (lane & 3) * 2;
                    if (col     > row0)     s[nf][0] = -1e30f;
                    if (col + 1 > row0)     s[nf][1] = -1e30f;
                    if (col     > row0 + 8) s[nf][2] = -1e30f;
                    if (col + 1 > row0 + 8) s[nf][3] = -1e30f;
                }
            }

            // ---- online softmax ----
            float rmax0 = -1e30f, rmax1 = -1e30f;
            #pragma unroll
            for (int nf = 0; nf < 8; nf++) {
                rmax0 = fmaxf(rmax0, fmaxf(s[nf][0], s[nf][1]));
                rmax1 = fmaxf(rmax1, fmaxf(s[nf][2], s[nf][3]));
            }
            rmax0 = fmaxf(rmax0, __shfl_xor_sync(0xffffffffu, rmax0, 1));
            rmax0 = fmaxf(rmax0, __shfl_xor_sync(0xffffffffu, rmax0, 2));
            rmax1 = fmaxf(rmax1, __shfl_xor_sync(0xffffffffu, rmax1, 1));
            rmax1 = fmaxf(rmax1, __shfl_xor_sync(0xffffffffu, rmax1, 2));
            const float mn0 = fmaxf(m0, rmax0), mn1 = fmaxf(m1, rmax1);
            const float a0 = ex2f((m0 - mn0) * LOG2E);
            const float a1 = ex2f((m1 - mn1) * LOG2E);
            m0 = mn0; m1 = mn1;
            const float ml0 = mn0 * LOG2E, ml1 = mn1 * LOG2E;
            float rs0 = 0.f, rs1 = 0.f;
            #pragma unroll
            for (int nf = 0; nf < 8; nf++) {
                s[nf][0] = ex2f(fmaf(s[nf][0], LOG2E, -ml0));
                s[nf][1] = ex2f(fmaf(s[nf][1], LOG2E, -ml0));
                s[nf][2] = ex2f(fmaf(s[nf][2], LOG2E, -ml1));
                s[nf][3] = ex2f(fmaf(s[nf][3], LOG2E, -ml1));
                rs0 += s[nf][0] + s[nf][1];
                rs1 += s[nf][2] + s[nf][3];
            }
            rs0 += __shfl_xor_sync(0xffffffffu, rs0, 1);
            rs0 += __shfl_xor_sync(0xffffffffu, rs0, 2);
            rs1 += __shfl_xor_sync(0xffffffffu, rs1, 1);
            rs1 += __shfl_xor_sync(0xffffffffu, rs1, 2);
            l0 = l0 * a0 + rs0;
            l1 = l1 * a1 + rs1;
            #pragma unroll
            for (int nf = 0; nf < 8; nf++) {
                o[nf][0] *= a0; o[nf][1] *= a0;
                o[nf][2] *= a1; o[nf][3] *= a1;
            }

            // ---- P -> fp16 hi/lo A-fragments (registers only) ----
            uint32_t ph[4][4], pl[4][4];
            #pragma unroll
            for (int j = 0; j < 4; j++) {
                #pragma unroll
                for (int half = 0; half < 2; half++) {
                    float v0 = s[2*j + half][0], v1 = s[2*j + half][1];
                    float w0 = s[2*j + half][2], w1 = s[2*j + half][3];
                    __half a0h = __float2half_rn(v0), a1h = __float2half_rn(v1);
                    __half b0h = __float2half_rn(w0), b1h = __float2half_rn(w1);
                    ph[j][2*half]     = pkh(a0h, a1h);
                    ph[j][2*half + 1] = pkh(b0h, b1h);
                    pl[j][2*half]     = pkh(__float2half_rn(v0 - __half2float(a0h)),
                                            __float2half_rn(v1 - __half2float(a1h)));
                    pl[j][2*half + 1] = pkh(__float2half_rn(w0 - __half2float(b0h)),
                                            __float2half_rn(w1 - __half2float(b1h)));
                }
            }

            // ---- O += Ph.V + Pl.V (2 passes), V^T via ldmatrix.trans ----
            #pragma unroll
            for (int j = 0; j < 4; j++) {
                #pragma unroll
                for (int nb = 0; nb < 4; nb++) {
                    uint32_t off = SW128((uint32_t)(
                        (j*16 + ((g & 1) ? 8 : 0) + r) * 128 +
                        (nb*16 + ((g & 2) ? 8 : 0)) * 2));
                    uint32_t h0, h1, h2, h3;
                    ldm_x4t(st + 8192 + off, h0, h1, h2, h3);   // V
                    mma_fp16(o[2*nb],   ph[j], h0, h1);
                    mma_fp16(o[2*nb+1], ph[j], h2, h3);
                    mma_fp16(o[2*nb],   pl[j], h0, h1);
                    mma_fp16(o[2*nb+1], pl[j], h2, h3);
                }
            }
        }
    }

    // ---- epilogue: o / l, split to bf16 hi/lo into g_y (proj stays bf16) ----
    const float inv0 = 1.0f / l0, inv1 = 1.0f / l1;
    const int batch = bh / HDIM, hh = bh % HDIM;
    const int row = qbase + wid * 16 + (lane >> 2);
    const size_t rb0 = ((size_t)(batch * TDIM + row))     * CDIM + hh * DDIM;
    const size_t rb1 = ((size_t)(batch * TDIM + row + 8)) * CDIM + hh * DDIM;
    #pragma unroll
    for (int nf = 0; nf < 8; nf++) {
        const int d = nf * 8 + (lane & 3) * 2;
        split_store(o[nf][0] * inv0, o[nf][1] * inv0, g_yhi, g_ylo, rb0 + d);
        split_store(o[nf][2] * inv1, o[nf][3] * inv1, g_yhi, g_ylo, rb1 + d);
    }
}

// ---------------------------------------------------------------------------
extern "C" void kernel_launch(void* const* d_in, const int* in_sizes, int n_in,
                              void* d_out, int out_size) {
    const float *x = nullptr, *Wa = nullptr, *ba = nullptr, *Wp = nullptr, *bp = nullptr;
    for (int i = 0; i < n_in; i++) {
        switch (in_sizes[i]) {
            case 6291456: x  = (const float*)d_in[i]; break;   // [2,4096,768]
            case 1769472: Wa = (const float*)d_in[i]; break;   // [768,2304]
            case 2304:    ba = (const float*)d_in[i]; break;
            case 589824:  Wp = (const float*)d_in[i]; break;   // [768,768]
            case 768:     bp = (const float*)d_in[i]; break;
        }
    }

    cudaFuncSetAttribute(qkv_mma,   cudaFuncAttributeMaxDynamicSharedMemorySize, GSMEM);
    cudaFuncSetAttribute(proj_mma,  cudaFuncAttributeMaxDynamicSharedMemorySize, GSMEM);
    cudaFuncSetAttribute(flash_mma, cudaFuncAttributeMaxDynamicSharedMemorySize, FSMEM);

    __nv_bfloat16 *xhi, *xlo, *wahi, *walo, *wphi, *wplo;
    cudaGetSymbolAddress((void**)&xhi,  g_xhi);
    cudaGetSymbolAddress((void**)&xlo,  g_xlo);
    cudaGetSymbolAddress((void**)&wahi, g_WaThi);
    cudaGetSymbolAddress((void**)&walo, g_WaTlo);
    cudaGetSymbolAddress((void**)&wphi, g_WpThi);
    cudaGetSymbolAddress((void**)&wplo, g_WpTlo);

    split_bf16<<<(MTOT*CDIM/2 + 255)/256, 256>>>(x, xhi, xlo, MTOT*CDIM/2);
    wsplit_T<<<dim3(N3DIM/32, CDIM/32), dim3(32, 8)>>>(Wa, wahi, walo, CDIM, N3DIM);
    wsplit_T<<<dim3(CDIM/32,  CDIM/32), dim3(32, 8)>>>(Wp, wphi, wplo, CDIM, CDIM);
    qkv_mma<<<dim3(N3DIM/128, MTOT/128), 512, GSMEM>>>(ba);        // (18,64)
    flash_mma<<<dim3(TDIM/128, BDIM*HDIM), 256, FSMEM>>>();        // (32,24)
    proj_mma<<<dim3(CDIM/128, MTOT/128), 512, GSMEM>>>(bp, (float*)d_out); // (6,64)
}

// round 8
// speedup vs baseline: 1.4570x; 1.1264x over previous
#include <cuda_runtime.h>
#include <cuda_bf16.h>
#include <cuda_fp16.h>
#include <cstdint>

// ---------------------------------------------------------------------------
// Problem constants
// ---------------------------------------------------------------------------
#define BDIM 2
#define TDIM 4096
#define CDIM 768
#define HDIM 12
#define DDIM 64
#define N3DIM 2304            // 3*C
#define MTOT  (BDIM*TDIM)     // 8192

// ---------------------------------------------------------------------------
// Device scratch (no allocation in kernel_launch)
// fp16 2-pass asymmetric everywhere: activations split (exact), weights single.
// ---------------------------------------------------------------------------
__device__ __align__(16) __half g_xh[MTOT*CDIM],  g_xl[MTOT*CDIM];
__device__ __align__(16) __half g_yh[MTOT*CDIM],  g_yl[MTOT*CDIM];
__device__ __align__(16) __half g_WaT[N3DIM*CDIM];   // [N,K] single fp16
__device__ __align__(16) __half g_WpT[CDIM*CDIM];    // [N,K] single fp16
// flash operands, [b*h][t][d] row-major: Q fp16 split (x0.125), K/V single fp16
__device__ __align__(16) __half g_qh[BDIM*HDIM*TDIM*DDIM], g_ql[BDIM*HDIM*TDIM*DDIM];
__device__ __align__(16) __half g_k [BDIM*HDIM*TDIM*DDIM];
__device__ __align__(16) __half g_v [BDIM*HDIM*TDIM*DDIM];

// ---------------------------------------------------------------------------
// Helpers (all sm_80-legal: mma.sync fp16, ldmatrix, cp.async)
// ---------------------------------------------------------------------------
__device__ __forceinline__ uint32_t smem_u32(const void* p) {
    uint32_t a;
    asm("{ .reg .u64 t; cvta.to.shared.u64 t, %1; cvt.u32.u64 %0, t; }"
        : "=r"(a) : "l"(p));
    return a;
}
#define SW128(off) ((off) ^ (((off) >> 3) & 0x70))

__device__ __forceinline__ void cp16(uint32_t dst, const void* src) {
    asm volatile("cp.async.cg.shared.global [%0], [%1], 16;"
                 :: "r"(dst), "l"(src) : "memory");
}
#define CP_COMMIT() asm volatile("cp.async.commit_group;" ::: "memory")
#define CP_WAIT0()  asm volatile("cp.async.wait_group 0;"  ::: "memory")
#define CP_WAIT1()  asm volatile("cp.async.wait_group 1;"  ::: "memory")

__device__ __forceinline__ void ldm_x4(uint32_t a, uint32_t& r0, uint32_t& r1,
                                       uint32_t& r2, uint32_t& r3) {
    asm volatile("ldmatrix.sync.aligned.m8n8.x4.shared.b16 {%0,%1,%2,%3}, [%4];"
                 : "=r"(r0), "=r"(r1), "=r"(r2), "=r"(r3) : "r"(a));
}
__device__ __forceinline__ void ldm_x4t(uint32_t a, uint32_t& r0, uint32_t& r1,
                                        uint32_t& r2, uint32_t& r3) {
    asm volatile("ldmatrix.sync.aligned.m8n8.x4.trans.shared.b16 {%0,%1,%2,%3}, [%4];"
                 : "=r"(r0), "=r"(r1), "=r"(r2), "=r"(r3) : "r"(a));
}
__device__ __forceinline__ void mma_fp16(float (&c)[4], const uint32_t (&a)[4],
                                         uint32_t b0, uint32_t b1) {
    asm volatile("mma.sync.aligned.m16n8k16.row.col.f32.f16.f16.f32 "
                 "{%0,%1,%2,%3}, {%4,%5,%6,%7}, {%8,%9}, {%0,%1,%2,%3};"
                 : "+f"(c[0]), "+f"(c[1]), "+f"(c[2]), "+f"(c[3])
                 : "r"(a[0]), "r"(a[1]), "r"(a[2]), "r"(a[3]), "r"(b0), "r"(b1));
}
// pack two halves into u32 (a -> low, b -> high)
__device__ __forceinline__ uint32_t pkh(__half a, __half b) {
    __half2 t = __halves2half2(a, b);
    return *(uint32_t*)&t;
}
__device__ __forceinline__ float ex2f(float x) {
    float y; asm("ex2.approx.ftz.f32 %0, %1;" : "=f"(y) : "f"(x)); return y;
}
// fp16 2-way split store
__device__ __forceinline__ void split_store_h(float v0, float v1,
                                              __half* hi, __half* lo, size_t idx) {
    __half a0 = __float2half_rn(v0), a1 = __float2half_rn(v1);
    *(uint32_t*)(hi + idx) = pkh(a0, a1);
    *(uint32_t*)(lo + idx) = pkh(__float2half_rn(v0 - __half2float(a0)),
                                 __float2half_rn(v1 - __half2float(a1)));
}

// ---------------------------------------------------------------------------
// Conversion kernels
// ---------------------------------------------------------------------------
__global__ __launch_bounds__(256) void split_f16(const float* __restrict__ in,
                                                 __half* __restrict__ hi,
                                                 __half* __restrict__ lo,
                                                 int n2) {
    int i = blockIdx.x * blockDim.x + threadIdx.x;
    if (i >= n2) return;
    float2 v = ((const float2*)in)[i];
    __half a0 = __float2half_rn(v.x), a1 = __float2half_rn(v.y);
    ((uint32_t*)hi)[i] = pkh(a0, a1);
    ((uint32_t*)lo)[i] = pkh(__float2half_rn(v.x - __half2float(a0)),
                             __float2half_rn(v.y - __half2float(a1)));
}

// W [K,N] fp32 -> WT [N,K] single fp16 (transpose + convert). block (32,8).
__global__ __launch_bounds__(256) void wconv_T(const float* __restrict__ W,
                                               __half* __restrict__ WT,
                                               int K, int N) {
    __shared__ float tile[32][33];
    const int tx = threadIdx.x, ty = threadIdx.y;
    const int bn = blockIdx.x * 32, bk = blockIdx.y * 32;
    #pragma unroll
    for (int i = 0; i < 4; i++)
        tile[ty + 8*i][tx] = W[(size_t)(bk + ty + 8*i) * N + bn + tx];
    __syncthreads();
    #pragma unroll
    for (int i = 0; i < 4; i++)
        WT[(size_t)(bn + ty + 8*i) * K + bk + tx] = __float2half_rn(tile[tx][ty + 8*i]);
}

// ---------------------------------------------------------------------------
// fp16 2-pass asymmetric HMMA GEMM mainloop.
// 512 thr = 16 warps (4m x 4n), warp tile 32x32, CTA 128x128, 3-stage.
// C = Ahi.B^T + Alo.B^T over K=768 (A split exact; B single fp16).
// smem stage (48KB): Ahi@0 Alo@16K B@32K, rows 128B SW128.
// ---------------------------------------------------------------------------
#define GSTAGE 49152
#define GSMEM  (3*GSTAGE)

__device__ __forceinline__ void gemm_issue(const __half* Ahi, const __half* Alo,
                                           const __half* B,
                                           int am0, int bn0, int k0,
                                           uint32_t stbase, int tid) {
    #pragma unroll
    for (int arr = 0; arr < 3; arr++) {
        const __half* base = arr == 0 ? Ahi : arr == 1 ? Alo : B;
        const int r0 = (arr < 2) ? am0 : bn0;
        #pragma unroll
        for (int i = 0; i < 2; i++) {
            int s2 = tid + (i << 9);          // 0..1023
            int row = s2 >> 3, c16 = s2 & 7;
            cp16(stbase + (arr << 14) + SW128((uint32_t)(row*128 + (c16 << 4))),
                 base + (size_t)(r0 + row) * 768 + k0 + (c16 << 3));
        }
    }
    CP_COMMIT();
}

__device__ __forceinline__ void gemm_main(const __half* Ahi, const __half* Alo,
                                          const __half* B,
                                          int am0, int bn0,
                                          float (&acc)[2][4][4], char* sm) {
    const int tid = threadIdx.x;
    const int wid = tid >> 5, lane = tid & 31;
    const uint32_t sb = smem_u32(sm);
    const int wm0 = (wid & 3) * 32;
    const int wn0 = (wid >> 2) * 32;
    const int r = lane & 7, g = lane >> 3;

    gemm_issue(Ahi, Alo, B, am0, bn0, 0,  sb,          tid);
    gemm_issue(Ahi, Alo, B, am0, bn0, 64, sb + GSTAGE, tid);

    for (int c = 0; c < 12; c++) {
        if (c < 11) CP_WAIT1(); else CP_WAIT0();
        __syncthreads();
        if (c < 10)
            gemm_issue(Ahi, Alo, B, am0, bn0, (c+2)*64,
                       sb + (uint32_t)(((c+2)%3) * GSTAGE), tid);
        const uint32_t st = sb + (uint32_t)((c % 3) * GSTAGE);
        #pragma unroll
        for (int kf = 0; kf < 4; kf++) {
            const int k0 = kf * 16;
            uint32_t ah[2][4], al[2][4];
            #pragma unroll
            for (int mf = 0; mf < 2; mf++) {
                uint32_t off = SW128((uint32_t)(
                    (wm0 + mf*16 + ((g & 1) ? 8 : 0) + r) * 128 +
                    (k0 + ((g & 2) ? 8 : 0)) * 2));
                ldm_x4(st + off,         ah[mf][0], ah[mf][1], ah[mf][2], ah[mf][3]);
                ldm_x4(st + 16384 + off, al[mf][0], al[mf][1], al[mf][2], al[mf][3]);
            }
            uint32_t bf[4][2];
            #pragma unroll
            for (int nb = 0; nb < 2; nb++) {
                uint32_t off = SW128((uint32_t)(
                    (wn0 + nb*16 + ((g & 2) ? 8 : 0) + r) * 128 +
                    (k0 + ((g & 1) ? 8 : 0)) * 2));
                uint32_t t0, t1, t2, t3;
                ldm_x4(st + 32768 + off, t0, t1, t2, t3);
                bf[2*nb][0] = t0; bf[2*nb][1] = t1;
                bf[2*nb+1][0] = t2; bf[2*nb+1][1] = t3;
            }
            #pragma unroll
            for (int mf = 0; mf < 2; mf++)
                #pragma unroll
                for (int nf = 0; nf < 4; nf++) {
                    mma_fp16(acc[mf][nf], ah[mf], bf[nf][0], bf[nf][1]);
                    mma_fp16(acc[mf][nf], al[mf], bf[nf][0], bf[nf][1]);
                }
        }
    }
}

// ---------------------------------------------------------------------------
// QKV GEMM: x @ W_attn + b.  Q -> fp16 split (x0.125), K/V -> single fp16.
// grid (18, 64), 512 threads
// ---------------------------------------------------------------------------
__global__ __launch_bounds__(512) void qkv_mma(const float* __restrict__ bias) {
    extern __shared__ char sm[];
    const int bm = blockIdx.y * 128;
    const int bn = blockIdx.x * 128;
    float acc[2][4][4] = {};
    gemm_main(g_xh, g_xl, g_WaT, bm, bn, acc, sm);

    const int wid = threadIdx.x >> 5, lane = threadIdx.x & 31;
    const int which = bn / CDIM;              // 0=q 1=k 2=v (tiles never straddle)
    const int batch = bm >> 12;

    #pragma unroll
    for (int nf = 0; nf < 4; nf++) {
        const int gcol = bn + (wid >> 2) * 32 + nf * 8 + (lane & 3) * 2;
        const float b0 = __ldg(bias + gcol), b1 = __ldg(bias + gcol + 1);
        const int within = gcol % CDIM;
        const int head = within >> 6, d = within & 63;
        #pragma unroll
        for (int mf = 0; mf < 2; mf++) {
            const int t = (bm & (TDIM - 1)) + (wid & 3) * 32 + mf * 16 + (lane >> 2);
            size_t o0 = ((size_t)(batch*HDIM + head)*TDIM + t)     * DDIM + d;
            size_t o1 = ((size_t)(batch*HDIM + head)*TDIM + t + 8) * DDIM + d;
            if (which == 0) {
                split_store_h((acc[mf][nf][0]+b0)*0.125f, (acc[mf][nf][1]+b1)*0.125f,
                              g_qh, g_ql, o0);
                split_store_h((acc[mf][nf][2]+b0)*0.125f, (acc[mf][nf][3]+b1)*0.125f,
                              g_qh, g_ql, o1);
            } else {
                __half* dst = (which == 1) ? g_k : g_v;
                *(uint32_t*)(dst + o0) = pkh(__float2half_rn(acc[mf][nf][0]+b0),
                                             __float2half_rn(acc[mf][nf][1]+b1));
                *(uint32_t*)(dst + o1) = pkh(__float2half_rn(acc[mf][nf][2]+b0),
                                             __float2half_rn(acc[mf][nf][3]+b1));
            }
        }
    }
}

// ---------------------------------------------------------------------------
// Projection GEMM: y @ W_proj + b -> d_out fp32.  grid (6, 64), 512 threads
// ---------------------------------------------------------------------------
__global__ __launch_bounds__(512) void proj_mma(const float* __restrict__ bias,
                                                float* __restrict__ out) {
    extern __shared__ char sm[];
    const int bm = blockIdx.y * 128;
    const int bn = blockIdx.x * 128;
    float acc[2][4][4] = {};
    gemm_main(g_yh, g_yl, g_WpT, bm, bn, acc, sm);

    const int wid = threadIdx.x >> 5, lane = threadIdx.x & 31;
    #pragma unroll
    for (int nf = 0; nf < 4; nf++) {
        const int gcol = bn + (wid >> 2) * 32 + nf * 8 + (lane & 3) * 2;
        const float b0 = __ldg(bias + gcol), b1 = __ldg(bias + gcol + 1);
        #pragma unroll
        for (int mf = 0; mf < 2; mf++) {
            const int m = bm + (wid & 3) * 32 + mf * 16 + (lane >> 2);
            *(float2*)(out + (size_t)m * CDIM + gcol) =
                make_float2(acc[mf][nf][0] + b0, acc[mf][nf][1] + b1);
            *(float2*)(out + (size_t)(m + 8) * CDIM + gcol) =
                make_float2(acc[mf][nf][2] + b0, acc[mf][nf][3] + b1);
        }
    }
}

// ---------------------------------------------------------------------------
// Flash attention, fp16 2-pass HMMA (proven R7 form).
// grid (32 q-tiles, 24 bh), 256 thr, 1 CTA/SM.  Q fp16-split in registers;
// K,V single fp16 in smem (stage 16KB: K@0 V@8K), 3-stage cp.async.
// S = Qh.K + Ql.K ;  O = Ph.V + Pl.V  (split side exact).
// ---------------------------------------------------------------------------
#define FSMEM (3*16384)

__global__ __launch_bounds__(256) void flash_mma() {
    extern __shared__ char sm[];
    const uint32_t sb = smem_u32(sm);
    const int tid = threadIdx.x, wid = tid >> 5, lane = tid & 31;
    const int qt = (int)gridDim.x - 1 - (int)blockIdx.x;   // heavy tiles first
    const int bh = blockIdx.y;
    const int qbase = qt * 128;
    const int ntiles = (qbase + 128) / 64;                  // 2qt+2 (>= 2)

    const __half* qhp = g_qh + (size_t)bh * TDIM * DDIM;
    const __half* qlp = g_ql + (size_t)bh * TDIM * DDIM;
    const __half* kp  = g_k  + (size_t)bh * TDIM * DDIM;
    const __half* vp  = g_v  + (size_t)bh * TDIM * DDIM;

    // Q fragments, register resident (fp16 split)
    uint32_t qh[4][4], ql[4][4];
    {
        const int row = qbase + wid * 16 + (lane >> 2);
        const int colb = (lane & 3) * 2;
        #pragma unroll
        for (int kf = 0; kf < 4; kf++)
            #pragma unroll
            for (int a = 0; a < 4; a++) {
                int rr = row + ((a & 1) ? 8 : 0);
                int cc = kf * 16 + colb + ((a & 2) ? 8 : 0);
                qh[kf][a] = *(const uint32_t*)(qhp + (size_t)rr * DDIM + cc);
                ql[kf][a] = *(const uint32_t*)(qlp + (size_t)rr * DDIM + cc);
            }
    }

    float m0 = -1e30f, m1 = -1e30f, l0 = 0.f, l1 = 0.f;
    float o[8][4] = {};
    const int qhi_row = qbase + wid * 16 + 15;
    const int r = lane & 7, g = lane >> 3;
    const float LOG2E = 1.4426950408889634f;

    // K/V tile loader (cp.async, 4 x 16B per thread; stage = 16KB)
    auto issue = [&](int jt) {
        const int kb = jt * 64;
        const uint32_t stg = sb + (uint32_t)((jt % 3) << 14);
        #pragma unroll
        for (int arr = 0; arr < 2; arr++) {
            const __half* base = arr == 0 ? kp : vp;
            #pragma unroll
            for (int i = 0; i < 2; i++) {
                int s2 = tid + (i << 8);            // 0..511
                int row = s2 >> 3, c16 = s2 & 7;
                cp16(stg + (arr << 13) + SW128((uint32_t)(row*128 + (c16 << 4))),
                     base + (size_t)(kb + row) * DDIM + (c16 << 3));
            }
        }
        CP_COMMIT();
    };
    issue(0);
    issue(1);

    for (int jt = 0; jt < ntiles; jt++) {
        if (jt + 1 < ntiles) CP_WAIT1(); else CP_WAIT0();
        __syncthreads();
        if (jt + 2 < ntiles) issue(jt + 2);
        const int kb = jt * 64;
        if (kb <= qhi_row) {                        // causal per-warp skip
            const uint32_t st = sb + (uint32_t)((jt % 3) << 14);

            // ---- S = Qh.K + Ql.K (2 passes) ----
            float s[8][4] = {};
            #pragma unroll
            for (int kf = 0; kf < 4; kf++) {
                const int k0 = kf * 16;
                #pragma unroll
                for (int nb = 0; nb < 4; nb++) {
                    uint32_t off = SW128((uint32_t)(
                        (nb*16 + ((g & 2) ? 8 : 0) + r) * 128 +
                        (k0 + ((g & 1) ? 8 : 0)) * 2));
                    uint32_t h0, h1, h2, h3;
                    ldm_x4(st + off, h0, h1, h2, h3);          // K
                    mma_fp16(s[2*nb],   qh[kf], h0, h1);
                    mma_fp16(s[2*nb+1], qh[kf], h2, h3);
                    mma_fp16(s[2*nb],   ql[kf], h0, h1);
                    mma_fp16(s[2*nb+1], ql[kf], h2, h3);
                }
            }

            // ---- causal mask (diagonal tiles only) ----
            const int row0 = qbase + wid * 16 + (lane >> 2);
            if (kb + 63 > row0) {
                #pragma unroll
                for (int nf = 0; nf < 8; nf++) {
                    int col = kb + nf * 8 + (lane & 3) * 2;
                    if (col     > row0)     s[nf][0] = -1e30f;
                    if (col + 1 > row0)     s[nf][1] = -1e30f;
                    if (col     > row0 + 8) s[nf][2] = -1e30f;
                    if (col + 1 > row0 + 8) s[nf][3] = -1e30f;
                }
            }

            // ---- online softmax ----
            float rmax0 = -1e30f, rmax1 = -1e30f;
            #pragma unroll
            for (int nf = 0; nf < 8; nf++) {
                rmax0 = fmaxf(rmax0, fmaxf(s[nf][0], s[nf][1]));
                rmax1 = fmaxf(rmax1, fmaxf(s[nf][2], s[nf][3]));
            }
            rmax0 = fmaxf(rmax0, __shfl_xor_sync(0xffffffffu, rmax0, 1));
            rmax0 = fmaxf(rmax0, __shfl_xor_sync(0xffffffffu, rmax0, 2));
            rmax1 = fmaxf(rmax1, __shfl_xor_sync(0xffffffffu, rmax1, 1));
            rmax1 = fmaxf(rmax1, __shfl_xor_sync(0xffffffffu, rmax1, 2));
            const float mn0 = fmaxf(m0, rmax0), mn1 = fmaxf(m1, rmax1);
            const float a0 = ex2f((m0 - mn0) * LOG2E);
            const float a1 = ex2f((m1 - mn1) * LOG2E);
            m0 = mn0; m1 = mn1;
            const float ml0 = mn0 * LOG2E, ml1 = mn1 * LOG2E;
            float rs0 = 0.f, rs1 = 0.f;
            #pragma unroll
            for (int nf = 0; nf < 8; nf++) {
                s[nf][0] = ex2f(fmaf(s[nf][0], LOG2E, -ml0));
                s[nf][1] = ex2f(fmaf(s[nf][1], LOG2E, -ml0));
                s[nf][2] = ex2f(fmaf(s[nf][2], LOG2E, -ml1));
                s[nf][3] = ex2f(fmaf(s[nf][3], LOG2E, -ml1));
                rs0 += s[nf][0] + s[nf][1];
                rs1 += s[nf][2] + s[nf][3];
            }
            rs0 += __shfl_xor_sync(0xffffffffu, rs0, 1);
            rs0 += __shfl_xor_sync(0xffffffffu, rs0, 2);
            rs1 += __shfl_xor_sync(0xffffffffu, rs1, 1);
            rs1 += __shfl_xor_sync(0xffffffffu, rs1, 2);
            l0 = l0 * a0 + rs0;
            l1 = l1 * a1 + rs1;
            #pragma unroll
            for (int nf = 0; nf < 8; nf++) {
                o[nf][0] *= a0; o[nf][1] *= a0;
                o[nf][2] *= a1; o[nf][3] *= a1;
            }

            // ---- P -> fp16 hi/lo A-fragments (registers only) ----
            uint32_t ph[4][4], pl[4][4];
            #pragma unroll
            for (int j = 0; j < 4; j++) {
                #pragma unroll
                for (int half = 0; half < 2; half++) {
                    float v0 = s[2*j + half][0], v1 = s[2*j + half][1];
                    float w0 = s[2*j + half][2], w1 = s[2*j + half][3];
                    __half a0h = __float2half_rn(v0), a1h = __float2half_rn(v1);
                    __half b0h = __float2half_rn(w0), b1h = __float2half_rn(w1);
                    ph[j][2*half]     = pkh(a0h, a1h);
                    ph[j][2*half + 1] = pkh(b0h, b1h);
                    pl[j][2*half]     = pkh(__float2half_rn(v0 - __half2float(a0h)),
                                            __float2half_rn(v1 - __half2float(a1h)));
                    pl[j][2*half + 1] = pkh(__float2half_rn(w0 - __half2float(b0h)),
                                            __float2half_rn(w1 - __half2float(b1h)));
                }
            }

            // ---- O += Ph.V + Pl.V (2 passes), V^T via ldmatrix.trans ----
            #pragma unroll
            for (int j = 0; j < 4; j++) {
                #pragma unroll
                for (int nb = 0; nb < 4; nb++) {
                    uint32_t off = SW128((uint32_t)(
                        (j*16 + ((g & 1) ? 8 : 0) + r) * 128 +
                        (nb*16 + ((g & 2) ? 8 : 0)) * 2));
                    uint32_t h0, h1, h2, h3;
                    ldm_x4t(st + 8192 + off, h0, h1, h2, h3);   // V
                    mma_fp16(o[2*nb],   ph[j], h0, h1);
                    mma_fp16(o[2*nb+1], ph[j], h2, h3);
                    mma_fp16(o[2*nb],   pl[j], h0, h1);
                    mma_fp16(o[2*nb+1], pl[j], h2, h3);
                }
            }
        }
    }

    // ---- epilogue: o / l, fp16 split into g_yh/g_yl (feeds proj 2-pass) ----
    const float inv0 = 1.0f / l0, inv1 = 1.0f / l1;
    const int batch = bh / HDIM, hh = bh % HDIM;
    const int row = qbase + wid * 16 + (lane >> 2);
    const size_t rb0 = ((size_t)(batch * TDIM + row))     * CDIM + hh * DDIM;
    const size_t rb1 = ((size_t)(batch * TDIM + row + 8)) * CDIM + hh * DDIM;
    #pragma unroll
    for (int nf = 0; nf < 8; nf++) {
        const int d = nf * 8 + (lane & 3) * 2;
        split_store_h(o[nf][0] * inv0, o[nf][1] * inv0, g_yh, g_yl, rb0 + d);
        split_store_h(o[nf][2] * inv1, o[nf][3] * inv1, g_yh, g_yl, rb1 + d);
    }
}

// ---------------------------------------------------------------------------
extern "C" void kernel_launch(void* const* d_in, const int* in_sizes, int n_in,
                              void* d_out, int out_size) {
    const float *x = nullptr, *Wa = nullptr, *ba = nullptr, *Wp = nullptr, *bp = nullptr;
    for (int i = 0; i < n_in; i++) {
        switch (in_sizes[i]) {
            case 6291456: x  = (const float*)d_in[i]; break;   // [2,4096,768]
            case 1769472: Wa = (const float*)d_in[i]; break;   // [768,2304]
            case 2304:    ba = (const float*)d_in[i]; break;
            case 589824:  Wp = (const float*)d_in[i]; break;   // [768,768]
            case 768:     bp = (const float*)d_in[i]; break;
        }
    }

    cudaFuncSetAttribute(qkv_mma,   cudaFuncAttributeMaxDynamicSharedMemorySize, GSMEM);
    cudaFuncSetAttribute(proj_mma,  cudaFuncAttributeMaxDynamicSharedMemorySize, GSMEM);
    cudaFuncSetAttribute(flash_mma, cudaFuncAttributeMaxDynamicSharedMemorySize, FSMEM);

    __half *xh, *xl, *wat, *wpt;
    cudaGetSymbolAddress((void**)&xh,  g_xh);
    cudaGetSymbolAddress((void**)&xl,  g_xl);
    cudaGetSymbolAddress((void**)&wat, g_WaT);
    cudaGetSymbolAddress((void**)&wpt, g_WpT);

    split_f16<<<(MTOT*CDIM/2 + 255)/256, 256>>>(x, xh, xl, MTOT*CDIM/2);
    wconv_T<<<dim3(N3DIM/32, CDIM/32), dim3(32, 8)>>>(Wa, wat, CDIM, N3DIM);
    wconv_T<<<dim3(CDIM/32,  CDIM/32), dim3(32, 8)>>>(Wp, wpt, CDIM, CDIM);
    qkv_mma<<<dim3(N3DIM/128, MTOT/128), 512, GSMEM>>>(ba);        // (18,64)
    flash_mma<<<dim3(TDIM/128, BDIM*HDIM), 256, FSMEM>>>();        // (32,24)
    proj_mma<<<dim3(CDIM/128, MTOT/128), 512, GSMEM>>>(bp, (float*)d_out); // (6,64)
}

// round 9
// speedup vs baseline: 1.7747x; 1.2180x over previous
#include <cuda_runtime.h>
#include <cuda_bf16.h>
#include <cuda_fp16.h>
#include <cstdint>

// ---------------------------------------------------------------------------
// Problem constants
// ---------------------------------------------------------------------------
#define BDIM 2
#define TDIM 4096
#define CDIM 768
#define HDIM 12
#define DDIM 64
#define N3DIM 2304            // 3*C
#define MTOT  (BDIM*TDIM)     // 8192

// ---------------------------------------------------------------------------
// Device scratch (no allocation in kernel_launch)
// GEMMs: fp16 2-pass asymmetric (activations split exact, weights single).
// Flash: pure fp16 single-pass (Q pre-scaled, K, V single fp16).
// ---------------------------------------------------------------------------
__device__ __align__(16) __half g_xh[MTOT*CDIM],  g_xl[MTOT*CDIM];
__device__ __align__(16) __half g_yh[MTOT*CDIM],  g_yl[MTOT*CDIM];
__device__ __align__(16) __half g_WaT[N3DIM*CDIM];   // [N,K] single fp16
__device__ __align__(16) __half g_WpT[CDIM*CDIM];    // [N,K] single fp16
__device__ __align__(16) __half g_q[BDIM*HDIM*TDIM*DDIM];   // x0.125
__device__ __align__(16) __half g_k[BDIM*HDIM*TDIM*DDIM];
__device__ __align__(16) __half g_v[BDIM*HDIM*TDIM*DDIM];

// ---------------------------------------------------------------------------
// Helpers (all sm_80-legal: mma.sync fp16, ldmatrix, cp.async)
// ---------------------------------------------------------------------------
__device__ __forceinline__ uint32_t smem_u32(const void* p) {
    uint32_t a;
    asm("{ .reg .u64 t; cvta.to.shared.u64 t, %1; cvt.u32.u64 %0, t; }"
        : "=r"(a) : "l"(p));
    return a;
}
#define SW128(off) ((off) ^ (((off) >> 3) & 0x70))

__device__ __forceinline__ void cp16(uint32_t dst, const void* src) {
    asm volatile("cp.async.cg.shared.global [%0], [%1], 16;"
                 :: "r"(dst), "l"(src) : "memory");
}
#define CP_COMMIT() asm volatile("cp.async.commit_group;" ::: "memory")
#define CP_WAIT0()  asm volatile("cp.async.wait_group 0;"  ::: "memory")
#define CP_WAIT1()  asm volatile("cp.async.wait_group 1;"  ::: "memory")

__device__ __forceinline__ void ldm_x4(uint32_t a, uint32_t& r0, uint32_t& r1,
                                       uint32_t& r2, uint32_t& r3) {
    asm volatile("ldmatrix.sync.aligned.m8n8.x4.shared.b16 {%0,%1,%2,%3}, [%4];"
                 : "=r"(r0), "=r"(r1), "=r"(r2), "=r"(r3) : "r"(a));
}
__device__ __forceinline__ void ldm_x4t(uint32_t a, uint32_t& r0, uint32_t& r1,
                                        uint32_t& r2, uint32_t& r3) {
    asm volatile("ldmatrix.sync.aligned.m8n8.x4.trans.shared.b16 {%0,%1,%2,%3}, [%4];"
                 : "=r"(r0), "=r"(r1), "=r"(r2), "=r"(r3) : "r"(a));
}
__device__ __forceinline__ void mma_fp16(float (&c)[4], const uint32_t (&a)[4],
                                         uint32_t b0, uint32_t b1) {
    asm volatile("mma.sync.aligned.m16n8k16.row.col.f32.f16.f16.f32 "
                 "{%0,%1,%2,%3}, {%4,%5,%6,%7}, {%8,%9}, {%0,%1,%2,%3};"
                 : "+f"(c[0]), "+f"(c[1]), "+f"(c[2]), "+f"(c[3])
                 : "r"(a[0]), "r"(a[1]), "r"(a[2]), "r"(a[3]), "r"(b0), "r"(b1));
}
// pack two halves into u32 (a -> low, b -> high)
__device__ __forceinline__ uint32_t pkh(__half a, __half b) {
    __half2 t = __halves2half2(a, b);
    return *(uint32_t*)&t;
}
__device__ __forceinline__ float ex2f(float x) {
    float y; asm("ex2.approx.ftz.f32 %0, %1;" : "=f"(y) : "f"(x)); return y;
}
// fp16 2-way split store
__device__ __forceinline__ void split_store_h(float v0, float v1,
                                              __half* hi, __half* lo, size_t idx) {
    __half a0 = __float2half_rn(v0), a1 = __float2half_rn(v1);
    *(uint32_t*)(hi + idx) = pkh(a0, a1);
    *(uint32_t*)(lo + idx) = pkh(__float2half_rn(v0 - __half2float(a0)),
                                 __float2half_rn(v1 - __half2float(a1)));
}

// ---------------------------------------------------------------------------
// Conversion kernels
// ---------------------------------------------------------------------------
__global__ __launch_bounds__(256) void split_f16(const float* __restrict__ in,
                                                 __half* __restrict__ hi,
                                                 __half* __restrict__ lo,
                                                 int n2) {
    int i = blockIdx.x * blockDim.x + threadIdx.x;
    if (i >= n2) return;
    float2 v = ((const float2*)in)[i];
    __half a0 = __float2half_rn(v.x), a1 = __float2half_rn(v.y);
    ((uint32_t*)hi)[i] = pkh(a0, a1);
    ((uint32_t*)lo)[i] = pkh(__float2half_rn(v.x - __half2float(a0)),
                             __float2half_rn(v.y - __half2float(a1)));
}

// W [K,N] fp32 -> WT [N,K] single fp16 (transpose + convert). block (32,8).
__global__ __launch_bounds__(256) void wconv_T(const float* __restrict__ W,
                                               __half* __restrict__ WT,
                                               int K, int N) {
    __shared__ float tile[32][33];
    const int tx = threadIdx.x, ty = threadIdx.y;
    const int bn = blockIdx.x * 32, bk = blockIdx.y * 32;
    #pragma unroll
    for (int i = 0; i < 4; i++)
        tile[ty + 8*i][tx] = W[(size_t)(bk + ty + 8*i) * N + bn + tx];
    __syncthreads();
    #pragma unroll
    for (int i = 0; i < 4; i++)
        WT[(size_t)(bn + ty + 8*i) * K + bk + tx] = __float2half_rn(tile[tx][ty + 8*i]);
}

// ---------------------------------------------------------------------------
// fp16 2-pass asymmetric HMMA GEMM mainloop (proven R8 form).
// 512 thr = 16 warps (4m x 4n), warp tile 32x32, CTA 128x128, 3-stage.
// C = Ahi.B^T + Alo.B^T over K=768 (A split exact; B single fp16).
// smem stage (48KB): Ahi@0 Alo@16K B@32K, rows 128B SW128.
// ---------------------------------------------------------------------------
#define GSTAGE 49152
#define GSMEM  (3*GSTAGE)

__device__ __forceinline__ void gemm_issue(const __half* Ahi, const __half* Alo,
                                           const __half* B,
                                           int am0, int bn0, int k0,
                                           uint32_t stbase, int tid) {
    #pragma unroll
    for (int arr = 0; arr < 3; arr++) {
        const __half* base = arr == 0 ? Ahi : arr == 1 ? Alo : B;
        const int r0 = (arr < 2) ? am0 : bn0;
        #pragma unroll
        for (int i = 0; i < 2; i++) {
            int s2 = tid + (i << 9);          // 0..1023
            int row = s2 >> 3, c16 = s2 & 7;
            cp16(stbase + (arr << 14) + SW128((uint32_t)(row*128 + (c16 << 4))),
                 base + (size_t)(r0 + row) * 768 + k0 + (c16 << 3));
        }
    }
    CP_COMMIT();
}

__device__ __forceinline__ void gemm_main(const __half* Ahi, const __half* Alo,
                                          const __half* B,
                                          int am0, int bn0,
                                          float (&acc)[2][4][4], char* sm) {
    const int tid = threadIdx.x;
    const int wid = tid >> 5, lane = tid & 31;
    const uint32_t sb = smem_u32(sm);
    const int wm0 = (wid & 3) * 32;
    const int wn0 = (wid >> 2) * 32;
    const int r = lane & 7, g = lane >> 3;

    gemm_issue(Ahi, Alo, B, am0, bn0, 0,  sb,          tid);
    gemm_issue(Ahi, Alo, B, am0, bn0, 64, sb + GSTAGE, tid);

    for (int c = 0; c < 12; c++) {
        if (c < 11) CP_WAIT1(); else CP_WAIT0();
        __syncthreads();
        if (c < 10)
            gemm_issue(Ahi, Alo, B, am0, bn0, (c+2)*64,
                       sb + (uint32_t)(((c+2)%3) * GSTAGE), tid);
        const uint32_t st = sb + (uint32_t)((c % 3) * GSTAGE);
        #pragma unroll
        for (int kf = 0; kf < 4; kf++) {
            const int k0 = kf * 16;
            uint32_t ah[2][4], al[2][4];
            #pragma unroll
            for (int mf = 0; mf < 2; mf++) {
                uint32_t off = SW128((uint32_t)(
                    (wm0 + mf*16 + ((g & 1) ? 8 : 0) + r) * 128 +
                    (k0 + ((g & 2) ? 8 : 0)) * 2));
                ldm_x4(st + off,         ah[mf][0], ah[mf][1], ah[mf][2], ah[mf][3]);
                ldm_x4(st + 16384 + off, al[mf][0], al[mf][1], al[mf][2], al[mf][3]);
            }
            uint32_t bf[4][2];
            #pragma unroll
            for (int nb = 0; nb < 2; nb++) {
                uint32_t off = SW128((uint32_t)(
                    (wn0 + nb*16 + ((g & 2) ? 8 : 0) + r) * 128 +
                    (k0 + ((g & 1) ? 8 : 0)) * 2));
                uint32_t t0, t1, t2, t3;
                ldm_x4(st + 32768 + off, t0, t1, t2, t3);
                bf[2*nb][0] = t0; bf[2*nb][1] = t1;
                bf[2*nb+1][0] = t2; bf[2*nb+1][1] = t3;
            }
            #pragma unroll
            for (int mf = 0; mf < 2; mf++)
                #pragma unroll
                for (int nf = 0; nf < 4; nf++) {
                    mma_fp16(acc[mf][nf], ah[mf], bf[nf][0], bf[nf][1]);
                    mma_fp16(acc[mf][nf], al[mf], bf[nf][0], bf[nf][1]);
                }
        }
    }
}

// ---------------------------------------------------------------------------
// QKV GEMM: x @ W_attn + b.  q (x0.125), k, v -> single fp16 [b*h][t][d].
// grid (18, 64), 512 threads
// ---------------------------------------------------------------------------
__global__ __launch_bounds__(512) void qkv_mma(const float* __restrict__ bias) {
    extern __shared__ char sm[];
    const int bm = blockIdx.y * 128;
    const int bn = blockIdx.x * 128;
    float acc[2][4][4] = {};
    gemm_main(g_xh, g_xl, g_WaT, bm, bn, acc, sm);

    const int wid = threadIdx.x >> 5, lane = threadIdx.x & 31;
    const int which = bn / CDIM;              // 0=q 1=k 2=v (tiles never straddle)
    const int batch = bm >> 12;
    const float sc = (which == 0) ? 0.125f : 1.0f;
    __half* dst = which == 0 ? g_q : which == 1 ? g_k : g_v;

    #pragma unroll
    for (int nf = 0; nf < 4; nf++) {
        const int gcol = bn + (wid >> 2) * 32 + nf * 8 + (lane & 3) * 2;
        const float b0 = __ldg(bias + gcol), b1 = __ldg(bias + gcol + 1);
        const int within = gcol % CDIM;
        const int head = within >> 6, d = within & 63;
        #pragma unroll
        for (int mf = 0; mf < 2; mf++) {
            const int t = (bm & (TDIM - 1)) + (wid & 3) * 32 + mf * 16 + (lane >> 2);
            size_t o0 = ((size_t)(batch*HDIM + head)*TDIM + t)     * DDIM + d;
            size_t o1 = ((size_t)(batch*HDIM + head)*TDIM + t + 8) * DDIM + d;
            *(uint32_t*)(dst + o0) = pkh(__float2half_rn((acc[mf][nf][0]+b0)*sc),
                                         __float2half_rn((acc[mf][nf][1]+b1)*sc));
            *(uint32_t*)(dst + o1) = pkh(__float2half_rn((acc[mf][nf][2]+b0)*sc),
                                         __float2half_rn((acc[mf][nf][3]+b1)*sc));
        }
    }
}

// ---------------------------------------------------------------------------
// Projection GEMM: y @ W_proj + b -> d_out fp32.  grid (6, 64), 512 threads
// ---------------------------------------------------------------------------
__global__ __launch_bounds__(512) void proj_mma(const float* __restrict__ bias,
                                                float* __restrict__ out) {
    extern __shared__ char sm[];
    const int bm = blockIdx.y * 128;
    const int bn = blockIdx.x * 128;
    float acc[2][4][4] = {};
    gemm_main(g_yh, g_yl, g_WpT, bm, bn, acc, sm);

    const int wid = threadIdx.x >> 5, lane = threadIdx.x & 31;
    #pragma unroll
    for (int nf = 0; nf < 4; nf++) {
        const int gcol = bn + (wid >> 2) * 32 + nf * 8 + (lane & 3) * 2;
        const float b0 = __ldg(bias + gcol), b1 = __ldg(bias + gcol + 1);
        #pragma unroll
        for (int mf = 0; mf < 2; mf++) {
            const int m = bm + (wid & 3) * 32 + mf * 16 + (lane >> 2);
            *(float2*)(out + (size_t)m * CDIM + gcol) =
                make_float2(acc[mf][nf][0] + b0, acc[mf][nf][1] + b1);
            *(float2*)(out + (size_t)(m + 8) * CDIM + gcol) =
                make_float2(acc[mf][nf][2] + b0, acc[mf][nf][3] + b1);
        }
    }
}

// ---------------------------------------------------------------------------
// Flash attention, pure fp16 single-pass HMMA.
// grid (32 q-tiles, 24 bh), 256 thr, 1 CTA/SM.  Q fp16 in registers;
// K,V single fp16 in smem (stage 16KB: K@0 V@8K), 3-stage cp.async.
// S = Q.K ;  O = P.V  (single pass each).
// ---------------------------------------------------------------------------
#define FSMEM (3*16384)

__global__ __launch_bounds__(256) void flash_mma() {
    extern __shared__ char sm[];
    const uint32_t sb = smem_u32(sm);
    const int tid = threadIdx.x, wid = tid >> 5, lane = tid & 31;
    const int qt = (int)gridDim.x - 1 - (int)blockIdx.x;   // heavy tiles first
    const int bh = blockIdx.y;
    const int qbase = qt * 128;
    const int ntiles = (qbase + 128) / 64;                  // 2qt+2 (>= 2)

    const __half* qp = g_q + (size_t)bh * TDIM * DDIM;
    const __half* kp = g_k + (size_t)bh * TDIM * DDIM;
    const __half* vp = g_v + (size_t)bh * TDIM * DDIM;

    // Q fragments, register resident
    uint32_t qf[4][4];
    {
        const int row = qbase + wid * 16 + (lane >> 2);
        const int colb = (lane & 3) * 2;
        #pragma unroll
        for (int kf = 0; kf < 4; kf++)
            #pragma unroll
            for (int a = 0; a < 4; a++) {
                int rr = row + ((a & 1) ? 8 : 0);
                int cc = kf * 16 + colb + ((a & 2) ? 8 : 0);
                qf[kf][a] = *(const uint32_t*)(qp + (size_t)rr * DDIM + cc);
            }
    }

    float m0 = -1e30f, m1 = -1e30f, l0 = 0.f, l1 = 0.f;
    float o[8][4] = {};
    const int qhi_row = qbase + wid * 16 + 15;
    const int r = lane & 7, g = lane >> 3;
    const float LOG2E = 1.4426950408889634f;

    // K/V tile loader (cp.async, 4 x 16B per thread; stage = 16KB)
    auto issue = [&](int jt) {
        const int kb = jt * 64;
        const uint32_t stg = sb + (uint32_t)((jt % 3) << 14);
        #pragma unroll
        for (int arr = 0; arr < 2; arr++) {
            const __half* base = arr == 0 ? kp : vp;
            #pragma unroll
            for (int i = 0; i < 2; i++) {
                int s2 = tid + (i << 8);            // 0..511
                int row = s2 >> 3, c16 = s2 & 7;
                cp16(stg + (arr << 13) + SW128((uint32_t)(row*128 + (c16 << 4))),
                     base + (size_t)(kb + row) * DDIM + (c16 << 3));
            }
        }
        CP_COMMIT();
    };
    issue(0);
    issue(1);

    for (int jt = 0; jt < ntiles; jt++) {
        if (jt + 1 < ntiles) CP_WAIT1(); else CP_WAIT0();
        __syncthreads();
        if (jt + 2 < ntiles) issue(jt + 2);
        const int kb = jt * 64;
        if (kb <= qhi_row) {                        // causal per-warp skip
            const uint32_t st = sb + (uint32_t)((jt % 3) << 14);

            // ---- S = Q.K (single pass) ----
            float s[8][4] = {};
            #pragma unroll
            for (int kf = 0; kf < 4; kf++) {
                const int k0 = kf * 16;
                #pragma unroll
                for (int nb = 0; nb < 4; nb++) {
                    uint32_t off = SW128((uint32_t)(
                        (nb*16 + ((g & 2) ? 8 : 0) + r) * 128 +
                        (k0 + ((g & 1) ? 8 : 0)) * 2));
                    uint32_t h0, h1, h2, h3;
                    ldm_x4(st + off, h0, h1, h2, h3);          // K
                    mma_fp16(s[2*nb],   qf[kf], h0, h1);
                    mma_fp16(s[2*nb+1], qf[kf], h2, h3);
                }
            }

            // ---- causal mask (diagonal tiles only) ----
            const int row0 = qbase + wid * 16 + (lane >> 2);
            if (kb + 63 > row0) {
                #pragma unroll
                for (int nf = 0; nf < 8; nf++) {
                    int col = kb + nf * 8 + (lane & 3) * 2;
                    if (col     > row0)     s[nf][0] = -1e30f;
                    if (col + 1 > row0)     s[nf][1] = -1e30f;
                    if (col     > row0 + 8) s[nf][2] = -1e30f;
                    if (col + 1 > row0 + 8) s[nf][3] = -1e30f;
                }
            }

            // ---- online softmax ----
            float rmax0 = -1e30f, rmax1 = -1e30f;
            #pragma unroll
            for (int nf = 0; nf < 8; nf++) {
                rmax0 = fmaxf(rmax0, fmaxf(s[nf][0], s[nf][1]));
                rmax1 = fmaxf(rmax1, fmaxf(s[nf][2], s[nf][3]));
            }
            rmax0 = fmaxf(rmax0, __shfl_xor_sync(0xffffffffu, rmax0, 1));
            rmax0 = fmaxf(rmax0, __shfl_xor_sync(0xffffffffu, rmax0, 2));
            rmax1 = fmaxf(rmax1, __shfl_xor_sync(0xffffffffu, rmax1, 1));
            rmax1 = fmaxf(rmax1, __shfl_xor_sync(0xffffffffu, rmax1, 2));
            const float mn0 = fmaxf(m0, rmax0), mn1 = fmaxf(m1, rmax1);
            const float a0 = ex2f((m0 - mn0) * LOG2E);
            const float a1 = ex2f((m1 - mn1) * LOG2E);
            m0 = mn0; m1 = mn1;
            const float ml0 = mn0 * LOG2E, ml1 = mn1 * LOG2E;
            float rs0 = 0.f, rs1 = 0.f;
            #pragma unroll
            for (int nf = 0; nf < 8; nf++) {
                s[nf][0] = ex2f(fmaf(s[nf][0], LOG2E, -ml0));
                s[nf][1] = ex2f(fmaf(s[nf][1], LOG2E, -ml0));
                s[nf][2] = ex2f(fmaf(s[nf][2], LOG2E, -ml1));
                s[nf][3] = ex2f(fmaf(s[nf][3], LOG2E, -ml1));
                rs0 += s[nf][0] + s[nf][1];
                rs1 += s[nf][2] + s[nf][3];
            }
            rs0 += __shfl_xor_sync(0xffffffffu, rs0, 1);
            rs0 += __shfl_xor_sync(0xffffffffu, rs0, 2);
            rs1 += __shfl_xor_sync(0xffffffffu, rs1, 1);
            rs1 += __shfl_xor_sync(0xffffffffu, rs1, 2);
            l0 = l0 * a0 + rs0;
            l1 = l1 * a1 + rs1;
            #pragma unroll
            for (int nf = 0; nf < 8; nf++) {
                o[nf][0] *= a0; o[nf][1] *= a0;
                o[nf][2] *= a1; o[nf][3] *= a1;
            }

            // ---- P -> fp16 A-fragments (registers only) ----
            uint32_t pf[4][4];
            #pragma unroll
            for (int j = 0; j < 4; j++) {
                #pragma unroll
                for (int half = 0; half < 2; half++) {
                    pf[j][2*half]     = pkh(__float2half_rn(s[2*j + half][0]),
                                            __float2half_rn(s[2*j + half][1]));
                    pf[j][2*half + 1] = pkh(__float2half_rn(s[2*j + half][2]),
                                            __float2half_rn(s[2*j + half][3]));
                }
            }

            // ---- O += P.V (single pass), V^T via ldmatrix.trans ----
            #pragma unroll
            for (int j = 0; j < 4; j++) {
                #pragma unroll
                for (int nb = 0; nb < 4; nb++) {
                    uint32_t off = SW128((uint32_t)(
                        (j*16 + ((g & 1) ? 8 : 0) + r) * 128 +
                        (nb*16 + ((g & 2) ? 8 : 0)) * 2));
                    uint32_t h0, h1, h2, h3;
                    ldm_x4t(st + 8192 + off, h0, h1, h2, h3);   // V
                    mma_fp16(o[2*nb],   pf[j], h0, h1);
                    mma_fp16(o[2*nb+1], pf[j], h2, h3);
                }
            }
        }
    }

    // ---- epilogue: o / l, fp16 split into g_yh/g_yl (feeds proj 2-pass) ----
    const float inv0 = 1.0f / l0, inv1 = 1.0f / l1;
    const int batch = bh / HDIM, hh = bh % HDIM;
    const int row = qbase + wid * 16 + (lane >> 2);
    const size_t rb0 = ((size_t)(batch * TDIM + row))     * CDIM + hh * DDIM;
    const size_t rb1 = ((size_t)(batch * TDIM + row + 8)) * CDIM + hh * DDIM;
    #pragma unroll
    for (int nf = 0; nf < 8; nf++) {
        const int d = nf * 8 + (lane & 3) * 2;
        split_store_h(o[nf][0] * inv0, o[nf][1] * inv0, g_yh, g_yl, rb0 + d);
        split_store_h(o[nf][2] * inv1, o[nf][3] * inv1, g_yh, g_yl, rb1 + d);
    }
}

// ---------------------------------------------------------------------------
extern "C" void kernel_launch(void* const* d_in, const int* in_sizes, int n_in,
                              void* d_out, int out_size) {
    const float *x = nullptr, *Wa = nullptr, *ba = nullptr, *Wp = nullptr, *bp = nullptr;
    for (int i = 0; i < n_in; i++) {
        switch (in_sizes[i]) {
            case 6291456: x  = (const float*)d_in[i]; break;   // [2,4096,768]
            case 1769472: Wa = (const float*)d_in[i]; break;   // [768,2304]
            case 2304:    ba = (const float*)d_in[i]; break;
            case 589824:  Wp = (const float*)d_in[i]; break;   // [768,768]
            case 768:     bp = (const float*)d_in[i]; break;
        }
    }

    cudaFuncSetAttribute(qkv_mma,   cudaFuncAttributeMaxDynamicSharedMemorySize, GSMEM);
    cudaFuncSetAttribute(proj_mma,  cudaFuncAttributeMaxDynamicSharedMemorySize, GSMEM);
    cudaFuncSetAttribute(flash_mma, cudaFuncAttributeMaxDynamicSharedMemorySize, FSMEM);

    __half *xh, *xl, *wat, *wpt;
    cudaGetSymbolAddress((void**)&xh,  g_xh);
    cudaGetSymbolAddress((void**)&xl,  g_xl);
    cudaGetSymbolAddress((void**)&wat, g_WaT);
    cudaGetSymbolAddress((void**)&wpt, g_WpT);

    split_f16<<<(MTOT*CDIM/2 + 255)/256, 256>>>(x, xh, xl, MTOT*CDIM/2);
    wconv_T<<<dim3(N3DIM/32, CDIM/32), dim3(32, 8)>>>(Wa, wat, CDIM, N3DIM);
    wconv_T<<<dim3(CDIM/32,  CDIM/32), dim3(32, 8)>>>(Wp, wpt, CDIM, CDIM);
    qkv_mma<<<dim3(N3DIM/128, MTOT/128), 512, GSMEM>>>(ba);        // (18,64)
    flash_mma<<<dim3(TDIM/128, BDIM*HDIM), 256, FSMEM>>>();        // (32,24)
    proj_mma<<<dim3(CDIM/128, MTOT/128), 512, GSMEM>>>(bp, (float*)d_out); // (6,64)
}

// round 10
// speedup vs baseline: 2.0817x; 1.1730x over previous
#include <cuda_runtime.h>
#include <cuda_bf16.h>
#include <cuda_fp16.h>
#include <cstdint>

// ---------------------------------------------------------------------------
// Problem constants
// ---------------------------------------------------------------------------
#define BDIM 2
#define TDIM 4096
#define CDIM 768
#define HDIM 12
#define DDIM 64
#define N3DIM 2304            // 3*C
#define MTOT  (BDIM*TDIM)     // 8192

// ---------------------------------------------------------------------------
// Device scratch (no allocation in kernel_launch) — pure fp16 pipeline
// ---------------------------------------------------------------------------
__device__ __align__(16) __half g_x [MTOT*CDIM];
__device__ __align__(16) __half g_y [MTOT*CDIM];
__device__ __align__(16) __half g_WaT[N3DIM*CDIM];   // [N,K]
__device__ __align__(16) __half g_WpT[CDIM*CDIM];    // [N,K]
__device__ __align__(16) __half g_q[BDIM*HDIM*TDIM*DDIM];   // x0.125
__device__ __align__(16) __half g_k[BDIM*HDIM*TDIM*DDIM];
__device__ __align__(16) __half g_v[BDIM*HDIM*TDIM*DDIM];

// ---------------------------------------------------------------------------
// Helpers (all sm_80-legal: mma.sync fp16, ldmatrix, cp.async)
// ---------------------------------------------------------------------------
__device__ __forceinline__ uint32_t smem_u32(const void* p) {
    uint32_t a;
    asm("{ .reg .u64 t; cvta.to.shared.u64 t, %1; cvt.u32.u64 %0, t; }"
        : "=r"(a) : "l"(p));
    return a;
}
#define SW128(off) ((off) ^ (((off) >> 3) & 0x70))

__device__ __forceinline__ void cp16(uint32_t dst, const void* src) {
    asm volatile("cp.async.cg.shared.global [%0], [%1], 16;"
                 :: "r"(dst), "l"(src) : "memory");
}
#define CP_COMMIT() asm volatile("cp.async.commit_group;" ::: "memory")
#define CP_WAIT0()  asm volatile("cp.async.wait_group 0;"  ::: "memory")
#define CP_WAIT1()  asm volatile("cp.async.wait_group 1;"  ::: "memory")

__device__ __forceinline__ void ldm_x4(uint32_t a, uint32_t& r0, uint32_t& r1,
                                       uint32_t& r2, uint32_t& r3) {
    asm volatile("ldmatrix.sync.aligned.m8n8.x4.shared.b16 {%0,%1,%2,%3}, [%4];"
                 : "=r"(r0), "=r"(r1), "=r"(r2), "=r"(r3) : "r"(a));
}
__device__ __forceinline__ void ldm_x4t(uint32_t a, uint32_t& r0, uint32_t& r1,
                                        uint32_t& r2, uint32_t& r3) {
    asm volatile("ldmatrix.sync.aligned.m8n8.x4.trans.shared.b16 {%0,%1,%2,%3}, [%4];"
                 : "=r"(r0), "=r"(r1), "=r"(r2), "=r"(r3) : "r"(a));
}
__device__ __forceinline__ void mma_fp16(float (&c)[4], const uint32_t (&a)[4],
                                         uint32_t b0, uint32_t b1) {
    asm volatile("mma.sync.aligned.m16n8k16.row.col.f32.f16.f16.f32 "
                 "{%0,%1,%2,%3}, {%4,%5,%6,%7}, {%8,%9}, {%0,%1,%2,%3};"
                 : "+f"(c[0]), "+f"(c[1]), "+f"(c[2]), "+f"(c[3])
                 : "r"(a[0]), "r"(a[1]), "r"(a[2]), "r"(a[3]), "r"(b0), "r"(b1));
}
// pack two halves into u32 (a -> low, b -> high)
__device__ __forceinline__ uint32_t pkh(__half a, __half b) {
    __half2 t = __halves2half2(a, b);
    return *(uint32_t*)&t;
}
__device__ __forceinline__ float ex2f(float x) {
    float y; asm("ex2.approx.ftz.f32 %0, %1;" : "=f"(y) : "f"(x)); return y;
}

// ---------------------------------------------------------------------------
// Conversion kernels
// ---------------------------------------------------------------------------
__global__ __launch_bounds__(256) void conv_f16(const float* __restrict__ in,
                                                __half* __restrict__ out, int n2) {
    int i = blockIdx.x * blockDim.x + threadIdx.x;
    if (i >= n2) return;
    float2 v = ((const float2*)in)[i];
    ((uint32_t*)out)[i] = pkh(__float2half_rn(v.x), __float2half_rn(v.y));
}

// W [K,N] fp32 -> WT [N,K] fp16 (transpose + convert). block (32,8).
__global__ __launch_bounds__(256) void wconv_T(const float* __restrict__ W,
                                               __half* __restrict__ WT,
                                               int K, int N) {
    __shared__ float tile[32][33];
    const int tx = threadIdx.x, ty = threadIdx.y;
    const int bn = blockIdx.x * 32, bk = blockIdx.y * 32;
    #pragma unroll
    for (int i = 0; i < 4; i++)
        tile[ty + 8*i][tx] = W[(size_t)(bk + ty + 8*i) * N + bn + tx];
    __syncthreads();
    #pragma unroll
    for (int i = 0; i < 4; i++)
        WT[(size_t)(bn + ty + 8*i) * K + bk + tx] = __float2half_rn(tile[tx][ty + 8*i]);
}

// ---------------------------------------------------------------------------
// Single-pass fp16 HMMA GEMM mainloop.
// 512 thr = 16 warps (4m x 4n), warp tile 32x32, CTA 128x128, 3-stage.
// C = A.B^T over K=768.  smem stage (32KB): A@0 B@16K, rows 128B SW128.
// ---------------------------------------------------------------------------
#define GSTAGE 32768
#define GSMEM  (3*GSTAGE)

__device__ __forceinline__ void gemm_issue(const __half* A, const __half* B,
                                           int am0, int bn0, int k0,
                                           uint32_t stbase, int tid) {
    #pragma unroll
    for (int arr = 0; arr < 2; arr++) {
        const __half* base = arr == 0 ? A : B;
        const int r0 = arr == 0 ? am0 : bn0;
        #pragma unroll
        for (int i = 0; i < 2; i++) {
            int s2 = tid + (i << 9);          // 0..1023
            int row = s2 >> 3, c16 = s2 & 7;
            cp16(stbase + (arr << 14) + SW128((uint32_t)(row*128 + (c16 << 4))),
                 base + (size_t)(r0 + row) * 768 + k0 + (c16 << 3));
        }
    }
    CP_COMMIT();
}

__device__ __forceinline__ void gemm_main(const __half* A, const __half* B,
                                          int am0, int bn0,
                                          float (&acc)[2][4][4], char* sm) {
    const int tid = threadIdx.x;
    const int wid = tid >> 5, lane = tid & 31;
    const uint32_t sb = smem_u32(sm);
    const int wm0 = (wid & 3) * 32;
    const int wn0 = (wid >> 2) * 32;
    const int r = lane & 7, g = lane >> 3;

    gemm_issue(A, B, am0, bn0, 0,  sb,          tid);
    gemm_issue(A, B, am0, bn0, 64, sb + GSTAGE, tid);

    for (int c = 0; c < 12; c++) {
        if (c < 11) CP_WAIT1(); else CP_WAIT0();
        __syncthreads();
        if (c < 10)
            gemm_issue(A, B, am0, bn0, (c+2)*64,
                       sb + (uint32_t)(((c+2)%3) * GSTAGE), tid);
        const uint32_t st = sb + (uint32_t)((c % 3) * GSTAGE);
        #pragma unroll
        for (int kf = 0; kf < 4; kf++) {
            const int k0 = kf * 16;
            uint32_t af[2][4];
            #pragma unroll
            for (int mf = 0; mf < 2; mf++) {
                uint32_t off = SW128((uint32_t)(
                    (wm0 + mf*16 + ((g & 1) ? 8 : 0) + r) * 128 +
                    (k0 + ((g & 2) ? 8 : 0)) * 2));
                ldm_x4(st + off, af[mf][0], af[mf][1], af[mf][2], af[mf][3]);
            }
            uint32_t bf[4][2];
            #pragma unroll
            for (int nb = 0; nb < 2; nb++) {
                uint32_t off = SW128((uint32_t)(
                    (wn0 + nb*16 + ((g & 2) ? 8 : 0) + r) * 128 +
                    (k0 + ((g & 1) ? 8 : 0)) * 2));
                uint32_t t0, t1, t2, t3;
                ldm_x4(st + 16384 + off, t0, t1, t2, t3);
                bf[2*nb][0] = t0; bf[2*nb][1] = t1;
                bf[2*nb+1][0] = t2; bf[2*nb+1][1] = t3;
            }
            #pragma unroll
            for (int mf = 0; mf < 2; mf++)
                #pragma unroll
                for (int nf = 0; nf < 4; nf++)
                    mma_fp16(acc[mf][nf], af[mf], bf[nf][0], bf[nf][1]);
        }
    }
}

// ---------------------------------------------------------------------------
// QKV GEMM: x @ W_attn + b.  q (x0.125), k, v -> fp16 [b*h][t][d].
// grid (18, 64), 512 threads
// ---------------------------------------------------------------------------
__global__ __launch_bounds__(512) void qkv_mma(const float* __restrict__ bias) {
    extern __shared__ char sm[];
    const int bm = blockIdx.y * 128;
    const int bn = blockIdx.x * 128;
    float acc[2][4][4] = {};
    gemm_main(g_x, g_WaT, bm, bn, acc, sm);

    const int wid = threadIdx.x >> 5, lane = threadIdx.x & 31;
    const int which = bn / CDIM;              // 0=q 1=k 2=v (tiles never straddle)
    const int batch = bm >> 12;
    const float sc = (which == 0) ? 0.125f : 1.0f;
    __half* dst = which == 0 ? g_q : which == 1 ? g_k : g_v;

    #pragma unroll
    for (int nf = 0; nf < 4; nf++) {
        const int gcol = bn + (wid >> 2) * 32 + nf * 8 + (lane & 3) * 2;
        const float b0 = __ldg(bias + gcol), b1 = __ldg(bias + gcol + 1);
        const int within = gcol % CDIM;
        const int head = within >> 6, d = within & 63;
        #pragma unroll
        for (int mf = 0; mf < 2; mf++) {
            const int t = (bm & (TDIM - 1)) + (wid & 3) * 32 + mf * 16 + (lane >> 2);
            size_t o0 = ((size_t)(batch*HDIM + head)*TDIM + t)     * DDIM + d;
            size_t o1 = ((size_t)(batch*HDIM + head)*TDIM + t + 8) * DDIM + d;
            *(uint32_t*)(dst + o0) = pkh(__float2half_rn((acc[mf][nf][0]+b0)*sc),
                                         __float2half_rn((acc[mf][nf][1]+b1)*sc));
            *(uint32_t*)(dst + o1) = pkh(__float2half_rn((acc[mf][nf][2]+b0)*sc),
                                         __float2half_rn((acc[mf][nf][3]+b1)*sc));
        }
    }
}

// ---------------------------------------------------------------------------
// Projection GEMM: y @ W_proj + b -> d_out fp32.  grid (6, 64), 512 threads
// ---------------------------------------------------------------------------
__global__ __launch_bounds__(512) void proj_mma(const float* __restrict__ bias,
                                                float* __restrict__ out) {
    extern __shared__ char sm[];
    const int bm = blockIdx.y * 128;
    const int bn = blockIdx.x * 128;
    float acc[2][4][4] = {};
    gemm_main(g_y, g_WpT, bm, bn, acc, sm);

    const int wid = threadIdx.x >> 5, lane = threadIdx.x & 31;
    #pragma unroll
    for (int nf = 0; nf < 4; nf++) {
        const int gcol = bn + (wid >> 2) * 32 + nf * 8 + (lane & 3) * 2;
        const float b0 = __ldg(bias + gcol), b1 = __ldg(bias + gcol + 1);
        #pragma unroll
        for (int mf = 0; mf < 2; mf++) {
            const int m = bm + (wid & 3) * 32 + mf * 16 + (lane >> 2);
            *(float2*)(out + (size_t)m * CDIM + gcol) =
                make_float2(acc[mf][nf][0] + b0, acc[mf][nf][1] + b1);
            *(float2*)(out + (size_t)(m + 8) * CDIM + gcol) =
                make_float2(acc[mf][nf][2] + b0, acc[mf][nf][3] + b1);
        }
    }
}

// ---------------------------------------------------------------------------
// Flash attention, pure fp16 single-pass HMMA (proven R9 form).
// grid (32 q-tiles, 24 bh), 256 thr, 1 CTA/SM.  Q fp16 in registers;
// K,V fp16 in smem (stage 16KB: K@0 V@8K), 3-stage cp.async.
// ---------------------------------------------------------------------------
#define FSMEM (3*16384)

__global__ __launch_bounds__(256) void flash_mma() {
    extern __shared__ char sm[];
    const uint32_t sb = smem_u32(sm);
    const int tid = threadIdx.x, wid = tid >> 5, lane = tid & 31;
    const int qt = (int)gridDim.x - 1 - (int)blockIdx.x;   // heavy tiles first
    const int bh = blockIdx.y;
    const int qbase = qt * 128;
    const int ntiles = (qbase + 128) / 64;                  // 2qt+2 (>= 2)

    const __half* qp = g_q + (size_t)bh * TDIM * DDIM;
    const __half* kp = g_k + (size_t)bh * TDIM * DDIM;
    const __half* vp = g_v + (size_t)bh * TDIM * DDIM;

    // Q fragments, register resident
    uint32_t qf[4][4];
    {
        const int row = qbase + wid * 16 + (lane >> 2);
        const int colb = (lane & 3) * 2;
        #pragma unroll
        for (int kf = 0; kf < 4; kf++)
            #pragma unroll
            for (int a = 0; a < 4; a++) {
                int rr = row + ((a & 1) ? 8 : 0);
                int cc = kf * 16 + colb + ((a & 2) ? 8 : 0);
                qf[kf][a] = *(const uint32_t*)(qp + (size_t)rr * DDIM + cc);
            }
    }

    float m0 = -1e30f, m1 = -1e30f, l0 = 0.f, l1 = 0.f;
    float o[8][4] = {};
    const int qhi_row = qbase + wid * 16 + 15;
    const int r = lane & 7, g = lane >> 3;
    const float LOG2E = 1.4426950408889634f;

    // K/V tile loader (cp.async, 4 x 16B per thread; stage = 16KB)
    auto issue = [&](int jt) {
        const int kb = jt * 64;
        const uint32_t stg = sb + (uint32_t)((jt % 3) << 14);
        #pragma unroll
        for (int arr = 0; arr < 2; arr++) {
            const __half* base = arr == 0 ? kp : vp;
            #pragma unroll
            for (int i = 0; i < 2; i++) {
                int s2 = tid + (i << 8);            // 0..511
                int row = s2 >> 3, c16 = s2 & 7;
                cp16(stg + (arr << 13) + SW128((uint32_t)(row*128 + (c16 << 4))),
                     base + (size_t)(kb + row) * DDIM + (c16 << 3));
            }
        }
        CP_COMMIT();
    };
    issue(0);
    issue(1);

    for (int jt = 0; jt < ntiles; jt++) {
        if (jt + 1 < ntiles) CP_WAIT1(); else CP_WAIT0();
        __syncthreads();
        if (jt + 2 < ntiles) issue(jt + 2);
        const int kb = jt * 64;
        if (kb <= qhi_row) {                        // causal per-warp skip
            const uint32_t st = sb + (uint32_t)((jt % 3) << 14);

            // ---- S = Q.K (single pass) ----
            float s[8][4] = {};
            #pragma unroll
            for (int kf = 0; kf < 4; kf++) {
                const int k0 = kf * 16;
                #pragma unroll
                for (int nb = 0; nb < 4; nb++) {
                    uint32_t off = SW128((uint32_t)(
                        (nb*16 + ((g & 2) ? 8 : 0) + r) * 128 +
                        (k0 + ((g & 1) ? 8 : 0)) * 2));
                    uint32_t h0, h1, h2, h3;
                    ldm_x4(st + off, h0, h1, h2, h3);          // K
                    mma_fp16(s[2*nb],   qf[kf], h0, h1);
                    mma_fp16(s[2*nb+1], qf[kf], h2, h3);
                }
            }

            // ---- causal mask (diagonal tiles only) ----
            const int row0 = qbase + wid * 16 + (lane >> 2);
            if (kb + 63 > row0) {
                #pragma unroll
                for (int nf = 0; nf < 8; nf++) {
                    int col = kb + nf * 8 + (lane & 3) * 2;
                    if (col     > row0)     s[nf][0] = -1e30f;
                    if (col + 1 > row0)     s[nf][1] = -1e30f;
                    if (col     > row0 + 8) s[nf][2] = -1e30f;
                    if (col + 1 > row0 + 8) s[nf][3] = -1e30f;
                }
            }

            // ---- online softmax ----
            float rmax0 = -1e30f, rmax1 = -1e30f;
            #pragma unroll
            for (int nf = 0; nf < 8; nf++) {
                rmax0 = fmaxf(rmax0, fmaxf(s[nf][0], s[nf][1]));
                rmax1 = fmaxf(rmax1, fmaxf(s[nf][2], s[nf][3]));
            }
            rmax0 = fmaxf(rmax0, __shfl_xor_sync(0xffffffffu, rmax0, 1));
            rmax0 = fmaxf(rmax0, __shfl_xor_sync(0xffffffffu, rmax0, 2));
            rmax1 = fmaxf(rmax1, __shfl_xor_sync(0xffffffffu, rmax1, 1));
            rmax1 = fmaxf(rmax1, __shfl_xor_sync(0xffffffffu, rmax1, 2));
            const float mn0 = fmaxf(m0, rmax0), mn1 = fmaxf(m1, rmax1);
            const float a0 = ex2f((m0 - mn0) * LOG2E);
            const float a1 = ex2f((m1 - mn1) * LOG2E);
            m0 = mn0; m1 = mn1;
            const float ml0 = mn0 * LOG2E, ml1 = mn1 * LOG2E;
            float rs0 = 0.f, rs1 = 0.f;
            #pragma unroll
            for (int nf = 0; nf < 8; nf++) {
                s[nf][0] = ex2f(fmaf(s[nf][0], LOG2E, -ml0));
                s[nf][1] = ex2f(fmaf(s[nf][1], LOG2E, -ml0));
                s[nf][2] = ex2f(fmaf(s[nf][2], LOG2E, -ml1));
                s[nf][3] = ex2f(fmaf(s[nf][3], LOG2E, -ml1));
                rs0 += s[nf][0] + s[nf][1];
                rs1 += s[nf][2] + s[nf][3];
            }
            rs0 += __shfl_xor_sync(0xffffffffu, rs0, 1);
            rs0 += __shfl_xor_sync(0xffffffffu, rs0, 2);
            rs1 += __shfl_xor_sync(0xffffffffu, rs1, 1);
            rs1 += __shfl_xor_sync(0xffffffffu, rs1, 2);
            l0 = l0 * a0 + rs0;
            l1 = l1 * a1 + rs1;
            #pragma unroll
            for (int nf = 0; nf < 8; nf++) {
                o[nf][0] *= a0; o[nf][1] *= a0;
                o[nf][2] *= a1; o[nf][3] *= a1;
            }

            // ---- P -> fp16 A-fragments (registers only) ----
            uint32_t pf[4][4];
            #pragma unroll
            for (int j = 0; j < 4; j++) {
                #pragma unroll
                for (int half = 0; half < 2; half++) {
                    pf[j][2*half]     = pkh(__float2half_rn(s[2*j + half][0]),
                                            __float2half_rn(s[2*j + half][1]));
                    pf[j][2*half + 1] = pkh(__float2half_rn(s[2*j + half][2]),
                                            __float2half_rn(s[2*j + half][3]));
                }
            }

            // ---- O += P.V (single pass), V^T via ldmatrix.trans ----
            #pragma unroll
            for (int j = 0; j < 4; j++) {
                #pragma unroll
                for (int nb = 0; nb < 4; nb++) {
                    uint32_t off = SW128((uint32_t)(
                        (j*16 + ((g & 1) ? 8 : 0) + r) * 128 +
                        (nb*16 + ((g & 2) ? 8 : 0)) * 2));
                    uint32_t h0, h1, h2, h3;
                    ldm_x4t(st + 8192 + off, h0, h1, h2, h3);   // V
                    mma_fp16(o[2*nb],   pf[j], h0, h1);
                    mma_fp16(o[2*nb+1], pf[j], h2, h3);
                }
            }
        }
    }

    // ---- epilogue: o / l -> fp16 into g_y ----
    const float inv0 = 1.0f / l0, inv1 = 1.0f / l1;
    const int batch = bh / HDIM, hh = bh % HDIM;
    const int row = qbase + wid * 16 + (lane >> 2);
    const size_t rb0 = ((size_t)(batch * TDIM + row))     * CDIM + hh * DDIM;
    const size_t rb1 = ((size_t)(batch * TDIM + row + 8)) * CDIM + hh * DDIM;
    #pragma unroll
    for (int nf = 0; nf < 8; nf++) {
        const int d = nf * 8 + (lane & 3) * 2;
        *(uint32_t*)(g_y + rb0 + d) = pkh(__float2half_rn(o[nf][0] * inv0),
                                          __float2half_rn(o[nf][1] * inv0));
        *(uint32_t*)(g_y + rb1 + d) = pkh(__float2half_rn(o[nf][2] * inv1),
                                          __float2half_rn(o[nf][3] * inv1));
    }
}

// ---------------------------------------------------------------------------
extern "C" void kernel_launch(void* const* d_in, const int* in_sizes, int n_in,
                              void* d_out, int out_size) {
    const float *x = nullptr, *Wa = nullptr, *ba = nullptr, *Wp = nullptr, *bp = nullptr;
    for (int i = 0; i < n_in; i++) {
        switch (in_sizes[i]) {
            case 6291456: x  = (const float*)d_in[i]; break;   // [2,4096,768]
            case 1769472: Wa = (const float*)d_in[i]; break;   // [768,2304]
            case 2304:    ba = (const float*)d_in[i]; break;
            case 589824:  Wp = (const float*)d_in[i]; break;   // [768,768]
            case 768:     bp = (const float*)d_in[i]; break;
        }
    }

    cudaFuncSetAttribute(qkv_mma,   cudaFuncAttributeMaxDynamicSharedMemorySize, GSMEM);
    cudaFuncSetAttribute(proj_mma,  cudaFuncAttributeMaxDynamicSharedMemorySize, GSMEM);
    cudaFuncSetAttribute(flash_mma, cudaFuncAttributeMaxDynamicSharedMemorySize, FSMEM);

    __half *xd, *wat, *wpt;
    cudaGetSymbolAddress((void**)&xd,  g_x);
    cudaGetSymbolAddress((void**)&wat, g_WaT);
    cudaGetSymbolAddress((void**)&wpt, g_WpT);

    conv_f16<<<(MTOT*CDIM/2 + 255)/256, 256>>>(x, xd, MTOT*CDIM/2);
    wconv_T<<<dim3(N3DIM/32, CDIM/32), dim3(32, 8)>>>(Wa, wat, CDIM, N3DIM);
    wconv_T<<<dim3(CDIM/32,  CDIM/32), dim3(32, 8)>>>(Wp, wpt, CDIM, CDIM);
    qkv_mma<<<dim3(N3DIM/128, MTOT/128), 512, GSMEM>>>(ba);        // (18,64)
    flash_mma<<<dim3(TDIM/128, BDIM*HDIM), 256, FSMEM>>>();        // (32,24)
    proj_mma<<<dim3(CDIM/128, MTOT/128), 512, GSMEM>>>(bp, (float*)d_out); // (6,64)
}

// round 11
// speedup vs baseline: 2.3533x; 1.1304x over previous
#include <cuda_runtime.h>
#include <cuda_bf16.h>
#include <cuda_fp16.h>
#include <cstdint>

// ---------------------------------------------------------------------------
// Problem constants
// ---------------------------------------------------------------------------
#define BDIM 2
#define TDIM 4096
#define CDIM 768
#define HDIM 12
#define DDIM 64
#define N3DIM 2304            // 3*C
#define MTOT  (BDIM*TDIM)     // 8192

// ---------------------------------------------------------------------------
// Device scratch (no allocation in kernel_launch) — pure fp16 pipeline
// ---------------------------------------------------------------------------
__device__ __align__(16) __half g_x [MTOT*CDIM];
__device__ __align__(16) __half g_y [MTOT*CDIM];
__device__ __align__(16) __half g_WaT[N3DIM*CDIM];   // [N,K]
__device__ __align__(16) __half g_WpT[CDIM*CDIM];    // [N,K]
__device__ __align__(16) __half g_q[BDIM*HDIM*TDIM*DDIM];   // x0.125
__device__ __align__(16) __half g_k[BDIM*HDIM*TDIM*DDIM];
__device__ __align__(16) __half g_v[BDIM*HDIM*TDIM*DDIM];

// ---------------------------------------------------------------------------
// Helpers (all sm_80-legal: mma.sync fp16, ldmatrix, cp.async)
// ---------------------------------------------------------------------------
__device__ __forceinline__ uint32_t smem_u32(const void* p) {
    uint32_t a;
    asm("{ .reg .u64 t; cvta.to.shared.u64 t, %1; cvt.u32.u64 %0, t; }"
        : "=r"(a) : "l"(p));
    return a;
}
#define SW128(off) ((off) ^ (((off) >> 3) & 0x70))

__device__ __forceinline__ void cp16(uint32_t dst, const void* src) {
    asm volatile("cp.async.cg.shared.global [%0], [%1], 16;"
                 :: "r"(dst), "l"(src) : "memory");
}
#define CP_COMMIT() asm volatile("cp.async.commit_group;" ::: "memory")
#define CP_WAIT0()  asm volatile("cp.async.wait_group 0;"  ::: "memory")
#define CP_WAIT1()  asm volatile("cp.async.wait_group 1;"  ::: "memory")

__device__ __forceinline__ void ldm_x4(uint32_t a, uint32_t& r0, uint32_t& r1,
                                       uint32_t& r2, uint32_t& r3) {
    asm volatile("ldmatrix.sync.aligned.m8n8.x4.shared.b16 {%0,%1,%2,%3}, [%4];"
                 : "=r"(r0), "=r"(r1), "=r"(r2), "=r"(r3) : "r"(a));
}
__device__ __forceinline__ void ldm_x4t(uint32_t a, uint32_t& r0, uint32_t& r1,
                                        uint32_t& r2, uint32_t& r3) {
    asm volatile("ldmatrix.sync.aligned.m8n8.x4.trans.shared.b16 {%0,%1,%2,%3}, [%4];"
                 : "=r"(r0), "=r"(r1), "=r"(r2), "=r"(r3) : "r"(a));
}
__device__ __forceinline__ void mma_fp16(float (&c)[4], const uint32_t (&a)[4],
                                         uint32_t b0, uint32_t b1) {
    asm volatile("mma.sync.aligned.m16n8k16.row.col.f32.f16.f16.f32 "
                 "{%0,%1,%2,%3}, {%4,%5,%6,%7}, {%8,%9}, {%0,%1,%2,%3};"
                 : "+f"(c[0]), "+f"(c[1]), "+f"(c[2]), "+f"(c[3])
                 : "r"(a[0]), "r"(a[1]), "r"(a[2]), "r"(a[3]), "r"(b0), "r"(b1));
}
// pack two halves into u32 (a -> low, b -> high)
__device__ __forceinline__ uint32_t pkh(__half a, __half b) {
    __half2 t = __halves2half2(a, b);
    return *(uint32_t*)&t;
}
__device__ __forceinline__ float ex2f(float x) {
    float y; asm("ex2.approx.ftz.f32 %0, %1;" : "=f"(y) : "f"(x)); return y;
}

// ---------------------------------------------------------------------------
// Conversion kernels
// ---------------------------------------------------------------------------
__global__ __launch_bounds__(256) void conv_f16(const float* __restrict__ in,
                                                __half* __restrict__ out, int n2) {
    int i = blockIdx.x * blockDim.x + threadIdx.x;
    if (i >= n2) return;
    float2 v = ((const float2*)in)[i];
    ((uint32_t*)out)[i] = pkh(__float2half_rn(v.x), __float2half_rn(v.y));
}

// W [K,N] fp32 -> WT [N,K] fp16 (transpose + convert). block (32,8).
__global__ __launch_bounds__(256) void wconv_T(const float* __restrict__ W,
                                               __half* __restrict__ WT,
                                               int K, int N) {
    __shared__ float tile[32][33];
    const int tx = threadIdx.x, ty = threadIdx.y;
    const int bn = blockIdx.x * 32, bk = blockIdx.y * 32;
    #pragma unroll
    for (int i = 0; i < 4; i++)
        tile[ty + 8*i][tx] = W[(size_t)(bk + ty + 8*i) * N + bn + tx];
    __syncthreads();
    #pragma unroll
    for (int i = 0; i < 4; i++)
        WT[(size_t)(bn + ty + 8*i) * K + bk + tx] = __float2half_rn(tile[tx][ty + 8*i]);
}

// ---------------------------------------------------------------------------
// Single-pass fp16 HMMA GEMM mainloop, templated warp-M (MF*16).
// 512 thr = 16 warps (4m x 4n), warp tile (MF*16)x32, CTA (MF*64)x128,
// K-chunk 64, 3-stage.  smem stage: A (MF*8KB) @0, B (16KB) @MF*8KB.
// ---------------------------------------------------------------------------
template<int MF>
__device__ __forceinline__ void gemm_issue(const __half* A, const __half* B,
                                           int am0, int bn0, int k0,
                                           uint32_t stbase, int tid) {
    #pragma unroll
    for (int i = 0; i < MF; i++) {                 // A: MF*64 rows
        int s2 = tid + (i << 9);
        int row = s2 >> 3, c16 = s2 & 7;
        cp16(stbase + SW128((uint32_t)(row*128 + (c16 << 4))),
             A + (size_t)(am0 + row) * 768 + k0 + (c16 << 3));
    }
    #pragma unroll
    for (int i = 0; i < 2; i++) {                  // B: 128 rows
        int s2 = tid + (i << 9);
        int row = s2 >> 3, c16 = s2 & 7;
        cp16(stbase + (uint32_t)(MF*8192) + SW128((uint32_t)(row*128 + (c16 << 4))),
             B + (size_t)(bn0 + row) * 768 + k0 + (c16 << 3));
    }
    CP_COMMIT();
}

template<int MF>
__device__ __forceinline__ void gemm_main(const __half* A, const __half* B,
                                          int am0, int bn0,
                                          float (&acc)[MF][4][4], char* sm) {
    const int GST = MF*8192 + 16384;
    const int tid = threadIdx.x;
    const int wid = tid >> 5, lane = tid & 31;
    const uint32_t sb = smem_u32(sm);
    const int wm0 = (wid & 3) * (MF*16);
    const int wn0 = (wid >> 2) * 32;
    const int r = lane & 7, g = lane >> 3;

    gemm_issue<MF>(A, B, am0, bn0, 0,  sb,       tid);
    gemm_issue<MF>(A, B, am0, bn0, 64, sb + GST, tid);

    for (int c = 0; c < 12; c++) {
        if (c < 11) CP_WAIT1(); else CP_WAIT0();
        __syncthreads();
        if (c < 10)
            gemm_issue<MF>(A, B, am0, bn0, (c+2)*64,
                           sb + (uint32_t)(((c+2)%3) * GST), tid);
        const uint32_t st = sb + (uint32_t)((c % 3) * GST);
        #pragma unroll
        for (int kf = 0; kf < 4; kf++) {
            const int k0 = kf * 16;
            uint32_t af[MF][4];
            #pragma unroll
            for (int mf = 0; mf < MF; mf++) {
                uint32_t off = SW128((uint32_t)(
                    (wm0 + mf*16 + ((g & 1) ? 8 : 0) + r) * 128 +
                    (k0 + ((g & 2) ? 8 : 0)) * 2));
                ldm_x4(st + off, af[mf][0], af[mf][1], af[mf][2], af[mf][3]);
            }
            uint32_t bf[4][2];
            #pragma unroll
            for (int nb = 0; nb < 2; nb++) {
                uint32_t off = SW128((uint32_t)(
                    (wn0 + nb*16 + ((g & 2) ? 8 : 0) + r) * 128 +
                    (k0 + ((g & 1) ? 8 : 0)) * 2));
                uint32_t t0, t1, t2, t3;
                ldm_x4(st + (uint32_t)(MF*8192) + off, t0, t1, t2, t3);
                bf[2*nb][0] = t0; bf[2*nb][1] = t1;
                bf[2*nb+1][0] = t2; bf[2*nb+1][1] = t3;
            }
            #pragma unroll
            for (int mf = 0; mf < MF; mf++)
                #pragma unroll
                for (int nf = 0; nf < 4; nf++)
                    mma_fp16(acc[mf][nf], af[mf], bf[nf][0], bf[nf][1]);
        }
    }
}

#define GSMEM4 (3*(4*8192 + 16384))   // qkv: 147456
#define GSMEM2 (3*(2*8192 + 16384))   // proj: 98304

// ---------------------------------------------------------------------------
// QKV GEMM: x @ W_attn + b.  q (x0.125), k, v -> fp16 [b*h][t][d].
// CTA 256x128, grid (18, 32), 512 threads
// ---------------------------------------------------------------------------
__global__ __launch_bounds__(512) void qkv_mma(const float* __restrict__ bias) {
    extern __shared__ char sm[];
    const int bm = blockIdx.y * 256;
    const int bn = blockIdx.x * 128;
    float acc[4][4][4] = {};
    gemm_main<4>(g_x, g_WaT, bm, bn, acc, sm);

    const int wid = threadIdx.x >> 5, lane = threadIdx.x & 31;
    const int which = bn / CDIM;              // 0=q 1=k 2=v (tiles never straddle)
    const int batch = bm >> 12;               // 256-row tile never straddles batch
    const float sc = (which == 0) ? 0.125f : 1.0f;
    __half* dst = which == 0 ? g_q : which == 1 ? g_k : g_v;

    #pragma unroll
    for (int nf = 0; nf < 4; nf++) {
        const int gcol = bn + (wid >> 2) * 32 + nf * 8 + (lane & 3) * 2;
        const float b0 = __ldg(bias + gcol), b1 = __ldg(bias + gcol + 1);
        const int within = gcol % CDIM;
        const int head = within >> 6, d = within & 63;
        #pragma unroll
        for (int mf = 0; mf < 4; mf++) {
            const int t = (bm & (TDIM - 1)) + (wid & 3) * 64 + mf * 16 + (lane >> 2);
            size_t o0 = ((size_t)(batch*HDIM + head)*TDIM + t)     * DDIM + d;
            size_t o1 = ((size_t)(batch*HDIM + head)*TDIM + t + 8) * DDIM + d;
            *(uint32_t*)(dst + o0) = pkh(__float2half_rn((acc[mf][nf][0]+b0)*sc),
                                         __float2half_rn((acc[mf][nf][1]+b1)*sc));
            *(uint32_t*)(dst + o1) = pkh(__float2half_rn((acc[mf][nf][2]+b0)*sc),
                                         __float2half_rn((acc[mf][nf][3]+b1)*sc));
        }
    }
}

// ---------------------------------------------------------------------------
// Projection GEMM: y @ W_proj + b -> d_out fp32.  CTA 128x128, grid (6, 64)
// ---------------------------------------------------------------------------
__global__ __launch_bounds__(512) void proj_mma(const float* __restrict__ bias,
                                                float* __restrict__ out) {
    extern __shared__ char sm[];
    const int bm = blockIdx.y * 128;
    const int bn = blockIdx.x * 128;
    float acc[2][4][4] = {};
    gemm_main<2>(g_y, g_WpT, bm, bn, acc, sm);

    const int wid = threadIdx.x >> 5, lane = threadIdx.x & 31;
    #pragma unroll
    for (int nf = 0; nf < 4; nf++) {
        const int gcol = bn + (wid >> 2) * 32 + nf * 8 + (lane & 3) * 2;
        const float b0 = __ldg(bias + gcol), b1 = __ldg(bias + gcol + 1);
        #pragma unroll
        for (int mf = 0; mf < 2; mf++) {
            const int m = bm + (wid & 3) * 32 + mf * 16 + (lane >> 2);
            *(float2*)(out + (size_t)m * CDIM + gcol) =
                make_float2(acc[mf][nf][0] + b0, acc[mf][nf][1] + b1);
            *(float2*)(out + (size_t)(m + 8) * CDIM + gcol) =
                make_float2(acc[mf][nf][2] + b0, acc[mf][nf][3] + b1);
        }
    }
}

// ---------------------------------------------------------------------------
// Flash attention, pure fp16 single-pass HMMA, 128-wide K/V tiles.
// grid (32 q-tiles, 24 bh), 256 thr, 1 CTA/SM.  Q fp16 in registers;
// K,V fp16 in smem (stage 32KB: K@0 (128 rows) V@16K), 3-stage cp.async.
// 128-wide tiles halve per-column softmax fixed costs (rescale/shuffle/sync).
// ---------------------------------------------------------------------------
#define FSMEM (3*32768)

__global__ __launch_bounds__(256) void flash_mma() {
    extern __shared__ char sm[];
    const uint32_t sb = smem_u32(sm);
    const int tid = threadIdx.x, wid = tid >> 5, lane = tid & 31;
    const int qt = (int)gridDim.x - 1 - (int)blockIdx.x;   // heavy tiles first
    const int bh = blockIdx.y;
    const int qbase = qt * 128;
    const int ntiles = qt + 1;                              // 128-wide K tiles

    const __half* qp = g_q + (size_t)bh * TDIM * DDIM;
    const __half* kp = g_k + (size_t)bh * TDIM * DDIM;
    const __half* vp = g_v + (size_t)bh * TDIM * DDIM;

    // Q fragments, register resident
    uint32_t qf[4][4];
    {
        const int row = qbase + wid * 16 + (lane >> 2);
        const int colb = (lane & 3) * 2;
        #pragma unroll
        for (int kf = 0; kf < 4; kf++)
            #pragma unroll
            for (int a = 0; a < 4; a++) {
                int rr = row + ((a & 1) ? 8 : 0);
                int cc = kf * 16 + colb + ((a & 2) ? 8 : 0);
                qf[kf][a] = *(const uint32_t*)(qp + (size_t)rr * DDIM + cc);
            }
    }

    float m0 = -1e30f, m1 = -1e30f, l0 = 0.f, l1 = 0.f;
    float o[8][4] = {};
    const int r = lane & 7, g = lane >> 3;
    const float LOG2E = 1.4426950408889634f;

    // K/V tile loader (cp.async, 8 x 16B per thread; stage = 32KB)
    auto issue = [&](int jt) {
        const int kb = jt * 128;
        const uint32_t stg = sb + (uint32_t)((jt % 3) << 15);
        #pragma unroll
        for (int arr = 0; arr < 2; arr++) {
            const __half* base = arr == 0 ? kp : vp;
            #pragma unroll
            for (int i = 0; i < 4; i++) {
                int s2 = tid + (i << 8);            // 0..1023 (128 rows x 8)
                int row = s2 >> 3, c16 = s2 & 7;
                cp16(stg + (arr << 14) + SW128((uint32_t)(row*128 + (c16 << 4))),
                     base + (size_t)(kb + row) * DDIM + (c16 << 3));
            }
        }
        CP_COMMIT();
    };
    issue(0);
    if (ntiles > 1) issue(1);

    for (int jt = 0; jt < ntiles; jt++) {
        if (jt + 1 < ntiles) CP_WAIT1(); else CP_WAIT0();
        __syncthreads();
        if (jt + 2 < ntiles) issue(jt + 2);
        const int kb = jt * 128;
        const uint32_t st = sb + (uint32_t)((jt % 3) << 15);

        // ---- S = Q.K (single pass, 128 cols) ----
        float s[16][4] = {};
        #pragma unroll
        for (int kf = 0; kf < 4; kf++) {
            const int k0 = kf * 16;
            #pragma unroll
            for (int nb = 0; nb < 8; nb++) {
                uint32_t off = SW128((uint32_t)(
                    (nb*16 + ((g & 2) ? 8 : 0) + r) * 128 +
                    (k0 + ((g & 1) ? 8 : 0)) * 2));
                uint32_t h0, h1, h2, h3;
                ldm_x4(st + off, h0, h1, h2, h3);          // K
                mma_fp16(s[2*nb],   qf[kf], h0, h1);
                mma_fp16(s[2*nb+1], qf[kf], h2, h3);
            }
        }

        // ---- causal mask (diagonal tile only) ----
        const int row0 = qbase + wid * 16 + (lane >> 2);
        if (kb + 127 > row0) {
            #pragma unroll
            for (int nf = 0; nf < 16; nf++) {
                int col = kb + nf * 8 + (lane & 3) * 2;
                if (col     > row0)     s[nf][0] = -1e30f;
                if (col + 1 > row0)     s[nf][1] = -1e30f;
                if (col     > row0 + 8) s[nf][2] = -1e30f;
                if (col + 1 > row0 + 8) s[nf][3] = -1e30f;
            }
        }

        // ---- online softmax ----
        float rmax0 = -1e30f, rmax1 = -1e30f;
        #pragma unroll
        for (int nf = 0; nf < 16; nf++) {
            rmax0 = fmaxf(rmax0, fmaxf(s[nf][0], s[nf][1]));
            rmax1 = fmaxf(rmax1, fmaxf(s[nf][2], s[nf][3]));
        }
        rmax0 = fmaxf(rmax0, __shfl_xor_sync(0xffffffffu, rmax0, 1));
        rmax0 = fmaxf(rmax0, __shfl_xor_sync(0xffffffffu, rmax0, 2));
        rmax1 = fmaxf(rmax1, __shfl_xor_sync(0xffffffffu, rmax1, 1));
        rmax1 = fmaxf(rmax1, __shfl_xor_sync(0xffffffffu, rmax1, 2));
        const float mn0 = fmaxf(m0, rmax0), mn1 = fmaxf(m1, rmax1);
        const float a0 = ex2f((m0 - mn0) * LOG2E);
        const float a1 = ex2f((m1 - mn1) * LOG2E);
        m0 = mn0; m1 = mn1;
        const float ml0 = mn0 * LOG2E, ml1 = mn1 * LOG2E;
        float rs0 = 0.f, rs1 = 0.f;
        #pragma unroll
        for (int nf = 0; nf < 16; nf++) {
            s[nf][0] = ex2f(fmaf(s[nf][0], LOG2E, -ml0));
            s[nf][1] = ex2f(fmaf(s[nf][1], LOG2E, -ml0));
            s[nf][2] = ex2f(fmaf(s[nf][2], LOG2E, -ml1));
            s[nf][3] = ex2f(fmaf(s[nf][3], LOG2E, -ml1));
            rs0 += s[nf][0] + s[nf][1];
            rs1 += s[nf][2] + s[nf][3];
        }
        rs0 += __shfl_xor_sync(0xffffffffu, rs0, 1);
        rs0 += __shfl_xor_sync(0xffffffffu, rs0, 2);
        rs1 += __shfl_xor_sync(0xffffffffu, rs1, 1);
        rs1 += __shfl_xor_sync(0xffffffffu, rs1, 2);
        l0 = l0 * a0 + rs0;
        l1 = l1 * a1 + rs1;
        #pragma unroll
        for (int nf = 0; nf < 8; nf++) {
            o[nf][0] *= a0; o[nf][1] *= a0;
            o[nf][2] *= a1; o[nf][3] *= a1;
        }

        // ---- P -> fp16 A-fragments (registers only) ----
        uint32_t pf[8][4];
        #pragma unroll
        for (int j = 0; j < 8; j++) {
            #pragma unroll
            for (int half = 0; half < 2; half++) {
                pf[j][2*half]     = pkh(__float2half_rn(s[2*j + half][0]),
                                        __float2half_rn(s[2*j + half][1]));
                pf[j][2*half + 1] = pkh(__float2half_rn(s[2*j + half][2]),
                                        __float2half_rn(s[2*j + half][3]));
            }
        }

        // ---- O += P.V (single pass, K=128), V^T via ldmatrix.trans ----
        #pragma unroll
        for (int j = 0; j < 8; j++) {
            #pragma unroll
            for (int nb = 0; nb < 4; nb++) {
                uint32_t off = SW128((uint32_t)(
                    (j*16 + ((g & 1) ? 8 : 0) + r) * 128 +
                    (nb*16 + ((g & 2) ? 8 : 0)) * 2));
                uint32_t h0, h1, h2, h3;
                ldm_x4t(st + 16384 + off, h0, h1, h2, h3);   // V
                mma_fp16(o[2*nb],   pf[j], h0, h1);
                mma_fp16(o[2*nb+1], pf[j], h2, h3);
            }
        }
    }

    // ---- epilogue: o / l -> fp16 into g_y ----
    const float inv0 = 1.0f / l0, inv1 = 1.0f / l1;
    const int batch = bh / HDIM, hh = bh % HDIM;
    const int row = qbase + wid * 16 + (lane >> 2);
    const size_t rb0 = ((size_t)(batch * TDIM + row))     * CDIM + hh * DDIM;
    const size_t rb1 = ((size_t)(batch * TDIM + row + 8)) * CDIM + hh * DDIM;
    #pragma unroll
    for (int nf = 0; nf < 8; nf++) {
        const int d = nf * 8 + (lane & 3) * 2;
        *(uint32_t*)(g_y + rb0 + d) = pkh(__float2half_rn(o[nf][0] * inv0),
                                          __float2half_rn(o[nf][1] * inv0));
        *(uint32_t*)(g_y + rb1 + d) = pkh(__float2half_rn(o[nf][2] * inv1),
                                          __float2half_rn(o[nf][3] * inv1));
    }
}

// ---------------------------------------------------------------------------
extern "C" void kernel_launch(void* const* d_in, const int* in_sizes, int n_in,
                              void* d_out, int out_size) {
    const float *x = nullptr, *Wa = nullptr, *ba = nullptr, *Wp = nullptr, *bp = nullptr;
    for (int i = 0; i < n_in; i++) {
        switch (in_sizes[i]) {
            case 6291456: x  = (const float*)d_in[i]; break;   // [2,4096,768]
            case 1769472: Wa = (const float*)d_in[i]; break;   // [768,2304]
            case 2304:    ba = (const float*)d_in[i]; break;
            case 589824:  Wp = (const float*)d_in[i]; break;   // [768,768]
            case 768:     bp = (const float*)d_in[i]; break;
        }
    }

    cudaFuncSetAttribute(qkv_mma,   cudaFuncAttributeMaxDynamicSharedMemorySize, GSMEM4);
    cudaFuncSetAttribute(proj_mma,  cudaFuncAttributeMaxDynamicSharedMemorySize, GSMEM2);
    cudaFuncSetAttribute(flash_mma, cudaFuncAttributeMaxDynamicSharedMemorySize, FSMEM);

    __half *xd, *wat, *wpt;
    cudaGetSymbolAddress((void**)&xd,  g_x);
    cudaGetSymbolAddress((void**)&wat, g_WaT);
    cudaGetSymbolAddress((void**)&wpt, g_WpT);

    conv_f16<<<(MTOT*CDIM/2 + 255)/256, 256>>>(x, xd, MTOT*CDIM/2);
    wconv_T<<<dim3(N3DIM/32, CDIM/32), dim3(32, 8)>>>(Wa, wat, CDIM, N3DIM);
    wconv_T<<<dim3(CDIM/32,  CDIM/32), dim3(32, 8)>>>(Wp, wpt, CDIM, CDIM);
    qkv_mma<<<dim3(N3DIM/128, MTOT/256), 512, GSMEM4>>>(ba);       // (18,32)
    flash_mma<<<dim3(TDIM/128, BDIM*HDIM), 256, FSMEM>>>();        // (32,24)
    proj_mma<<<dim3(CDIM/128, MTOT/128), 512, GSMEM2>>>(bp, (float*)d_out); // (6,64)
}

// round 12
// speedup vs baseline: 2.3781x; 1.0105x over previous
#include <cuda_runtime.h>
#include <cuda_bf16.h>
#include <cuda_fp16.h>
#include <cstdint>

// ---------------------------------------------------------------------------
// Problem constants
// ---------------------------------------------------------------------------
#define BDIM 2
#define TDIM 4096
#define CDIM 768
#define HDIM 12
#define DDIM 64
#define N3DIM 2304            // 3*C
#define MTOT  (BDIM*TDIM)     // 8192

// ---------------------------------------------------------------------------
// Device scratch (no allocation in kernel_launch) — pure fp16 pipeline
// ---------------------------------------------------------------------------
__device__ __align__(16) __half g_x [MTOT*CDIM];
__device__ __align__(16) __half g_y [MTOT*CDIM];
__device__ __align__(16) __half g_WaT[N3DIM*CDIM];   // [N,K]
__device__ __align__(16) __half g_WpT[CDIM*CDIM];    // [N,K]
__device__ __align__(16) __half g_q[BDIM*HDIM*TDIM*DDIM];   // x0.125
__device__ __align__(16) __half g_k[BDIM*HDIM*TDIM*DDIM];
__device__ __align__(16) __half g_v[BDIM*HDIM*TDIM*DDIM];

// ---------------------------------------------------------------------------
// Helpers (all sm_80-legal: mma.sync fp16, ldmatrix, cp.async)
// ---------------------------------------------------------------------------
__device__ __forceinline__ uint32_t smem_u32(const void* p) {
    uint32_t a;
    asm("{ .reg .u64 t; cvta.to.shared.u64 t, %1; cvt.u32.u64 %0, t; }"
        : "=r"(a) : "l"(p));
    return a;
}
#define SW128(off) ((off) ^ (((off) >> 3) & 0x70))

__device__ __forceinline__ void cp16(uint32_t dst, const void* src) {
    asm volatile("cp.async.cg.shared.global [%0], [%1], 16;"
                 :: "r"(dst), "l"(src) : "memory");
}
#define CP_COMMIT() asm volatile("cp.async.commit_group;" ::: "memory")
#define CP_WAIT0()  asm volatile("cp.async.wait_group 0;"  ::: "memory")
#define CP_WAIT1()  asm volatile("cp.async.wait_group 1;"  ::: "memory")

__device__ __forceinline__ void ldm_x4(uint32_t a, uint32_t& r0, uint32_t& r1,
                                       uint32_t& r2, uint32_t& r3) {
    asm volatile("ldmatrix.sync.aligned.m8n8.x4.shared.b16 {%0,%1,%2,%3}, [%4];"
                 : "=r"(r0), "=r"(r1), "=r"(r2), "=r"(r3) : "r"(a));
}
__device__ __forceinline__ void ldm_x4t(uint32_t a, uint32_t& r0, uint32_t& r1,
                                        uint32_t& r2, uint32_t& r3) {
    asm volatile("ldmatrix.sync.aligned.m8n8.x4.trans.shared.b16 {%0,%1,%2,%3}, [%4];"
                 : "=r"(r0), "=r"(r1), "=r"(r2), "=r"(r3) : "r"(a));
}
__device__ __forceinline__ void mma_fp16(float (&c)[4], const uint32_t (&a)[4],
                                         uint32_t b0, uint32_t b1) {
    asm volatile("mma.sync.aligned.m16n8k16.row.col.f32.f16.f16.f32 "
                 "{%0,%1,%2,%3}, {%4,%5,%6,%7}, {%8,%9}, {%0,%1,%2,%3};"
                 : "+f"(c[0]), "+f"(c[1]), "+f"(c[2]), "+f"(c[3])
                 : "r"(a[0]), "r"(a[1]), "r"(a[2]), "r"(a[3]), "r"(b0), "r"(b1));
}
// pack two halves into u32 (a -> low, b -> high)
__device__ __forceinline__ uint32_t pkh(__half a, __half b) {
    __half2 t = __halves2half2(a, b);
    return *(uint32_t*)&t;
}
__device__ __forceinline__ float ex2f(float x) {
    float y; asm("ex2.approx.ftz.f32 %0, %1;" : "=f"(y) : "f"(x)); return y;
}

// ---------------------------------------------------------------------------
// Conversion kernels
// ---------------------------------------------------------------------------
__global__ __launch_bounds__(256) void conv_f16(const float* __restrict__ in,
                                                __half* __restrict__ out, int n2) {
    int i = blockIdx.x * blockDim.x + threadIdx.x;
    if (i >= n2) return;
    float2 v = ((const float2*)in)[i];
    ((uint32_t*)out)[i] = pkh(__float2half_rn(v.x), __float2half_rn(v.y));
}

// W [K,N] fp32 -> WT [N,K] fp16 (transpose + convert). block (32,8).
__global__ __launch_bounds__(256) void wconv_T(const float* __restrict__ W,
                                               __half* __restrict__ WT,
                                               int K, int N) {
    __shared__ float tile[32][33];
    const int tx = threadIdx.x, ty = threadIdx.y;
    const int bn = blockIdx.x * 32, bk = blockIdx.y * 32;
    #pragma unroll
    for (int i = 0; i < 4; i++)
        tile[ty + 8*i][tx] = W[(size_t)(bk + ty + 8*i) * N + bn + tx];
    __syncthreads();
    #pragma unroll
    for (int i = 0; i < 4; i++)
        WT[(size_t)(bn + ty + 8*i) * K + bk + tx] = __float2half_rn(tile[tx][ty + 8*i]);
}

// ---------------------------------------------------------------------------
// Single-pass fp16 HMMA GEMM mainloop, templated warp-M (MF*16).
// 512 thr = 16 warps (4m x 4n), warp tile (MF*16)x32, CTA (MF*64)x128,
// K-chunk 64, 3-stage.  smem stage: A (MF*8KB) @0, B (16KB) @MF*8KB.
// ---------------------------------------------------------------------------
template<int MF>
__device__ __forceinline__ void gemm_issue(const __half* A, const __half* B,
                                           int am0, int bn0, int k0,
                                           uint32_t stbase, int tid) {
    #pragma unroll
    for (int i = 0; i < MF; i++) {                 // A: MF*64 rows
        int s2 = tid + (i << 9);
        int row = s2 >> 3, c16 = s2 & 7;
        cp16(stbase + SW128((uint32_t)(row*128 + (c16 << 4))),
             A + (size_t)(am0 + row) * 768 + k0 + (c16 << 3));
    }
    #pragma unroll
    for (int i = 0; i < 2; i++) {                  // B: 128 rows
        int s2 = tid + (i << 9);
        int row = s2 >> 3, c16 = s2 & 7;
        cp16(stbase + (uint32_t)(MF*8192) + SW128((uint32_t)(row*128 + (c16 << 4))),
             B + (size_t)(bn0 + row) * 768 + k0 + (c16 << 3));
    }
    CP_COMMIT();
}

template<int MF>
__device__ __forceinline__ void gemm_main(const __half* A, const __half* B,
                                          int am0, int bn0,
                                          float (&acc)[MF][4][4], char* sm) {
    const int GST = MF*8192 + 16384;
    const int tid = threadIdx.x;
    const int wid = tid >> 5, lane = tid & 31;
    const uint32_t sb = smem_u32(sm);
    const int wm0 = (wid & 3) * (MF*16);
    const int wn0 = (wid >> 2) * 32;
    const int r = lane & 7, g = lane >> 3;

    gemm_issue<MF>(A, B, am0, bn0, 0,  sb,       tid);
    gemm_issue<MF>(A, B, am0, bn0, 64, sb + GST, tid);

    for (int c = 0; c < 12; c++) {
        if (c < 11) CP_WAIT1(); else CP_WAIT0();
        __syncthreads();
        if (c < 10)
            gemm_issue<MF>(A, B, am0, bn0, (c+2)*64,
                           sb + (uint32_t)(((c+2)%3) * GST), tid);
        const uint32_t st = sb + (uint32_t)((c % 3) * GST);
        #pragma unroll
        for (int kf = 0; kf < 4; kf++) {
            const int k0 = kf * 16;
            uint32_t af[MF][4];
            #pragma unroll
            for (int mf = 0; mf < MF; mf++) {
                uint32_t off = SW128((uint32_t)(
                    (wm0 + mf*16 + ((g & 1) ? 8 : 0) + r) * 128 +
                    (k0 + ((g & 2) ? 8 : 0)) * 2));
                ldm_x4(st + off, af[mf][0], af[mf][1], af[mf][2], af[mf][3]);
            }
            uint32_t bf[4][2];
            #pragma unroll
            for (int nb = 0; nb < 2; nb++) {
                uint32_t off = SW128((uint32_t)(
                    (wn0 + nb*16 + ((g & 2) ? 8 : 0) + r) * 128 +
                    (k0 + ((g & 1) ? 8 : 0)) * 2));
                uint32_t t0, t1, t2, t3;
                ldm_x4(st + (uint32_t)(MF*8192) + off, t0, t1, t2, t3);
                bf[2*nb][0] = t0; bf[2*nb][1] = t1;
                bf[2*nb+1][0] = t2; bf[2*nb+1][1] = t3;
            }
            #pragma unroll
            for (int mf = 0; mf < MF; mf++)
                #pragma unroll
                for (int nf = 0; nf < 4; nf++)
                    mma_fp16(acc[mf][nf], af[mf], bf[nf][0], bf[nf][1]);
        }
    }
}

#define GSMEM4 (3*(4*8192 + 16384))   // qkv: 147456
#define GSMEM2 (3*(2*8192 + 16384))   // proj: 98304

// ---------------------------------------------------------------------------
// QKV GEMM: x @ W_attn + b.  q (x0.125), k, v -> fp16 [b*h][t][d].
// CTA 256x128, grid (18, 32), 512 threads
// ---------------------------------------------------------------------------
__global__ __launch_bounds__(512) void qkv_mma(const float* __restrict__ bias) {
    extern __shared__ char sm[];
    const int bm = blockIdx.y * 256;
    const int bn = blockIdx.x * 128;
    float acc[4][4][4] = {};
    gemm_main<4>(g_x, g_WaT, bm, bn, acc, sm);

    const int wid = threadIdx.x >> 5, lane = threadIdx.x & 31;
    const int which = bn / CDIM;              // 0=q 1=k 2=v (tiles never straddle)
    const int batch = bm >> 12;               // 256-row tile never straddles batch
    const float sc = (which == 0) ? 0.125f : 1.0f;
    __half* dst = which == 0 ? g_q : which == 1 ? g_k : g_v;

    #pragma unroll
    for (int nf = 0; nf < 4; nf++) {
        const int gcol = bn + (wid >> 2) * 32 + nf * 8 + (lane & 3) * 2;
        const float b0 = __ldg(bias + gcol), b1 = __ldg(bias + gcol + 1);
        const int within = gcol % CDIM;
        const int head = within >> 6, d = within & 63;
        #pragma unroll
        for (int mf = 0; mf < 4; mf++) {
            const int t = (bm & (TDIM - 1)) + (wid & 3) * 64 + mf * 16 + (lane >> 2);
            size_t o0 = ((size_t)(batch*HDIM + head)*TDIM + t)     * DDIM + d;
            size_t o1 = ((size_t)(batch*HDIM + head)*TDIM + t + 8) * DDIM + d;
            *(uint32_t*)(dst + o0) = pkh(__float2half_rn((acc[mf][nf][0]+b0)*sc),
                                         __float2half_rn((acc[mf][nf][1]+b1)*sc));
            *(uint32_t*)(dst + o1) = pkh(__float2half_rn((acc[mf][nf][2]+b0)*sc),
                                         __float2half_rn((acc[mf][nf][3]+b1)*sc));
        }
    }
}

// ---------------------------------------------------------------------------
// Projection GEMM: y @ W_proj + b -> d_out fp32.  CTA 128x128, grid (6, 64)
// ---------------------------------------------------------------------------
__global__ __launch_bounds__(512) void proj_mma(const float* __restrict__ bias,
                                                float* __restrict__ out) {
    extern __shared__ char sm[];
    const int bm = blockIdx.y * 128;
    const int bn = blockIdx.x * 128;
    float acc[2][4][4] = {};
    gemm_main<2>(g_y, g_WpT, bm, bn, acc, sm);

    const int wid = threadIdx.x >> 5, lane = threadIdx.x & 31;
    #pragma unroll
    for (int nf = 0; nf < 4; nf++) {
        const int gcol = bn + (wid >> 2) * 32 + nf * 8 + (lane & 3) * 2;
        const float b0 = __ldg(bias + gcol), b1 = __ldg(bias + gcol + 1);
        #pragma unroll
        for (int mf = 0; mf < 2; mf++) {
            const int m = bm + (wid & 3) * 32 + mf * 16 + (lane >> 2);
            *(float2*)(out + (size_t)m * CDIM + gcol) =
                make_float2(acc[mf][nf][0] + b0, acc[mf][nf][1] + b1);
            *(float2*)(out + (size_t)(m + 8) * CDIM + gcol) =
                make_float2(acc[mf][nf][2] + b0, acc[mf][nf][3] + b1);
        }
    }
}

// ---------------------------------------------------------------------------
// Flash attention, pure fp16 single-pass HMMA, 128-wide K/V tiles,
// SOFTWARE-PIPELINED: per iteration softmax(jt) -> S(jt+1) -> PV(jt), so the
// independent S(jt+1) HMMAs fill the MUFU shadow of softmax(jt).
// grid (32 q-tiles, 24 bh), 256 thr, 1 CTA/SM.  Q fp16 in registers;
// K,V fp16 in smem (stage 32KB: K@0 (128 rows) V@16K), 3-stage cp.async.
// ---------------------------------------------------------------------------
#define FSMEM (3*32768)

__global__ __launch_bounds__(256) void flash_mma() {
    extern __shared__ char sm[];
    const uint32_t sb = smem_u32(sm);
    const int tid = threadIdx.x, wid = tid >> 5, lane = tid & 31;
    const int qt = (int)gridDim.x - 1 - (int)blockIdx.x;   // heavy tiles first
    const int bh = blockIdx.y;
    const int qbase = qt * 128;
    const int ntiles = qt + 1;                              // 128-wide K tiles

    const __half* qp = g_q + (size_t)bh * TDIM * DDIM;
    const __half* kp = g_k + (size_t)bh * TDIM * DDIM;
    const __half* vp = g_v + (size_t)bh * TDIM * DDIM;

    // Q fragments, register resident
    uint32_t qf[4][4];
    {
        const int row = qbase + wid * 16 + (lane >> 2);
        const int colb = (lane & 3) * 2;
        #pragma unroll
        for (int kf = 0; kf < 4; kf++)
            #pragma unroll
            for (int a = 0; a < 4; a++) {
                int rr = row + ((a & 1) ? 8 : 0);
                int cc = kf * 16 + colb + ((a & 2) ? 8 : 0);
                qf[kf][a] = *(const uint32_t*)(qp + (size_t)rr * DDIM + cc);
            }
    }

    float m0 = -1e30f, m1 = -1e30f, l0 = 0.f, l1 = 0.f;
    float o[8][4] = {};
    const int r = lane & 7, g = lane >> 3;
    const float LOG2E = 1.4426950408889634f;

    // K/V tile loader (cp.async, 8 x 16B per thread; stage = 32KB)
    auto issue = [&](int jt) {
        const int kb = jt * 128;
        const uint32_t stg = sb + (uint32_t)((jt % 3) << 15);
        #pragma unroll
        for (int arr = 0; arr < 2; arr++) {
            const __half* base = arr == 0 ? kp : vp;
            #pragma unroll
            for (int i = 0; i < 4; i++) {
                int s2 = tid + (i << 8);            // 0..1023 (128 rows x 8)
                int row = s2 >> 3, c16 = s2 & 7;
                cp16(stg + (arr << 14) + SW128((uint32_t)(row*128 + (c16 << 4))),
                     base + (size_t)(kb + row) * DDIM + (c16 << 3));
            }
        }
        CP_COMMIT();
    };

    // S accumulation from K stage (zeroes s, then 64 HMMAs)
    float s[16][4];
    auto computeS = [&](uint32_t st) {
        #pragma unroll
        for (int nf = 0; nf < 16; nf++)
            #pragma unroll
            for (int q = 0; q < 4; q++) s[nf][q] = 0.f;
        #pragma unroll
        for (int kf = 0; kf < 4; kf++) {
            const int k0 = kf * 16;
            #pragma unroll
            for (int nb = 0; nb < 8; nb++) {
                uint32_t off = SW128((uint32_t)(
                    (nb*16 + ((g & 2) ? 8 : 0) + r) * 128 +
                    (k0 + ((g & 1) ? 8 : 0)) * 2));
                uint32_t h0, h1, h2, h3;
                ldm_x4(st + off, h0, h1, h2, h3);          // K
                mma_fp16(s[2*nb],   qf[kf], h0, h1);
                mma_fp16(s[2*nb+1], qf[kf], h2, h3);
            }
        }
    };

    // Prologue: load tiles 0 (and 1), compute S(0)
    issue(0);
    if (ntiles > 1) { issue(1); CP_WAIT1(); } else { CP_WAIT0(); }
    __syncthreads();
    computeS(sb);

    for (int jt = 0; jt < ntiles; jt++) {
        CP_WAIT0();              // tile jt+1 (if any) fully arrived
        __syncthreads();         // ... and visible CTA-wide; stage jt-1 free
        if (jt + 2 < ntiles) issue(jt + 2);
        const int kb = jt * 128;
        const uint32_t st = sb + (uint32_t)((jt % 3) << 15);

        // ---- causal mask (diagonal tile only) ----
        const int row0 = qbase + wid * 16 + (lane >> 2);
        if (kb + 127 > row0) {
            #pragma unroll
            for (int nf = 0; nf < 16; nf++) {
                int col = kb + nf * 8 + (lane & 3) * 2;
                if (col     > row0)     s[nf][0] = -1e30f;
                if (col + 1 > row0)     s[nf][1] = -1e30f;
                if (col     > row0 + 8) s[nf][2] = -1e30f;
                if (col + 1 > row0 + 8) s[nf][3] = -1e30f;
            }
        }

        // ---- online softmax (MUFU) ----
        float rmax0 = -1e30f, rmax1 = -1e30f;
        #pragma unroll
        for (int nf = 0; nf < 16; nf++) {
            rmax0 = fmaxf(rmax0, fmaxf(s[nf][0], s[nf][1]));
            rmax1 = fmaxf(rmax1, fmaxf(s[nf][2], s[nf][3]));
        }
        rmax0 = fmaxf(rmax0, __shfl_xor_sync(0xffffffffu, rmax0, 1));
        rmax0 = fmaxf(rmax0, __shfl_xor_sync(0xffffffffu, rmax0, 2));
        rmax1 = fmaxf(rmax1, __shfl_xor_sync(0xffffffffu, rmax1, 1));
        rmax1 = fmaxf(rmax1, __shfl_xor_sync(0xffffffffu, rmax1, 2));
        const float mn0 = fmaxf(m0, rmax0), mn1 = fmaxf(m1, rmax1);
        const float a0 = ex2f((m0 - mn0) * LOG2E);
        const float a1 = ex2f((m1 - mn1) * LOG2E);
        m0 = mn0; m1 = mn1;
        const float ml0 = mn0 * LOG2E, ml1 = mn1 * LOG2E;
        float rs0 = 0.f, rs1 = 0.f;
        #pragma unroll
        for (int nf = 0; nf < 16; nf++) {
            s[nf][0] = ex2f(fmaf(s[nf][0], LOG2E, -ml0));
            s[nf][1] = ex2f(fmaf(s[nf][1], LOG2E, -ml0));
            s[nf][2] = ex2f(fmaf(s[nf][2], LOG2E, -ml1));
            s[nf][3] = ex2f(fmaf(s[nf][3], LOG2E, -ml1));
            rs0 += s[nf][0] + s[nf][1];
            rs1 += s[nf][2] + s[nf][3];
        }
        rs0 += __shfl_xor_sync(0xffffffffu, rs0, 1);
        rs0 += __shfl_xor_sync(0xffffffffu, rs0, 2);
        rs1 += __shfl_xor_sync(0xffffffffu, rs1, 1);
        rs1 += __shfl_xor_sync(0xffffffffu, rs1, 2);
        l0 = l0 * a0 + rs0;
        l1 = l1 * a1 + rs1;
        #pragma unroll
        for (int nf = 0; nf < 8; nf++) {
            o[nf][0] *= a0; o[nf][1] *= a0;
            o[nf][2] *= a1; o[nf][3] *= a1;
        }

        // ---- P -> fp16 A-fragments (frees s) ----
        uint32_t pf[8][4];
        #pragma unroll
        for (int j = 0; j < 8; j++) {
            #pragma unroll
            for (int half = 0; half < 2; half++) {
                pf[j][2*half]     = pkh(__float2half_rn(s[2*j + half][0]),
                                        __float2half_rn(s[2*j + half][1]));
                pf[j][2*half + 1] = pkh(__float2half_rn(s[2*j + half][2]),
                                        __float2half_rn(s[2*j + half][3]));
            }
        }

        // ---- S(jt+1): independent HMMAs, interleavable with the MUFU above ----
        if (jt + 1 < ntiles)
            computeS(sb + (uint32_t)(((jt + 1) % 3) << 15));

        // ---- O += P.V (tile jt), V^T via ldmatrix.trans ----
        #pragma unroll
        for (int j = 0; j < 8; j++) {
            #pragma unroll
            for (int nb = 0; nb < 4; nb++) {
                uint32_t off = SW128((uint32_t)(
                    (j*16 + ((g & 1) ? 8 : 0) + r) * 128 +
                    (nb*16 + ((g & 2) ? 8 : 0)) * 2));
                uint32_t h0, h1, h2, h3;
                ldm_x4t(st + 16384 + off, h0, h1, h2, h3);   // V
                mma_fp16(o[2*nb],   pf[j], h0, h1);
                mma_fp16(o[2*nb+1], pf[j], h2, h3);
            }
        }
    }

    // ---- epilogue: o / l -> fp16 into g_y ----
    const float inv0 = 1.0f / l0, inv1 = 1.0f / l1;
    const int batch = bh / HDIM, hh = bh % HDIM;
    const int row = qbase + wid * 16 + (lane >> 2);
    const size_t rb0 = ((size_t)(batch * TDIM + row))     * CDIM + hh * DDIM;
    const size_t rb1 = ((size_t)(batch * TDIM + row + 8)) * CDIM + hh * DDIM;
    #pragma unroll
    for (int nf = 0; nf < 8; nf++) {
        const int d = nf * 8 + (lane & 3) * 2;
        *(uint32_t*)(g_y + rb0 + d) = pkh(__float2half_rn(o[nf][0] * inv0),
                                          __float2half_rn(o[nf][1] * inv0));
        *(uint32_t*)(g_y + rb1 + d) = pkh(__float2half_rn(o[nf][2] * inv1),
                                          __float2half_rn(o[nf][3] * inv1));
    }
}

// ---------------------------------------------------------------------------
extern "C" void kernel_launch(void* const* d_in, const int* in_sizes, int n_in,
                              void* d_out, int out_size) {
    const float *x = nullptr, *Wa = nullptr, *ba = nullptr, *Wp = nullptr, *bp = nullptr;
    for (int i = 0; i < n_in; i++) {
        switch (in_sizes[i]) {
            case 6291456: x  = (const float*)d_in[i]; break;   // [2,4096,768]
            case 1769472: Wa = (const float*)d_in[i]; break;   // [768,2304]
            case 2304:    ba = (const float*)d_in[i]; break;
            case 589824:  Wp = (const float*)d_in[i]; break;   // [768,768]
            case 768:     bp = (const float*)d_in[i]; break;
        }
    }

    cudaFuncSetAttribute(qkv_mma,   cudaFuncAttributeMaxDynamicSharedMemorySize, GSMEM4);
    cudaFuncSetAttribute(proj_mma,  cudaFuncAttributeMaxDynamicSharedMemorySize, GSMEM2);
    cudaFuncSetAttribute(flash_mma, cudaFuncAttributeMaxDynamicSharedMemorySize, FSMEM);

    __half *xd, *wat, *wpt;
    cudaGetSymbolAddress((void**)&xd,  g_x);
    cudaGetSymbolAddress((void**)&wat, g_WaT);
    cudaGetSymbolAddress((void**)&wpt, g_WpT);

    conv_f16<<<(MTOT*CDIM/2 + 255)/256, 256>>>(x, xd, MTOT*CDIM/2);
    wconv_T<<<dim3(N3DIM/32, CDIM/32), dim3(32, 8)>>>(Wa, wat, CDIM, N3DIM);
    wconv_T<<<dim3(CDIM/32,  CDIM/32), dim3(32, 8)>>>(Wp, wpt, CDIM, CDIM);
    qkv_mma<<<dim3(N3DIM/128, MTOT/256), 512, GSMEM4>>>(ba);       // (18,32)
    flash_mma<<<dim3(TDIM/128, BDIM*HDIM), 256, FSMEM>>>();        // (32,24)
    proj_mma<<<dim3(CDIM/128, MTOT/128), 512, GSMEM2>>>(bp, (float*)d_out); // (6,64)
}

// round 13
// speedup vs baseline: 2.4667x; 1.0373x over previous
#include <cuda_runtime.h>
#include <cuda_bf16.h>
#include <cuda_fp16.h>
#include <cstdint>

// ---------------------------------------------------------------------------
// Problem constants
// ---------------------------------------------------------------------------
#define BDIM 2
#define TDIM 4096
#define CDIM 768
#define HDIM 12
#define DDIM 64
#define N3DIM 2304            // 3*C
#define MTOT  (BDIM*TDIM)     // 8192

// ---------------------------------------------------------------------------
// Device scratch (no allocation in kernel_launch) — pure fp16 pipeline
// ---------------------------------------------------------------------------
__device__ __align__(16) __half g_x [MTOT*CDIM];
__device__ __align__(16) __half g_y [MTOT*CDIM];
__device__ __align__(16) __half g_WaT[N3DIM*CDIM];   // [N,K]
__device__ __align__(16) __half g_WpT[CDIM*CDIM];    // [N,K]
__device__ __align__(16) __half g_q[BDIM*HDIM*TDIM*DDIM];   // x0.125
__device__ __align__(16) __half g_k[BDIM*HDIM*TDIM*DDIM];
__device__ __align__(16) __half g_v[BDIM*HDIM*TDIM*DDIM];

// ---------------------------------------------------------------------------
// Helpers (all sm_80-legal: mma.sync fp16, ldmatrix, cp.async)
// ---------------------------------------------------------------------------
__device__ __forceinline__ uint32_t smem_u32(const void* p) {
    uint32_t a;
    asm("{ .reg .u64 t; cvta.to.shared.u64 t, %1; cvt.u32.u64 %0, t; }"
        : "=r"(a) : "l"(p));
    return a;
}
#define SW128(off) ((off) ^ (((off) >> 3) & 0x70))

__device__ __forceinline__ void cp16(uint32_t dst, const void* src) {
    asm volatile("cp.async.cg.shared.global [%0], [%1], 16;"
                 :: "r"(dst), "l"(src) : "memory");
}
#define CP_COMMIT() asm volatile("cp.async.commit_group;" ::: "memory")
#define CP_WAIT0()  asm volatile("cp.async.wait_group 0;"  ::: "memory")
#define CP_WAIT1()  asm volatile("cp.async.wait_group 1;"  ::: "memory")

__device__ __forceinline__ void ldm_x4(uint32_t a, uint32_t& r0, uint32_t& r1,
                                       uint32_t& r2, uint32_t& r3) {
    asm volatile("ldmatrix.sync.aligned.m8n8.x4.shared.b16 {%0,%1,%2,%3}, [%4];"
                 : "=r"(r0), "=r"(r1), "=r"(r2), "=r"(r3) : "r"(a));
}
__device__ __forceinline__ void ldm_x4t(uint32_t a, uint32_t& r0, uint32_t& r1,
                                        uint32_t& r2, uint32_t& r3) {
    asm volatile("ldmatrix.sync.aligned.m8n8.x4.trans.shared.b16 {%0,%1,%2,%3}, [%4];"
                 : "=r"(r0), "=r"(r1), "=r"(r2), "=r"(r3) : "r"(a));
}
__device__ __forceinline__ void mma_fp16(float (&c)[4], const uint32_t (&a)[4],
                                         uint32_t b0, uint32_t b1) {
    asm volatile("mma.sync.aligned.m16n8k16.row.col.f32.f16.f16.f32 "
                 "{%0,%1,%2,%3}, {%4,%5,%6,%7}, {%8,%9}, {%0,%1,%2,%3};"
                 : "+f"(c[0]), "+f"(c[1]), "+f"(c[2]), "+f"(c[3])
                 : "r"(a[0]), "r"(a[1]), "r"(a[2]), "r"(a[3]), "r"(b0), "r"(b1));
}
// pack two halves into u32 (a -> low, b -> high)
__device__ __forceinline__ uint32_t pkh(__half a, __half b) {
    __half2 t = __halves2half2(a, b);
    return *(uint32_t*)&t;
}
__device__ __forceinline__ float ex2f(float x) {
    float y; asm("ex2.approx.ftz.f32 %0, %1;" : "=f"(y) : "f"(x)); return y;
}

// ---------------------------------------------------------------------------
// Conversion kernels
// ---------------------------------------------------------------------------
__global__ __launch_bounds__(256) void conv_f16(const float* __restrict__ in,
                                                __half* __restrict__ out, int n2) {
    int i = blockIdx.x * blockDim.x + threadIdx.x;
    if (i >= n2) return;
    float2 v = ((const float2*)in)[i];
    ((uint32_t*)out)[i] = pkh(__float2half_rn(v.x), __float2half_rn(v.y));
}

// W [K,N] fp32 -> WT [N,K] fp16 (transpose + convert). block (32,8).
__global__ __launch_bounds__(256) void wconv_T(const float* __restrict__ W,
                                               __half* __restrict__ WT,
                                               int K, int N) {
    __shared__ float tile[32][33];
    const int tx = threadIdx.x, ty = threadIdx.y;
    const int bn = blockIdx.x * 32, bk = blockIdx.y * 32;
    #pragma unroll
    for (int i = 0; i < 4; i++)
        tile[ty + 8*i][tx] = W[(size_t)(bk + ty + 8*i) * N + bn + tx];
    __syncthreads();
    #pragma unroll
    for (int i = 0; i < 4; i++)
        WT[(size_t)(bn + ty + 8*i) * K + bk + tx] = __float2half_rn(tile[tx][ty + 8*i]);
}

// ---------------------------------------------------------------------------
// Single-pass fp16 HMMA GEMM mainloop, templated warp-M (MF*16).
// 512 thr = 16 warps (4m x 4n), warp tile (MF*16)x32, CTA (MF*64)x128,
// K-chunk 64, 3-stage.  smem stage: A (MF*8KB) @0, B (16KB) @MF*8KB.
// ---------------------------------------------------------------------------
template<int MF>
__device__ __forceinline__ void gemm_issue(const __half* A, const __half* B,
                                           int am0, int bn0, int k0,
                                           uint32_t stbase, int tid) {
    #pragma unroll
    for (int i = 0; i < MF; i++) {                 // A: MF*64 rows
        int s2 = tid + (i << 9);
        int row = s2 >> 3, c16 = s2 & 7;
        cp16(stbase + SW128((uint32_t)(row*128 + (c16 << 4))),
             A + (size_t)(am0 + row) * 768 + k0 + (c16 << 3));
    }
    #pragma unroll
    for (int i = 0; i < 2; i++) {                  // B: 128 rows
        int s2 = tid + (i << 9);
        int row = s2 >> 3, c16 = s2 & 7;
        cp16(stbase + (uint32_t)(MF*8192) + SW128((uint32_t)(row*128 + (c16 << 4))),
             B + (size_t)(bn0 + row) * 768 + k0 + (c16 << 3));
    }
    CP_COMMIT();
}

template<int MF>
__device__ __forceinline__ void gemm_main(const __half* A, const __half* B,
                                          int am0, int bn0,
                                          float (&acc)[MF][4][4], char* sm) {
    const int GST = MF*8192 + 16384;
    const int tid = threadIdx.x;
    const int wid = tid >> 5, lane = tid & 31;
    const uint32_t sb = smem_u32(sm);
    const int wm0 = (wid & 3) * (MF*16);
    const int wn0 = (wid >> 2) * 32;
    const int r = lane & 7, g = lane >> 3;

    gemm_issue<MF>(A, B, am0, bn0, 0,  sb,       tid);
    gemm_issue<MF>(A, B, am0, bn0, 64, sb + GST, tid);

    for (int c = 0; c < 12; c++) {
        if (c < 11) CP_WAIT1(); else CP_WAIT0();
        __syncthreads();
        if (c < 10)
            gemm_issue<MF>(A, B, am0, bn0, (c+2)*64,
                           sb + (uint32_t)(((c+2)%3) * GST), tid);
        const uint32_t st = sb + (uint32_t)((c % 3) * GST);
        #pragma unroll
        for (int kf = 0; kf < 4; kf++) {
            const int k0 = kf * 16;
            uint32_t af[MF][4];
            #pragma unroll
            for (int mf = 0; mf < MF; mf++) {
                uint32_t off = SW128((uint32_t)(
                    (wm0 + mf*16 + ((g & 1) ? 8 : 0) + r) * 128 +
                    (k0 + ((g & 2) ? 8 : 0)) * 2));
                ldm_x4(st + off, af[mf][0], af[mf][1], af[mf][2], af[mf][3]);
            }
            uint32_t bf[4][2];
            #pragma unroll
            for (int nb = 0; nb < 2; nb++) {
                uint32_t off = SW128((uint32_t)(
                    (wn0 + nb*16 + ((g & 2) ? 8 : 0) + r) * 128 +
                    (k0 + ((g & 1) ? 8 : 0)) * 2));
                uint32_t t0, t1, t2, t3;
                ldm_x4(st + (uint32_t)(MF*8192) + off, t0, t1, t2, t3);
                bf[2*nb][0] = t0; bf[2*nb][1] = t1;
                bf[2*nb+1][0] = t2; bf[2*nb+1][1] = t3;
            }
            #pragma unroll
            for (int mf = 0; mf < MF; mf++)
                #pragma unroll
                for (int nf = 0; nf < 4; nf++)
                    mma_fp16(acc[mf][nf], af[mf], bf[nf][0], bf[nf][1]);
        }
    }
}

#define GSMEM4 (3*(4*8192 + 16384))   // qkv: 147456
#define GSMEM2 (3*(2*8192 + 16384))   // proj: 98304

// ---------------------------------------------------------------------------
// QKV GEMM: x @ W_attn + b.  q (x0.125), k, v -> fp16 [b*h][t][d].
// CTA 256x128, grid (18, 32), 512 threads
// ---------------------------------------------------------------------------
__global__ __launch_bounds__(512) void qkv_mma(const float* __restrict__ bias) {
    extern __shared__ char sm[];
    const int bm = blockIdx.y * 256;
    const int bn = blockIdx.x * 128;
    float acc[4][4][4] = {};
    gemm_main<4>(g_x, g_WaT, bm, bn, acc, sm);

    const int wid = threadIdx.x >> 5, lane = threadIdx.x & 31;
    const int which = bn / CDIM;              // 0=q 1=k 2=v (tiles never straddle)
    const int batch = bm >> 12;               // 256-row tile never straddles batch
    const float sc = (which == 0) ? 0.125f : 1.0f;
    __half* dst = which == 0 ? g_q : which == 1 ? g_k : g_v;

    #pragma unroll
    for (int nf = 0; nf < 4; nf++) {
        const int gcol = bn + (wid >> 2) * 32 + nf * 8 + (lane & 3) * 2;
        const float b0 = __ldg(bias + gcol), b1 = __ldg(bias + gcol + 1);
        const int within = gcol % CDIM;
        const int head = within >> 6, d = within & 63;
        #pragma unroll
        for (int mf = 0; mf < 4; mf++) {
            const int t = (bm & (TDIM - 1)) + (wid & 3) * 64 + mf * 16 + (lane >> 2);
            size_t o0 = ((size_t)(batch*HDIM + head)*TDIM + t)     * DDIM + d;
            size_t o1 = ((size_t)(batch*HDIM + head)*TDIM + t + 8) * DDIM + d;
            *(uint32_t*)(dst + o0) = pkh(__float2half_rn((acc[mf][nf][0]+b0)*sc),
                                         __float2half_rn((acc[mf][nf][1]+b1)*sc));
            *(uint32_t*)(dst + o1) = pkh(__float2half_rn((acc[mf][nf][2]+b0)*sc),
                                         __float2half_rn((acc[mf][nf][3]+b1)*sc));
        }
    }
}

// ---------------------------------------------------------------------------
// Projection GEMM: y @ W_proj + b -> d_out fp32.  CTA 128x128, grid (6, 64)
// ---------------------------------------------------------------------------
__global__ __launch_bounds__(512) void proj_mma(const float* __restrict__ bias,
                                                float* __restrict__ out) {
    extern __shared__ char sm[];
    const int bm = blockIdx.y * 128;
    const int bn = blockIdx.x * 128;
    float acc[2][4][4] = {};
    gemm_main<2>(g_y, g_WpT, bm, bn, acc, sm);

    const int wid = threadIdx.x >> 5, lane = threadIdx.x & 31;
    #pragma unroll
    for (int nf = 0; nf < 4; nf++) {
        const int gcol = bn + (wid >> 2) * 32 + nf * 8 + (lane & 3) * 2;
        const float b0 = __ldg(bias + gcol), b1 = __ldg(bias + gcol + 1);
        #pragma unroll
        for (int mf = 0; mf < 2; mf++) {
            const int m = bm + (wid & 3) * 32 + mf * 16 + (lane >> 2);
            *(float2*)(out + (size_t)m * CDIM + gcol) =
                make_float2(acc[mf][nf][0] + b0, acc[mf][nf][1] + b1);
            *(float2*)(out + (size_t)(m + 8) * CDIM + gcol) =
                make_float2(acc[mf][nf][2] + b0, acc[mf][nf][3] + b1);
        }
    }
}

// ---------------------------------------------------------------------------
// Flash attention, pure fp16 single-pass HMMA, 128-wide K/V tiles,
// PING-PONG S REGISTERS: iteration jt issues S(jt+1) into the OTHER register
// array BEFORE the softmax of jt, so the independent HMMAs execute under the
// MUFU/shuffle softmax (no WAR hazard — the R12 failure mode).
// grid (32 q-tiles, 24 bh), 256 thr, 1 CTA/SM.  Q fp16 in registers;
// K,V fp16 in smem (stage 32KB: K@0 (128 rows) V@16K), 3-stage cp.async.
// ---------------------------------------------------------------------------
#define FSMEM (3*32768)

__global__ __launch_bounds__(256) void flash_mma() {
    extern __shared__ char sm[];
    const uint32_t sb = smem_u32(sm);
    const int tid = threadIdx.x, wid = tid >> 5, lane = tid & 31;
    const int qt = (int)gridDim.x - 1 - (int)blockIdx.x;   // heavy tiles first
    const int bh = blockIdx.y;
    const int qbase = qt * 128;
    const int ntiles = qt + 1;                              // 128-wide K tiles

    const __half* qp = g_q + (size_t)bh * TDIM * DDIM;
    const __half* kp = g_k + (size_t)bh * TDIM * DDIM;
    const __half* vp = g_v + (size_t)bh * TDIM * DDIM;

    // Q fragments, register resident
    uint32_t qf[4][4];
    {
        const int row = qbase + wid * 16 + (lane >> 2);
        const int colb = (lane & 3) * 2;
        #pragma unroll
        for (int kf = 0; kf < 4; kf++)
            #pragma unroll
            for (int a = 0; a < 4; a++) {
                int rr = row + ((a & 1) ? 8 : 0);
                int cc = kf * 16 + colb + ((a & 2) ? 8 : 0);
                qf[kf][a] = *(const uint32_t*)(qp + (size_t)rr * DDIM + cc);
            }
    }

    float m0 = -1e30f, m1 = -1e30f, l0 = 0.f, l1 = 0.f;
    float o[8][4] = {};
    const int r = lane & 7, g = lane >> 3;
    const float LOG2E = 1.4426950408889634f;

    // K/V tile loader (cp.async, 8 x 16B per thread; stage = 32KB)
    auto issue = [&](int jt) {
        const int kb = jt * 128;
        const uint32_t stg = sb + (uint32_t)((jt % 3) << 15);
        #pragma unroll
        for (int arr = 0; arr < 2; arr++) {
            const __half* base = arr == 0 ? kp : vp;
            #pragma unroll
            for (int i = 0; i < 4; i++) {
                int s2 = tid + (i << 8);            // 0..1023 (128 rows x 8)
                int row = s2 >> 3, c16 = s2 & 7;
                cp16(stg + (arr << 14) + SW128((uint32_t)(row*128 + (c16 << 4))),
                     base + (size_t)(kb + row) * DDIM + (c16 << 3));
            }
        }
        CP_COMMIT();
    };

    // S accumulation from K stage into the given register array
    auto computeS = [&](uint32_t st, float (&s)[16][4]) {
        #pragma unroll
        for (int nf = 0; nf < 16; nf++)
            #pragma unroll
            for (int q = 0; q < 4; q++) s[nf][q] = 0.f;
        #pragma unroll
        for (int kf = 0; kf < 4; kf++) {
            const int k0 = kf * 16;
            #pragma unroll
            for (int nb = 0; nb < 8; nb++) {
                uint32_t off = SW128((uint32_t)(
                    (nb*16 + ((g & 2) ? 8 : 0) + r) * 128 +
                    (k0 + ((g & 1) ? 8 : 0)) * 2));
                uint32_t h0, h1, h2, h3;
                ldm_x4(st + off, h0, h1, h2, h3);          // K
                mma_fp16(s[2*nb],   qf[kf], h0, h1);
                mma_fp16(s[2*nb+1], qf[kf], h2, h3);
            }
        }
    };

    float sA[16][4], sB[16][4];

    // Per-tile body: softmax+PV on scur while S(jt+1) accumulates into snx.
    auto body = [&](int jt, float (&scur)[16][4], float (&snx)[16][4]) {
        CP_WAIT0();              // tile jt+1 (if issued) fully arrived
        __syncthreads();         // visible CTA-wide; stage jt-1 free
        if (jt + 2 < ntiles) issue(jt + 2);
        const int kb = jt * 128;
        const uint32_t st = sb + (uint32_t)((jt % 3) << 15);

        // ---- S(jt+1) FIRST: fills the tensor pipe under the softmax below ----
        if (jt + 1 < ntiles)
            computeS(sb + (uint32_t)(((jt + 1) % 3) << 15), snx);

        // ---- causal mask (diagonal tile only) ----
        const int row0 = qbase + wid * 16 + (lane >> 2);
        if (kb + 127 > row0) {
            #pragma unroll
            for (int nf = 0; nf < 16; nf++) {
                int col = kb + nf * 8 + (lane & 3) * 2;
                if (col     > row0)     scur[nf][0] = -1e30f;
                if (col + 1 > row0)     scur[nf][1] = -1e30f;
                if (col     > row0 + 8) scur[nf][2] = -1e30f;
                if (col + 1 > row0 + 8) scur[nf][3] = -1e30f;
            }
        }

        // ---- online softmax (MUFU; overlaps in-flight S HMMAs) ----
        float rmax0 = -1e30f, rmax1 = -1e30f;
        #pragma unroll
        for (int nf = 0; nf < 16; nf++) {
            rmax0 = fmaxf(rmax0, fmaxf(scur[nf][0], scur[nf][1]));
            rmax1 = fmaxf(rmax1, fmaxf(scur[nf][2], scur[nf][3]));
        }
        rmax0 = fmaxf(rmax0, __shfl_xor_sync(0xffffffffu, rmax0, 1));
        rmax0 = fmaxf(rmax0, __shfl_xor_sync(0xffffffffu, rmax0, 2));
        rmax1 = fmaxf(rmax1, __shfl_xor_sync(0xffffffffu, rmax1, 1));
        rmax1 = fmaxf(rmax1, __shfl_xor_sync(0xffffffffu, rmax1, 2));
        const float mn0 = fmaxf(m0, rmax0), mn1 = fmaxf(m1, rmax1);
        const float a0 = ex2f((m0 - mn0) * LOG2E);
        const float a1 = ex2f((m1 - mn1) * LOG2E);
        m0 = mn0; m1 = mn1;
        const float ml0 = mn0 * LOG2E, ml1 = mn1 * LOG2E;
        float rs0 = 0.f, rs1 = 0.f;
        #pragma unroll
        for (int nf = 0; nf < 16; nf++) {
            scur[nf][0] = ex2f(fmaf(scur[nf][0], LOG2E, -ml0));
            scur[nf][1] = ex2f(fmaf(scur[nf][1], LOG2E, -ml0));
            scur[nf][2] = ex2f(fmaf(scur[nf][2], LOG2E, -ml1));
            scur[nf][3] = ex2f(fmaf(scur[nf][3], LOG2E, -ml1));
            rs0 += scur[nf][0] + scur[nf][1];
            rs1 += scur[nf][2] + scur[nf][3];
        }
        rs0 += __shfl_xor_sync(0xffffffffu, rs0, 1);
        rs0 += __shfl_xor_sync(0xffffffffu, rs0, 2);
        rs1 += __shfl_xor_sync(0xffffffffu, rs1, 1);
        rs1 += __shfl_xor_sync(0xffffffffu, rs1, 2);
        l0 = l0 * a0 + rs0;
        l1 = l1 * a1 + rs1;
        #pragma unroll
        for (int nf = 0; nf < 8; nf++) {
            o[nf][0] *= a0; o[nf][1] *= a0;
            o[nf][2] *= a1; o[nf][3] *= a1;
        }

        // ---- P -> fp16 A-fragments ----
        uint32_t pf[8][4];
        #pragma unroll
        for (int j = 0; j < 8; j++) {
            #pragma unroll
            for (int half = 0; half < 2; half++) {
                pf[j][2*half]     = pkh(__float2half_rn(scur[2*j + half][0]),
                                        __float2half_rn(scur[2*j + half][1]));
                pf[j][2*half + 1] = pkh(__float2half_rn(scur[2*j + half][2]),
                                        __float2half_rn(scur[2*j + half][3]));
            }
        }

        // ---- O += P.V (tile jt), V^T via ldmatrix.trans ----
        #pragma unroll
        for (int j = 0; j < 8; j++) {
            #pragma unroll
            for (int nb = 0; nb < 4; nb++) {
                uint32_t off = SW128((uint32_t)(
                    (j*16 + ((g & 1) ? 8 : 0) + r) * 128 +
                    (nb*16 + ((g & 2) ? 8 : 0)) * 2));
                uint32_t h0, h1, h2, h3;
                ldm_x4t(st + 16384 + off, h0, h1, h2, h3);   // V
                mma_fp16(o[2*nb],   pf[j], h0, h1);
                mma_fp16(o[2*nb+1], pf[j], h2, h3);
            }
        }
    };

    // Prologue: load tiles 0 (and 1), compute S(0) into sA
    issue(0);
    if (ntiles > 1) { issue(1); CP_WAIT1(); } else { CP_WAIT0(); }
    __syncthreads();
    computeS(sb, sA);

    for (int jt = 0; jt < ntiles; jt++) {
        if (jt & 1) body(jt, sB, sA);
        else        body(jt, sA, sB);
    }

    // ---- epilogue: o / l -> fp16 into g_y ----
    const float inv0 = 1.0f / l0, inv1 = 1.0f / l1;
    const int batch = bh / HDIM, hh = bh % HDIM;
    const int row = qbase + wid * 16 + (lane >> 2);
    const size_t rb0 = ((size_t)(batch * TDIM + row))     * CDIM + hh * DDIM;
    const size_t rb1 = ((size_t)(batch * TDIM + row + 8)) * CDIM + hh * DDIM;
    #pragma unroll
    for (int nf = 0; nf < 8; nf++) {
        const int d = nf * 8 + (lane & 3) * 2;
        *(uint32_t*)(g_y + rb0 + d) = pkh(__float2half_rn(o[nf][0] * inv0),
                                          __float2half_rn(o[nf][1] * inv0));
        *(uint32_t*)(g_y + rb1 + d) = pkh(__float2half_rn(o[nf][2] * inv1),
                                          __float2half_rn(o[nf][3] * inv1));
    }
}

// ---------------------------------------------------------------------------
extern "C" void kernel_launch(void* const* d_in, const int* in_sizes, int n_in,
                              void* d_out, int out_size) {
    const float *x = nullptr, *Wa = nullptr, *ba = nullptr, *Wp = nullptr, *bp = nullptr;
    for (int i = 0; i < n_in; i++) {
        switch (in_sizes[i]) {
            case 6291456: x  = (const float*)d_in[i]; break;   // [2,4096,768]
            case 1769472: Wa = (const float*)d_in[i]; break;   // [768,2304]
            case 2304:    ba = (const float*)d_in[i]; break;
            case 589824:  Wp = (const float*)d_in[i]; break;   // [768,768]
            case 768:     bp = (const float*)d_in[i]; break;
        }
    }

    cudaFuncSetAttribute(qkv_mma,   cudaFuncAttributeMaxDynamicSharedMemorySize, GSMEM4);
    cudaFuncSetAttribute(proj_mma,  cudaFuncAttributeMaxDynamicSharedMemorySize, GSMEM2);
    cudaFuncSetAttribute(flash_mma, cudaFuncAttributeMaxDynamicSharedMemorySize, FSMEM);

    __half *xd, *wat, *wpt;
    cudaGetSymbolAddress((void**)&xd,  g_x);
    cudaGetSymbolAddress((void**)&wat, g_WaT);
    cudaGetSymbolAddress((void**)&wpt, g_WpT);

    conv_f16<<<(MTOT*CDIM/2 + 255)/256, 256>>>(x, xd, MTOT*CDIM/2);
    wconv_T<<<dim3(N3DIM/32, CDIM/32), dim3(32, 8)>>>(Wa, wat, CDIM, N3DIM);
    wconv_T<<<dim3(CDIM/32,  CDIM/32), dim3(32, 8)>>>(Wp, wpt, CDIM, CDIM);
    qkv_mma<<<dim3(N3DIM/128, MTOT/256), 512, GSMEM4>>>(ba);       // (18,32)
    flash_mma<<<dim3(TDIM/128, BDIM*HDIM), 256, FSMEM>>>();        // (32,24)
    proj_mma<<<dim3(CDIM/128, MTOT/128), 512, GSMEM2>>>(bp, (float*)d_out); // (6,64)
}